// round 6
// baseline (speedup 1.0000x reference)
#include <cuda_runtime.h>
#include <cuda_bf16.h>
#include <cstdint>

#define BB 32
#define CC 64
#define NN 1024
#define DEPTH 8
#define NCLS 10

using u64 = unsigned long long;

static __device__ float g_X[2][BB * NN * CC];   // ping-pong token states
static __device__ float g_Q[BB * NN * CC];
static __device__ float g_K[BB * NN * CC];
static __device__ float g_V[BB * NN * CC];

// ---------------- packed fp32 helpers (Blackwell f32x2 pipe) ----------------
__device__ __forceinline__ u64 ffma2(u64 a, u64 b, u64 c) {
    u64 d;
    asm("fma.rn.f32x2 %0, %1, %2, %3;" : "=l"(d) : "l"(a), "l"(b), "l"(c));
    return d;
}
__device__ __forceinline__ u64 fmul2(u64 a, u64 b) {
    u64 d;
    asm("mul.rn.f32x2 %0, %1, %2;" : "=l"(d) : "l"(a), "l"(b));
    return d;
}
__device__ __forceinline__ u64 dup2(float x) {
    u64 r;
    asm("mov.b64 %0, {%1, %1};" : "=l"(r) : "f"(x));
    return r;
}
__device__ __forceinline__ float2 u2f2(u64 v) {
    float2 r;
    asm("mov.b64 {%0, %1}, %2;" : "=f"(r.x), "=f"(r.y) : "l"(v));
    return r;
}

// ---------------- cp.async helpers ----------------
__device__ __forceinline__ void cp16(uint32_t dst, const float* src) {
    asm volatile("cp.async.cg.shared.global [%0], [%1], 16;" :: "r"(dst), "l"(src));
}
__device__ __forceinline__ void cp_commit() {
    asm volatile("cp.async.commit_group;" ::: "memory");
}
__device__ __forceinline__ void cp_wait0() {
    asm volatile("cp.async.wait_group 0;" ::: "memory");
}

// ---------------------------------------------------------------------------
// Transpose: image (B,C,1024) -> X[0] (B,1024,C)
// ---------------------------------------------------------------------------
__global__ void k_transpose(const float* __restrict__ img) {
    __shared__ float t[64][65];
    int b = blockIdx.y;
    int n0 = blockIdx.x * 64;
    const float* src = img + (size_t)b * CC * NN;
    for (int idx = threadIdx.x; idx < 64 * 64; idx += 256) {
        int c = idx >> 6, n = idx & 63;
        t[c][n] = src[c * NN + n0 + n];
    }
    __syncthreads();
    float* dst = g_X[0] + ((size_t)b * NN + n0) * CC;
    for (int idx = threadIdx.x; idx < 64 * 64; idx += 256) {
        int n = idx >> 6, c = idx & 63;
        dst[n * CC + c] = t[c][n];
    }
}

// ---------------------------------------------------------------------------
// Fused QKV (f32x2): Q = (X @ WQ) * scale, K = X @ WK, V = X @ WV
// ---------------------------------------------------------------------------
#define XSTRIDE 68

__global__ void __launch_bounds__(256) k_qkv(const float* __restrict__ WQ,
                                             const float* __restrict__ WK,
                                             const float* __restrict__ WV,
                                             int pp) {
    extern __shared__ float sm[];
    float* Xs = sm;                   // 64 x 68
    float* Ws = sm + 64 * XSTRIDE;    // 64 x 192  (Q|K|V columns)
    uint32_t sXs = (uint32_t)__cvta_generic_to_shared(Xs);
    uint32_t sWs = (uint32_t)__cvta_generic_to_shared(Ws);

    int b = blockIdx.y;
    int n0 = blockIdx.x * 64;
    int tid = threadIdx.x;

    const float* Xin = g_X[pp] + ((size_t)b * NN + n0) * CC;
#pragma unroll
    for (int t = 0; t < 4; t++) {
        int i = tid + t * 256;
        int r = i >> 4, c = (i & 15) << 2;
        cp16(sXs + (r * XSTRIDE + c) * 4, Xin + r * 64 + c);
        cp16(sWs + (r * 192 + c) * 4,       WQ + r * 64 + c);
        cp16(sWs + (r * 192 + 64 + c) * 4,  WK + r * 64 + c);
        cp16(sWs + (r * 192 + 128 + c) * 4, WV + r * 64 + c);
    }
    cp_commit();

    int tx = tid & 15, ty = tid >> 4;
    u64 acc[4][6];
#pragma unroll
    for (int i = 0; i < 4; i++)
#pragma unroll
        for (int j = 0; j < 6; j++) acc[i][j] = 0ULL;

    cp_wait0();
    __syncthreads();

#pragma unroll 2
    for (int k0 = 0; k0 < 64; k0 += 4) {
        float4 xv[4];
#pragma unroll
        for (int i = 0; i < 4; i++)
            xv[i] = *(const float4*)&Xs[(ty * 4 + i) * XSTRIDE + k0];
#pragma unroll
        for (int kk = 0; kk < 4; kk++) {
            u64 wv[6];
#pragma unroll
            for (int j = 0; j < 6; j++)
                wv[j] = *(const u64*)&Ws[(k0 + kk) * 192 + tx * 2 + 32 * j];
            u64 xd[4];
            xd[0] = dup2(kk == 0 ? xv[0].x : kk == 1 ? xv[0].y : kk == 2 ? xv[0].z : xv[0].w);
            xd[1] = dup2(kk == 0 ? xv[1].x : kk == 1 ? xv[1].y : kk == 2 ? xv[1].z : xv[1].w);
            xd[2] = dup2(kk == 0 ? xv[2].x : kk == 1 ? xv[2].y : kk == 2 ? xv[2].z : xv[2].w);
            xd[3] = dup2(kk == 0 ? xv[3].x : kk == 1 ? xv[3].y : kk == 2 ? xv[3].z : xv[3].w);
#pragma unroll
            for (int i = 0; i < 4; i++)
#pragma unroll
                for (int j = 0; j < 6; j++)
                    acc[i][j] = ffma2(xd[i], wv[j], acc[i][j]);
        }
    }

    const u64 scale2 = dup2(0.03125f);   // 1/sqrt(1024)
    size_t base = ((size_t)b * NN + n0) * CC;
    float* Qo = g_Q + base;
    float* Ko = g_K + base;
    float* Vo = g_V + base;
#pragma unroll
    for (int i = 0; i < 4; i++) {
        int r = ty * 4 + i;
        int co = tx * 2;
#pragma unroll
        for (int j = 0; j < 2; j++) {
            *(u64*)&Qo[r * 64 + co + 32 * j] = fmul2(acc[i][j], scale2);
            *(u64*)&Ko[r * 64 + co + 32 * j] = acc[i][2 + j];
            *(u64*)&Vo[r * 64 + co + 32 * j] = acc[i][4 + j];
        }
    }
}

// ---------------------------------------------------------------------------
// Flash attention + residual. 128 q-rows/CTA, 512 threads (4 warps/SMSP),
// 4x4 reg tile. K/V cp.async ring-3, Ps double-buffered, 1 barrier/key-tile.
// Pipeline: bar -> cp(kt+1) -> S(kt) -> PV(kt-1) -> softmax(kt) -> corr.
// ---------------------------------------------------------------------------
#define KSTR 68
#define QROWS 128

__device__ __forceinline__ void pv_accum(const float* __restrict__ Vp,
                                         const float* __restrict__ Pr,
                                         u64 (&o2)[4][2], int tx, int ty) {
#pragma unroll 2
    for (int k0 = 0; k0 < 64; k0 += 4) {
        ulonglong2 vv[4];
#pragma unroll
        for (int kk = 0; kk < 4; kk++)
            vv[kk] = *(const ulonglong2*)&Vp[(k0 + kk) * 64 + tx * 4];
#pragma unroll
        for (int i = 0; i < 4; i++) {
            float4 p = *(const float4*)&Pr[(ty * 4 + i) * KSTR + k0];
            u64 d;
            d = dup2(p.x);
            o2[i][0] = ffma2(d, vv[0].x, o2[i][0]);
            o2[i][1] = ffma2(d, vv[0].y, o2[i][1]);
            d = dup2(p.y);
            o2[i][0] = ffma2(d, vv[1].x, o2[i][0]);
            o2[i][1] = ffma2(d, vv[1].y, o2[i][1]);
            d = dup2(p.z);
            o2[i][0] = ffma2(d, vv[2].x, o2[i][0]);
            o2[i][1] = ffma2(d, vv[2].y, o2[i][1]);
            d = dup2(p.w);
            o2[i][0] = ffma2(d, vv[3].x, o2[i][0]);
            o2[i][1] = ffma2(d, vv[3].y, o2[i][1]);
        }
    }
}

__global__ void __launch_bounds__(512) k_attn(int pp) {
    extern __shared__ float sm[];
    float* Qs = sm;                            // 128 x 68
    float* Ks = Qs + QROWS * KSTR;             // 3 x (64 x 68)
    float* Vs = Ks + 3 * 64 * KSTR;            // 3 x (64 x 64)
    float* Ps = Vs + 3 * 64 * 64;              // 2 x (128 x 68)
    uint32_t sQ = (uint32_t)__cvta_generic_to_shared(Qs);
    uint32_t sK = (uint32_t)__cvta_generic_to_shared(Ks);
    uint32_t sV = (uint32_t)__cvta_generic_to_shared(Vs);

    int b = blockIdx.y;
    int n0 = blockIdx.x * QROWS;
    int tid = threadIdx.x, tx = tid & 15, ty = tid >> 4;   // ty in [0,32)

    const float* Qg = g_Q + ((size_t)b * NN + n0) * CC;
    const float* Kg = g_K + (size_t)b * NN * CC;
    const float* Vg = g_V + (size_t)b * NN * CC;

    // prologue: Q (4 chunks/thread) + K0/V0 (2+2)
#pragma unroll
    for (int t = 0; t < 4; t++) {
        int i = tid + t * 512;
        int r = i >> 4, c = (i & 15) << 2;
        cp16(sQ + (r * KSTR + c) * 4, Qg + r * 64 + c);
    }
#pragma unroll
    for (int t = 0; t < 2; t++) {
        int i = tid + t * 512;
        int r = i >> 4, c = (i & 15) << 2;
        cp16(sK + (r * KSTR + c) * 4, Kg + r * 64 + c);
        cp16(sV + (r * 64 + c) * 4,   Vg + r * 64 + c);
    }
    cp_commit();

    u64 o2[4][2];
    float mrun[4], lrun[4];
#pragma unroll
    for (int i = 0; i < 4; i++) {
        mrun[i] = -1e30f;
        lrun[i] = 0.0f;
        o2[i][0] = 0ULL;
        o2[i][1] = 0ULL;
    }

#pragma unroll 1
    for (int kt = 0; kt < 16; ++kt) {
        cp_wait0();        // tile kt resident
        __syncthreads();   // cp visible; Ps(kt-1) visible; prev reads done

        // prefetch tile kt+1 into ring slot (kt+1)%3
        if (kt + 1 < 16) {
            int s = (kt + 1) % 3;
            const float* Kt = Kg + (kt + 1) * 64 * 64;
            const float* Vt = Vg + (kt + 1) * 64 * 64;
            uint32_t dK = sK + s * 64 * KSTR * 4;
            uint32_t dV = sV + s * 64 * 64 * 4;
#pragma unroll
            for (int t = 0; t < 2; t++) {
                int i = tid + t * 512;
                int r = i >> 4, c = (i & 15) << 2;
                cp16(dK + (r * KSTR + c) * 4, Kt + r * 64 + c);
                cp16(dV + (r * 64 + c) * 4,   Vt + r * 64 + c);
            }
        }
        cp_commit();

        // ---- S = Qs @ K(kt)^T, packed over channel pairs ----
        const float* Kp = Ks + (kt % 3) * 64 * KSTR;
        u64 acc[4][4];
#pragma unroll
        for (int i = 0; i < 4; i++)
#pragma unroll
            for (int j = 0; j < 4; j++) acc[i][j] = 0ULL;

#pragma unroll 2
        for (int c0 = 0; c0 < 64; c0 += 4) {
            ulonglong2 qv[4], kv[4];
#pragma unroll
            for (int i = 0; i < 4; i++)
                qv[i] = *(const ulonglong2*)&Qs[(ty * 4 + i) * KSTR + c0];
#pragma unroll
            for (int j = 0; j < 4; j++)
                kv[j] = *(const ulonglong2*)&Kp[(tx + 16 * j) * KSTR + c0];
#pragma unroll
            for (int i = 0; i < 4; i++)
#pragma unroll
                for (int j = 0; j < 4; j++) {
                    acc[i][j] = ffma2(qv[i].x, kv[j].x, acc[i][j]);
                    acc[i][j] = ffma2(qv[i].y, kv[j].y, acc[i][j]);
                }
        }

        float s[4][4];
#pragma unroll
        for (int i = 0; i < 4; i++)
#pragma unroll
            for (int j = 0; j < 4; j++) {
                float2 p = u2f2(acc[i][j]);
                s[i][j] = p.x + p.y;
            }

        // ---- PV(kt-1): overlaps softmax latency below via scheduler ----
        if (kt > 0)
            pv_accum(Vs + ((kt - 1) % 3) * 4096,
                     Ps + ((kt - 1) & 1) * QROWS * KSTR, o2, tx, ty);

        // ---- online softmax for tile kt; write Ps[kt&1]; defer corr ----
        float corr[4];
        float* Pw = Ps + (kt & 1) * QROWS * KSTR;
#pragma unroll
        for (int i = 0; i < 4; i++) {
            float mx = fmaxf(fmaxf(s[i][0], s[i][1]), fmaxf(s[i][2], s[i][3]));
#pragma unroll
            for (int d = 1; d < 16; d <<= 1)
                mx = fmaxf(mx, __shfl_xor_sync(0xffffffffu, mx, d, 16));
            float mnew = fmaxf(mrun[i], mx);
            corr[i] = __expf(mrun[i] - mnew);
            float rs = 0.0f;
#pragma unroll
            for (int j = 0; j < 4; j++) {
                float p = __expf(s[i][j] - mnew);
                s[i][j] = p;
                rs += p;
            }
#pragma unroll
            for (int d = 1; d < 16; d <<= 1)
                rs += __shfl_xor_sync(0xffffffffu, rs, d, 16);
            lrun[i] = lrun[i] * corr[i] + rs;
            mrun[i] = mnew;
#pragma unroll
            for (int j = 0; j < 4; j++)
                Pw[(ty * 4 + i) * KSTR + tx + 16 * j] = s[i][j];
        }

        // ---- apply correction AFTER PV(kt-1) contributions ----
#pragma unroll
        for (int i = 0; i < 4; i++) {
            u64 c2 = dup2(corr[i]);
            o2[i][0] = fmul2(o2[i][0], c2);
            o2[i][1] = fmul2(o2[i][1], c2);
        }
    }

    // tail: PV for last tile (kt=15), after making Ps[1] visible
    __syncthreads();
    pv_accum(Vs + (15 % 3) * 4096, Ps + (15 & 1) * QROWS * KSTR, o2, tx, ty);

    // epilogue: Xout = O / l + Xin
    const float* Xin = g_X[pp] + ((size_t)b * NN + n0) * CC;
    float* Xout = g_X[pp ^ 1] + ((size_t)b * NN + n0) * CC;
#pragma unroll
    for (int i = 0; i < 4; i++) {
        float inv = 1.0f / lrun[i];
        int r = ty * 4 + i;
        float2 a = u2f2(o2[i][0]);
        float2 bb2 = u2f2(o2[i][1]);
        float4 xi = *(const float4*)&Xin[r * 64 + tx * 4];
        float4 res;
        res.x = a.x * inv + xi.x;
        res.y = a.y * inv + xi.y;
        res.z = bb2.x * inv + xi.z;
        res.w = bb2.y * inv + xi.w;
        *(float4*)&Xout[r * 64 + tx * 4] = res;
    }
}

// ---------------------------------------------------------------------------
// Head: pred[b] = mean_c(X[b]) @ last_W^T + last_b
// ---------------------------------------------------------------------------
__global__ void k_head(const float* __restrict__ lw,
                       const float* __restrict__ lb,
                       float* __restrict__ out) {
    __shared__ float meanv[NN];
    __shared__ float red[8];
    int b = blockIdx.x;
    const float* Xb = g_X[0] + (size_t)b * NN * CC;   // DEPTH even -> final in buf 0

    for (int n = threadIdx.x; n < NN; n += 256) {
        const float4* p = (const float4*)(Xb + (size_t)n * CC);
        float s = 0.0f;
#pragma unroll
        for (int q = 0; q < 16; q++) {
            float4 v = p[q];
            s += v.x + v.y + v.z + v.w;
        }
        meanv[n] = s * (1.0f / 64.0f);
    }
    __syncthreads();

    for (int cls = 0; cls < NCLS; cls++) {
        float s = 0.0f;
        for (int n = threadIdx.x; n < NN; n += 256)
            s += meanv[n] * lw[cls * NN + n];
#pragma unroll
        for (int d = 16; d; d >>= 1) s += __shfl_xor_sync(0xffffffffu, s, d);
        if ((threadIdx.x & 31) == 0) red[threadIdx.x >> 5] = s;
        __syncthreads();
        if (threadIdx.x == 0) {
            float t = 0.0f;
#pragma unroll
            for (int w = 0; w < 8; w++) t += red[w];
            out[b * NCLS + cls] = t + lb[cls];
        }
        __syncthreads();
    }
}

// ---------------------------------------------------------------------------
extern "C" void kernel_launch(void* const* d_in, const int* in_sizes, int n_in,
                              void* d_out, int out_size) {
    (void)in_sizes; (void)n_in; (void)out_size;
    const float* img = (const float*)d_in[0];
    const float* WV  = (const float*)d_in[1];
    const float* WK  = (const float*)d_in[2];
    const float* WQ  = (const float*)d_in[3];
    const float* lw  = (const float*)d_in[4];
    const float* lb  = (const float*)d_in[5];
    float* out = (float*)d_out;

    const int QKV_SMEM  = (64 * XSTRIDE + 64 * 192) * 4;
    const int ATTN_SMEM = (QROWS * KSTR + 3 * 64 * KSTR + 3 * 64 * 64 + 2 * QROWS * KSTR) * 4; // 205824
    cudaFuncSetAttribute(k_qkv,  cudaFuncAttributeMaxDynamicSharedMemorySize, QKV_SMEM);
    cudaFuncSetAttribute(k_attn, cudaFuncAttributeMaxDynamicSharedMemorySize, ATTN_SMEM);

    dim3 gq(16, 32), ga(8, 32);
    k_transpose<<<gq, 256>>>(img);
    for (int l = 0; l < DEPTH; l++) {
        k_qkv<<<gq, 256, QKV_SMEM>>>(WQ, WK, WV, l & 1);
        k_attn<<<ga, 512, ATTN_SMEM>>>(l & 1);
    }
    k_head<<<32, 256>>>(lw, lb, out);
}

// round 8
// speedup vs baseline: 1.2742x; 1.2742x over previous
#include <cuda_runtime.h>
#include <cuda_bf16.h>
#include <cstdint>

#define BB 32
#define CC 64
#define NN 1024
#define DEPTH 8
#define NCLS 10

using u64 = unsigned long long;

static __device__ float g_X[2][BB * NN * CC];
static __device__ float g_Qh[BB * NN * CC];
static __device__ float g_Ql[BB * NN * CC];
static __device__ float g_Kh[BB * NN * CC];
static __device__ float g_Kl[BB * NN * CC];
static __device__ float g_Vth[BB * CC * NN];   // V^T hi: [b][c][n]
static __device__ float g_Vtl[BB * CC * NN];   // V^T lo

// ---------------- packed fp32 helpers ----------------
__device__ __forceinline__ u64 ffma2(u64 a, u64 b, u64 c) {
    u64 d; asm("fma.rn.f32x2 %0, %1, %2, %3;" : "=l"(d) : "l"(a), "l"(b), "l"(c)); return d;
}
__device__ __forceinline__ u64 fmul2(u64 a, u64 b) {
    u64 d; asm("mul.rn.f32x2 %0, %1, %2;" : "=l"(d) : "l"(a), "l"(b)); return d;
}
__device__ __forceinline__ u64 dup2(float x) {
    u64 r; asm("mov.b64 %0, {%1, %1};" : "=l"(r) : "f"(x)); return r;
}
__device__ __forceinline__ float2 u2f2(u64 v) {
    float2 r; asm("mov.b64 {%0, %1}, %2;" : "=f"(r.x), "=f"(r.y) : "l"(v)); return r;
}
__device__ __forceinline__ float tf32r(float x) {
    uint32_t u; asm("cvt.rna.tf32.f32 %0, %1;" : "=r"(u) : "f"(x)); return __uint_as_float(u);
}
// ---------------- cp.async ----------------
__device__ __forceinline__ void cp16(uint32_t dst, const float* src) {
    asm volatile("cp.async.cg.shared.global [%0], [%1], 16;" :: "r"(dst), "l"(src));
}
__device__ __forceinline__ void cp_commit() { asm volatile("cp.async.commit_group;" ::: "memory"); }
__device__ __forceinline__ void cp_wait0()  { asm volatile("cp.async.wait_group 0;" ::: "memory"); }

// ---------------- warp mma.sync tf32 m16n8k8 ----------------
__device__ __forceinline__ void mma8(float4& d, const uint4& a, uint32_t b0, uint32_t b1) {
    asm volatile(
        "mma.sync.aligned.m16n8k8.row.col.f32.tf32.tf32.f32 "
        "{%0,%1,%2,%3}, {%4,%5,%6,%7}, {%8,%9}, {%0,%1,%2,%3};"
        : "+f"(d.x), "+f"(d.y), "+f"(d.z), "+f"(d.w)
        : "r"(a.x), "r"(a.y), "r"(a.z), "r"(a.w), "r"(b0), "r"(b1));
}

// ---------------------------------------------------------------------------
__global__ void k_transpose(const float* __restrict__ img) {
    __shared__ float t[64][65];
    int b = blockIdx.y, n0 = blockIdx.x * 64;
    const float* src = img + (size_t)b * CC * NN;
    for (int i = threadIdx.x; i < 4096; i += 256) t[i >> 6][i & 63] = src[(i >> 6) * NN + n0 + (i & 63)];
    __syncthreads();
    float* dst = g_X[0] + ((size_t)b * NN + n0) * CC;
    for (int i = threadIdx.x; i < 4096; i += 256) dst[(i >> 6) * CC + (i & 63)] = t[i & 63][i >> 6];
}
// ---------------------------------------------------------------------------
// QKV (f32x2) -> split tf32 hi/lo outputs; V transposed.
#define XSTRIDE 68
__global__ void __launch_bounds__(256) k_qkv(const float* __restrict__ WQ,
                                             const float* __restrict__ WK,
                                             const float* __restrict__ WV, int pp) {
    extern __shared__ float sm[];
    float* Xs = sm;
    float* Ws = sm + 64 * XSTRIDE;
    uint32_t sXs = (uint32_t)__cvta_generic_to_shared(Xs);
    int b = blockIdx.y, n0 = blockIdx.x * 64, tid = threadIdx.x;
    const float* Xin = g_X[pp] + ((size_t)b * NN + n0) * CC;
#pragma unroll
    for (int t = 0; t < 4; t++) {
        int i = tid + t * 256, r = i >> 4, c = (i & 15) << 2;
        cp16(sXs + (r * XSTRIDE + c) * 4, Xin + r * 64 + c);
    }
    cp_commit();
    for (int i = tid; i < 64 * 192; i += 256) {
        int k = i / 192, c = i - k * 192;
        Ws[i] = c < 64 ? WQ[k * 64 + c] : (c < 128 ? WK[k * 64 + c - 64] : WV[k * 64 + c - 128]);
    }
    int tx = tid & 15, ty = tid >> 4;
    u64 acc[4][6];
#pragma unroll
    for (int i = 0; i < 4; i++)
#pragma unroll
        for (int j = 0; j < 6; j++) acc[i][j] = 0ULL;
    cp_wait0();
    __syncthreads();
#pragma unroll 2
    for (int k0 = 0; k0 < 64; k0 += 4) {
        float4 xv[4];
#pragma unroll
        for (int i = 0; i < 4; i++) xv[i] = *(const float4*)&Xs[(ty * 4 + i) * XSTRIDE + k0];
#pragma unroll
        for (int kk = 0; kk < 4; kk++) {
            u64 wv[6];
#pragma unroll
            for (int j = 0; j < 6; j++) wv[j] = *(const u64*)&Ws[(k0 + kk) * 192 + tx * 2 + 32 * j];
            u64 xd[4];
#pragma unroll
            for (int i = 0; i < 4; i++)
                xd[i] = dup2(kk == 0 ? xv[i].x : kk == 1 ? xv[i].y : kk == 2 ? xv[i].z : xv[i].w);
#pragma unroll
            for (int i = 0; i < 4; i++)
#pragma unroll
                for (int j = 0; j < 6; j++) acc[i][j] = ffma2(xd[i], wv[j], acc[i][j]);
        }
    }
    const u64 scale2 = dup2(0.03125f);
    size_t base = ((size_t)b * NN + n0) * CC;
#pragma unroll
    for (int i = 0; i < 4; i++) {
        int r = ty * 4 + i, co = tx * 2;
#pragma unroll
        for (int j = 0; j < 2; j++) {
            int c = co + 32 * j;
            float2 q = u2f2(fmul2(acc[i][j], scale2));
            float qhx = tf32r(q.x), qhy = tf32r(q.y);
            *(float2*)&g_Qh[base + r * 64 + c] = make_float2(qhx, qhy);
            *(float2*)&g_Ql[base + r * 64 + c] = make_float2(tf32r(q.x - qhx), tf32r(q.y - qhy));
            float2 kv = u2f2(acc[i][2 + j]);
            float khx = tf32r(kv.x), khy = tf32r(kv.y);
            *(float2*)&g_Kh[base + r * 64 + c] = make_float2(khx, khy);
            *(float2*)&g_Kl[base + r * 64 + c] = make_float2(tf32r(kv.x - khx), tf32r(kv.y - khy));
            float2 vv = u2f2(acc[i][4 + j]);
            float vhx = tf32r(vv.x), vhy = tf32r(vv.y);
            size_t vb = (size_t)b * CC * NN + (size_t)(n0 + r);
            g_Vth[vb + (size_t)c * NN] = vhx;
            g_Vtl[vb + (size_t)c * NN] = tf32r(vv.x - vhx);
            g_Vth[vb + (size_t)(c + 1) * NN] = vhy;
            g_Vtl[vb + (size_t)(c + 1) * NN] = tf32r(vv.y - vhy);
        }
    }
}
// ---------------------------------------------------------------------------
// mma.sync flash attention. CTA = 128 q-rows x batch, 8 warps, each warp owns
// 16 rows. Q frags persistent in regs; K/V double-buffered smem (pad 68);
// P via per-warp private smem staging. Online softmax in fragments.
// smem float offsets:
#define KH(s) ((s) * 4352)
#define KL(s) (8704 + (s) * 4352)
#define VH(s) (17408 + (s) * 4352)
#define VL(s) (26112 + (s) * 4352)
#define PST(w) (34816 + (w) * 2176)       // Ph at +0, Pl at +1088
#define ATTN_SMEMF 52224                   // floats (208896 B)

__device__ __forceinline__ void ldtile(uint32_t dst, const float* src, int stride, int tid) {
    // 64x64 tile -> smem rows of stride 68
#pragma unroll
    for (int t = 0; t < 4; t++) {
        int q = tid + t * 256;
        int r = q >> 4, c = (q & 15) << 2;
        cp16(dst + (r * 68 + c) * 4, src + (size_t)r * stride + c);
    }
}

__global__ void __launch_bounds__(256) k_attn(int pp) {
    extern __shared__ float sf[];
    uint32_t sb = (uint32_t)__cvta_generic_to_shared(sf);
    int b = blockIdx.y, n0 = blockIdx.x * 128, tid = threadIdx.x;
    int wid = tid >> 5, lane = tid & 31;
    int qr = lane >> 2, qc = lane & 3;          // fragment row/col ids
    int wrow = wid * 16;                        // warp's row base within CTA

    const float* Qhg = g_Qh + ((size_t)b * NN + n0) * CC;
    const float* Qlg = g_Ql + ((size_t)b * NN + n0) * CC;
    const float* Khg = g_Kh + (size_t)b * NN * CC;
    const float* Klg = g_Kl + (size_t)b * NN * CC;
    const float* Vhg = g_Vth + (size_t)b * CC * NN;
    const float* Vlg = g_Vtl + (size_t)b * CC * NN;

    // K0/V0 prefetch
    ldtile(sb + KH(0) * 4, Khg, 64, tid);
    ldtile(sb + KL(0) * 4, Klg, 64, tid);
    ldtile(sb + VH(0) * 4, Vhg, NN, tid);
    ldtile(sb + VL(0) * 4, Vlg, NN, tid);
    cp_commit();

    // persistent Q fragments
    uint4 Ah[8], Al[8];
    {
        const float* q0h = Qhg + (size_t)(wrow + qr) * 64;
        const float* q8h = q0h + 8 * 64;
        const float* q0l = Qlg + (size_t)(wrow + qr) * 64;
        const float* q8l = q0l + 8 * 64;
#pragma unroll
        for (int k8 = 0; k8 < 8; k8++) {
            int c = qc + 8 * k8;
            Ah[k8] = make_uint4(__float_as_uint(q0h[c]), __float_as_uint(q8h[c]),
                                __float_as_uint(q0h[c + 4]), __float_as_uint(q8h[c + 4]));
            Al[k8] = make_uint4(__float_as_uint(q0l[c]), __float_as_uint(q8l[c]),
                                __float_as_uint(q0l[c + 4]), __float_as_uint(q8l[c + 4]));
        }
    }

    float4 O[8];
#pragma unroll
    for (int nt = 0; nt < 8; nt++) O[nt] = make_float4(0.f, 0.f, 0.f, 0.f);
    float m0 = -1e30f, m1 = -1e30f, l0 = 0.f, l1 = 0.f;

    float* Pw = sf + PST(wid);        // Ph: 16x68, Pl at +1088
    const uint32_t FULL = 0xffffffffu;

#pragma unroll 1
    for (int kt = 0; kt < 16; ++kt) {
        cp_wait0();
        __syncthreads();
        if (kt + 1 < 16) {
            int s = (kt + 1) & 1;
            ldtile(sb + KH(s) * 4, Khg + (kt + 1) * 4096, 64, tid);
            ldtile(sb + KL(s) * 4, Klg + (kt + 1) * 4096, 64, tid);
            ldtile(sb + VH(s) * 4, Vhg + (kt + 1) * 64, NN, tid);
            ldtile(sb + VL(s) * 4, Vlg + (kt + 1) * 64, NN, tid);
        }
        cp_commit();

        const float* Kh = sf + KH(kt & 1);
        const float* Kl = sf + KL(kt & 1);
        const float* Vh = sf + VH(kt & 1);
        const float* Vl = sf + VL(kt & 1);

        // ---- S = Qh*Kh + Qh*Kl + Ql*Kh ----
        float4 S[8];
#pragma unroll
        for (int nt = 0; nt < 8; nt++) S[nt] = make_float4(0.f, 0.f, 0.f, 0.f);
#pragma unroll
        for (int k8 = 0; k8 < 8; k8++) {
#pragma unroll
            for (int nt = 0; nt < 8; nt++) {
                // B frag: K[key = 8nt+qr][ch = 8k8+qc (+4)]
                int ab = (8 * nt + qr) * 68 + 8 * k8 + qc;
                uint32_t bh0 = __float_as_uint(Kh[ab]);
                uint32_t bh1 = __float_as_uint(Kh[ab + 4]);
                uint32_t bl0 = __float_as_uint(Kl[ab]);
                uint32_t bl1 = __float_as_uint(Kl[ab + 4]);
                mma8(S[nt], Ah[k8], bh0, bh1);
                mma8(S[nt], Ah[k8], bl0, bl1);
                mma8(S[nt], Al[k8], bh0, bh1);
            }
        }

        // ---- online softmax on fragments ----
        float mx0 = -1e30f, mx1 = -1e30f;
#pragma unroll
        for (int nt = 0; nt < 8; nt++) {
            mx0 = fmaxf(mx0, fmaxf(S[nt].x, S[nt].y));
            mx1 = fmaxf(mx1, fmaxf(S[nt].z, S[nt].w));
        }
        mx0 = fmaxf(mx0, __shfl_xor_sync(FULL, mx0, 1));
        mx0 = fmaxf(mx0, __shfl_xor_sync(FULL, mx0, 2));
        mx1 = fmaxf(mx1, __shfl_xor_sync(FULL, mx1, 1));
        mx1 = fmaxf(mx1, __shfl_xor_sync(FULL, mx1, 2));
        float mn0 = fmaxf(m0, mx0), mn1 = fmaxf(m1, mx1);
        float c0 = __expf(m0 - mn0), c1 = __expf(m1 - mn1);
        m0 = mn0; m1 = mn1;
        float ps0 = 0.f, ps1 = 0.f;
#pragma unroll
        for (int nt = 0; nt < 8; nt++) {
            float px = __expf(S[nt].x - m0), py = __expf(S[nt].y - m0);
            float pz = __expf(S[nt].z - m1), pw = __expf(S[nt].w - m1);
            ps0 += px + py; ps1 += pz + pw;
            float hx = tf32r(px), hy = tf32r(py), hz = tf32r(pz), hw = tf32r(pw);
            int o0 = qr * 68 + 8 * nt + 2 * qc;
            *(float2*)&Pw[o0] = make_float2(hx, hy);
            *(float2*)&Pw[o0 + 8 * 68] = make_float2(hz, hw);
            *(float2*)&Pw[1088 + o0] = make_float2(tf32r(px - hx), tf32r(py - hy));
            *(float2*)&Pw[1088 + o0 + 8 * 68] = make_float2(tf32r(pz - hz), tf32r(pw - hw));
        }
        l0 = l0 * c0 + ps0;
        l1 = l1 * c1 + ps1;
#pragma unroll
        for (int nt = 0; nt < 8; nt++) {
            O[nt].x *= c0; O[nt].y *= c0; O[nt].z *= c1; O[nt].w *= c1;
        }
        __syncwarp();

        // ---- O += Ph*Vh + Ph*Vl + Pl*Vh ----
#pragma unroll
        for (int k8 = 0; k8 < 8; k8++) {
            int pa = qr * 68 + 8 * k8 + qc;
            uint4 Ph = make_uint4(__float_as_uint(Pw[pa]),
                                  __float_as_uint(Pw[pa + 8 * 68]),
                                  __float_as_uint(Pw[pa + 4]),
                                  __float_as_uint(Pw[pa + 4 + 8 * 68]));
            uint4 Pl = make_uint4(__float_as_uint(Pw[1088 + pa]),
                                  __float_as_uint(Pw[1088 + pa + 8 * 68]),
                                  __float_as_uint(Pw[1088 + pa + 4]),
                                  __float_as_uint(Pw[1088 + pa + 4 + 8 * 68]));
#pragma unroll
            for (int nt = 0; nt < 8; nt++) {
                // B frag: Vt[outch = 8nt+qr][key = 8k8+qc (+4)]
                int vb = (8 * nt + qr) * 68 + 8 * k8 + qc;
                uint32_t bh0 = __float_as_uint(Vh[vb]);
                uint32_t bh1 = __float_as_uint(Vh[vb + 4]);
                uint32_t bl0 = __float_as_uint(Vl[vb]);
                uint32_t bl1 = __float_as_uint(Vl[vb + 4]);
                mma8(O[nt], Ph, bh0, bh1);
                mma8(O[nt], Ph, bl0, bl1);
                mma8(O[nt], Pl, bh0, bh1);
            }
        }
    }

    // final l: quad reduce
    l0 += __shfl_xor_sync(FULL, l0, 1);
    l0 += __shfl_xor_sync(FULL, l0, 2);
    l1 += __shfl_xor_sync(FULL, l1, 1);
    l1 += __shfl_xor_sync(FULL, l1, 2);
    float i0 = 1.0f / l0, i1 = 1.0f / l1;

    const float* Xi0 = g_X[pp] + ((size_t)(b * NN + n0) + wrow + qr) * CC;
    const float* Xi8 = Xi0 + 8 * CC;
    float* Xo0 = g_X[pp ^ 1] + ((size_t)(b * NN + n0) + wrow + qr) * CC;
    float* Xo8 = Xo0 + 8 * CC;
#pragma unroll
    for (int nt = 0; nt < 8; nt++) {
        int c = 8 * nt + 2 * qc;
        float2 a = *(const float2*)&Xi0[c];
        float2 bb = *(const float2*)&Xi8[c];
        *(float2*)&Xo0[c] = make_float2(O[nt].x * i0 + a.x, O[nt].y * i0 + a.y);
        *(float2*)&Xo8[c] = make_float2(O[nt].z * i1 + bb.x, O[nt].w * i1 + bb.y);
    }
}
// ---------------------------------------------------------------------------
__global__ void k_head(const float* __restrict__ lw, const float* __restrict__ lb,
                       float* __restrict__ out) {
    __shared__ float meanv[NN];
    __shared__ float red[8];
    int b = blockIdx.x;
    const float* Xb = g_X[0] + (size_t)b * NN * CC;
    for (int n = threadIdx.x; n < NN; n += 256) {
        const float4* p = (const float4*)(Xb + (size_t)n * CC);
        float s = 0.0f;
#pragma unroll
        for (int q = 0; q < 16; q++) { float4 v = p[q]; s += v.x + v.y + v.z + v.w; }
        meanv[n] = s * (1.0f / 64.0f);
    }
    __syncthreads();
    for (int cls = 0; cls < NCLS; cls++) {
        float s = 0.0f;
        for (int n = threadIdx.x; n < NN; n += 256) s += meanv[n] * lw[cls * NN + n];
#pragma unroll
        for (int d = 16; d; d >>= 1) s += __shfl_xor_sync(0xffffffffu, s, d);
        if ((threadIdx.x & 31) == 0) red[threadIdx.x >> 5] = s;
        __syncthreads();
        if (threadIdx.x == 0) {
            float t = 0.0f;
#pragma unroll
            for (int w = 0; w < 8; w++) t += red[w];
            out[b * NCLS + cls] = t + lb[cls];
        }
        __syncthreads();
    }
}
// ---------------------------------------------------------------------------
extern "C" void kernel_launch(void* const* d_in, const int* in_sizes, int n_in,
                              void* d_out, int out_size) {
    (void)in_sizes; (void)n_in; (void)out_size;
    const float* img = (const float*)d_in[0];
    const float* WV  = (const float*)d_in[1];
    const float* WK  = (const float*)d_in[2];
    const float* WQ  = (const float*)d_in[3];
    const float* lw  = (const float*)d_in[4];
    const float* lb  = (const float*)d_in[5];
    float* out = (float*)d_out;

    const int QKV_SMEM  = (64 * XSTRIDE + 64 * 192) * 4;
    const int ATTN_SMEM = ATTN_SMEMF * 4;    // 208896 B
    cudaFuncSetAttribute(k_qkv,  cudaFuncAttributeMaxDynamicSharedMemorySize, QKV_SMEM);
    cudaFuncSetAttribute(k_attn, cudaFuncAttributeMaxDynamicSharedMemorySize, ATTN_SMEM);

    dim3 gq(16, 32), ga(8, 32);
    k_transpose<<<gq, 256>>>(img);
    for (int l = 0; l < DEPTH; l++) {
        k_qkv<<<gq, 256, QKV_SMEM>>>(WQ, WK, WV, l & 1);
        k_attn<<<ga, 256, ATTN_SMEM>>>(l & 1);
    }
    k_head<<<32, 256>>>(lw, lb, out);
}

// round 10
// speedup vs baseline: 1.4342x; 1.1256x over previous
#include <cuda_runtime.h>
#include <cuda_bf16.h>
#include <cstdint>

#define BB 32
#define CC 64
#define NN 1024
#define DEPTH 8
#define NCLS 10

using u64 = unsigned long long;

static __device__ float g_X[2][BB * NN * CC];
static __device__ float g_Qh[BB * NN * CC];
static __device__ float g_Ql[BB * NN * CC];
static __device__ float g_Kh[BB * NN * CC];
static __device__ float g_Kl[BB * NN * CC];
static __device__ float g_Vth[BB * CC * NN];   // V^T hi: [b][c][n]
static __device__ float g_Vtl[BB * CC * NN];   // V^T lo

// ---------------- packed fp32 helpers ----------------
__device__ __forceinline__ u64 ffma2(u64 a, u64 b, u64 c) {
    u64 d; asm("fma.rn.f32x2 %0, %1, %2, %3;" : "=l"(d) : "l"(a), "l"(b), "l"(c)); return d;
}
__device__ __forceinline__ u64 fmul2(u64 a, u64 b) {
    u64 d; asm("mul.rn.f32x2 %0, %1, %2;" : "=l"(d) : "l"(a), "l"(b)); return d;
}
__device__ __forceinline__ u64 dup2(float x) {
    u64 r; asm("mov.b64 %0, {%1, %1};" : "=l"(r) : "f"(x)); return r;
}
__device__ __forceinline__ float2 u2f2(u64 v) {
    float2 r; asm("mov.b64 {%0, %1}, %2;" : "=f"(r.x), "=f"(r.y) : "l"(v)); return r;
}
__device__ __forceinline__ float tf32r(float x) {
    uint32_t u; asm("cvt.rna.tf32.f32 %0, %1;" : "=r"(u) : "f"(x)); return __uint_as_float(u);
}
// ---------------- cp.async ----------------
__device__ __forceinline__ void cp16(uint32_t dst, const float* src) {
    asm volatile("cp.async.cg.shared.global [%0], [%1], 16;" :: "r"(dst), "l"(src));
}
__device__ __forceinline__ void cp_commit() { asm volatile("cp.async.commit_group;" ::: "memory"); }
__device__ __forceinline__ void cp_wait0()  { asm volatile("cp.async.wait_group 0;" ::: "memory"); }

// ---------------- warp mma.sync tf32 m16n8k8 ----------------
__device__ __forceinline__ void mma8(float4& d, const uint4& a, uint32_t b0, uint32_t b1) {
    asm volatile(
        "mma.sync.aligned.m16n8k8.row.col.f32.tf32.tf32.f32 "
        "{%0,%1,%2,%3}, {%4,%5,%6,%7}, {%8,%9}, {%0,%1,%2,%3};"
        : "+f"(d.x), "+f"(d.y), "+f"(d.z), "+f"(d.w)
        : "r"(a.x), "r"(a.y), "r"(a.z), "r"(a.w), "r"(b0), "r"(b1));
}

// ---------------------------------------------------------------------------
__global__ void k_transpose(const float* __restrict__ img) {
    __shared__ float t[64][65];
    int b = blockIdx.y, n0 = blockIdx.x * 64;
    const float* src = img + (size_t)b * CC * NN;
    for (int i = threadIdx.x; i < 4096; i += 256) t[i >> 6][i & 63] = src[(i >> 6) * NN + n0 + (i & 63)];
    __syncthreads();
    float* dst = g_X[0] + ((size_t)b * NN + n0) * CC;
    for (int i = threadIdx.x; i < 4096; i += 256) dst[(i >> 6) * CC + (i & 63)] = t[i & 63][i >> 6];
}
// ---------------------------------------------------------------------------
// QKV (f32x2) -> split tf32 hi/lo; V transposed via smem staging (coalesced).
#define XSTRIDE 68
__global__ void __launch_bounds__(256) k_qkv(const float* __restrict__ WQ,
                                             const float* __restrict__ WK,
                                             const float* __restrict__ WV, int pp) {
    extern __shared__ float sm[];
    float* Xs = sm;                       // 64 x 68
    float* Ws = sm + 64 * XSTRIDE;        // 64 x 192; later reused as V staging
    uint32_t sXs = (uint32_t)__cvta_generic_to_shared(Xs);
    int b = blockIdx.y, n0 = blockIdx.x * 64, tid = threadIdx.x;
    const float* Xin = g_X[pp] + ((size_t)b * NN + n0) * CC;
#pragma unroll
    for (int t = 0; t < 4; t++) {
        int i = tid + t * 256, r = i >> 4, c = (i & 15) << 2;
        cp16(sXs + (r * XSTRIDE + c) * 4, Xin + r * 64 + c);
    }
    cp_commit();
    for (int i = tid; i < 64 * 192; i += 256) {
        int k = i / 192, c = i - k * 192;
        Ws[i] = c < 64 ? WQ[k * 64 + c] : (c < 128 ? WK[k * 64 + c - 64] : WV[k * 64 + c - 128]);
    }
    int tx = tid & 15, ty = tid >> 4;
    u64 acc[4][6];
#pragma unroll
    for (int i = 0; i < 4; i++)
#pragma unroll
        for (int j = 0; j < 6; j++) acc[i][j] = 0ULL;
    cp_wait0();
    __syncthreads();
#pragma unroll 2
    for (int k0 = 0; k0 < 64; k0 += 4) {
        float4 xv[4];
#pragma unroll
        for (int i = 0; i < 4; i++) xv[i] = *(const float4*)&Xs[(ty * 4 + i) * XSTRIDE + k0];
#pragma unroll
        for (int kk = 0; kk < 4; kk++) {
            u64 wv[6];
#pragma unroll
            for (int j = 0; j < 6; j++) wv[j] = *(const u64*)&Ws[(k0 + kk) * 192 + tx * 2 + 32 * j];
            u64 xd[4];
#pragma unroll
            for (int i = 0; i < 4; i++)
                xd[i] = dup2(kk == 0 ? xv[i].x : kk == 1 ? xv[i].y : kk == 2 ? xv[i].z : xv[i].w);
#pragma unroll
            for (int i = 0; i < 4; i++)
#pragma unroll
                for (int j = 0; j < 6; j++) acc[i][j] = ffma2(xd[i], wv[j], acc[i][j]);
        }
    }
    const u64 scale2 = dup2(0.03125f);
    size_t base = ((size_t)b * NN + n0) * CC;
    // Q/K split writes (coalesced float2; global rows are 64-float aligned)
#pragma unroll
    for (int i = 0; i < 4; i++) {
        int r = ty * 4 + i, co = tx * 2;
#pragma unroll
        for (int j = 0; j < 2; j++) {
            int c = co + 32 * j;
            float2 q = u2f2(fmul2(acc[i][j], scale2));
            float qhx = tf32r(q.x), qhy = tf32r(q.y);
            *(float2*)&g_Qh[base + r * 64 + c] = make_float2(qhx, qhy);
            *(float2*)&g_Ql[base + r * 64 + c] = make_float2(tf32r(q.x - qhx), tf32r(q.y - qhy));
            float2 kv = u2f2(acc[i][2 + j]);
            float khx = tf32r(kv.x), khy = tf32r(kv.y);
            *(float2*)&g_Kh[base + r * 64 + c] = make_float2(khx, khy);
            *(float2*)&g_Kl[base + r * 64 + c] = make_float2(tf32r(kv.x - khx), tf32r(kv.y - khy));
        }
    }
    // V: stage split hi/lo into smem (reuse Ws), then coalesced V^T stores.
    // NOTE: stride-65 rows are only 4B-aligned for odd r -> scalar stores only.
    __syncthreads();                     // Ws reads complete
    float* Vsth = Ws;                    // 64 x 65
    float* Vstl = Ws + 4160;             // 64 x 65
#pragma unroll
    for (int i = 0; i < 4; i++) {
        int r = ty * 4 + i, co = tx * 2;
#pragma unroll
        for (int j = 0; j < 2; j++) {
            int c = co + 32 * j;
            float2 vv = u2f2(acc[i][4 + j]);
            float vhx = tf32r(vv.x), vhy = tf32r(vv.y);
            Vsth[r * 65 + c]     = vhx;
            Vsth[r * 65 + c + 1] = vhy;
            Vstl[r * 65 + c]     = tf32r(vv.x - vhx);
            Vstl[r * 65 + c + 1] = tf32r(vv.y - vhy);
        }
    }
    __syncthreads();
    size_t vb0 = (size_t)b * CC * NN + n0;
    for (int q = tid; q < 4096; q += 256) {
        int c = q >> 6, n = q & 63;
        g_Vth[vb0 + (size_t)c * NN + n] = Vsth[n * 65 + c];
        g_Vtl[vb0 + (size_t)c * NN + n] = Vstl[n * 65 + c];
    }
}
// ---------------------------------------------------------------------------
// mma.sync flash attention. CTA = 256 q-rows, 512 threads (16 warps, 4/SMSP),
// single wave (grid 4x32=128 CTAs). Q hi/lo in smem; K/V single-buffered;
// P via register shuffles (no smem round-trip).
// smem float offsets:
#define QH_ 0
#define QL_ 17408
#define KH_ 34816
#define KL_ 39168
#define VH_ 43520
#define VL_ 47872
#define ATTN_SMEMF 52224      // 208896 bytes

__device__ __forceinline__ void ldtile512(uint32_t dst, const float* src, int stride, int tid) {
#pragma unroll
    for (int t = 0; t < 2; t++) {
        int q = tid + t * 512;
        int r = q >> 4, c = (q & 15) << 2;
        cp16(dst + (r * 68 + c) * 4, src + (size_t)r * stride + c);
    }
}

__global__ void __launch_bounds__(512, 1) k_attn(int pp) {
    extern __shared__ float sf[];
    uint32_t sb = (uint32_t)__cvta_generic_to_shared(sf);
    int b = blockIdx.y, n0 = blockIdx.x * 256, tid = threadIdx.x;
    int wid = tid >> 5, lane = tid & 31;
    int qr = lane >> 2, qc = lane & 3;
    int wrow = wid * 16;
    int L1 = (lane & 0x1C) | ((lane & 3) >> 1);
    int L2 = L1 + 2;
    bool par = (lane & 1) != 0;
    const uint32_t FULL = 0xffffffffu;

    const float* Qhg = g_Qh + ((size_t)b * NN + n0) * CC;
    const float* Qlg = g_Ql + ((size_t)b * NN + n0) * CC;
    const float* Khg = g_Kh + (size_t)b * NN * CC;
    const float* Klg = g_Kl + (size_t)b * NN * CC;
    const float* Vhg = g_Vth + (size_t)b * CC * NN;
    const float* Vlg = g_Vtl + (size_t)b * CC * NN;

    // prologue: Q hi/lo (256x64) + K0/V0
#pragma unroll
    for (int t = 0; t < 8; t++) {
        int q = tid + t * 512;
        int r = q >> 4, c = (q & 15) << 2;
        cp16(sb + (QH_ + r * 68 + c) * 4, Qhg + r * 64 + c);
        cp16(sb + (QL_ + r * 68 + c) * 4, Qlg + r * 64 + c);
    }
    ldtile512(sb + KH_ * 4, Khg, 64, tid);
    ldtile512(sb + KL_ * 4, Klg, 64, tid);
    ldtile512(sb + VH_ * 4, Vhg, NN, tid);
    ldtile512(sb + VL_ * 4, Vlg, NN, tid);
    cp_commit();

    float4 O[8];
#pragma unroll
    for (int nt = 0; nt < 8; nt++) O[nt] = make_float4(0.f, 0.f, 0.f, 0.f);
    float m0 = -1e30f, m1 = -1e30f, l0 = 0.f, l1 = 0.f;

#pragma unroll 1
    for (int kt = 0; kt < 16; ++kt) {
        cp_wait0();
        __syncthreads();   // K/V(kt) (and Q on kt=0) resident & visible

        // ---- S = Qh*Kh + Qh*Kl + Ql*Kh ----
        float4 S[8];
#pragma unroll
        for (int nt = 0; nt < 8; nt++) S[nt] = make_float4(0.f, 0.f, 0.f, 0.f);
#pragma unroll
        for (int k8 = 0; k8 < 8; k8++) {
            int qa = QH_ + (wrow + qr) * 68 + 8 * k8 + qc;
            uint4 Ah = make_uint4(__float_as_uint(sf[qa]),
                                  __float_as_uint(sf[qa + 8 * 68]),
                                  __float_as_uint(sf[qa + 4]),
                                  __float_as_uint(sf[qa + 4 + 8 * 68]));
            int ql = qa + (QL_ - QH_);
            uint4 Al = make_uint4(__float_as_uint(sf[ql]),
                                  __float_as_uint(sf[ql + 8 * 68]),
                                  __float_as_uint(sf[ql + 4]),
                                  __float_as_uint(sf[ql + 4 + 8 * 68]));
#pragma unroll
            for (int nt = 0; nt < 8; nt++) {
                int ab = KH_ + (8 * nt + qr) * 68 + 8 * k8 + qc;
                uint32_t bh0 = __float_as_uint(sf[ab]);
                uint32_t bh1 = __float_as_uint(sf[ab + 4]);
                int al2 = ab + (KL_ - KH_);
                uint32_t bl0 = __float_as_uint(sf[al2]);
                uint32_t bl1 = __float_as_uint(sf[al2 + 4]);
                mma8(S[nt], Ah, bh0, bh1);
                mma8(S[nt], Ah, bl0, bl1);
                mma8(S[nt], Al, bh0, bh1);
            }
        }

        // ---- online softmax in fragments ----
        float mx0 = -1e30f, mx1 = -1e30f;
#pragma unroll
        for (int nt = 0; nt < 8; nt++) {
            mx0 = fmaxf(mx0, fmaxf(S[nt].x, S[nt].y));
            mx1 = fmaxf(mx1, fmaxf(S[nt].z, S[nt].w));
        }
        mx0 = fmaxf(mx0, __shfl_xor_sync(FULL, mx0, 1));
        mx0 = fmaxf(mx0, __shfl_xor_sync(FULL, mx0, 2));
        mx1 = fmaxf(mx1, __shfl_xor_sync(FULL, mx1, 1));
        mx1 = fmaxf(mx1, __shfl_xor_sync(FULL, mx1, 2));
        float mn0 = fmaxf(m0, mx0), mn1 = fmaxf(m1, mx1);
        float c0 = __expf(m0 - mn0), c1 = __expf(m1 - mn1);
        m0 = mn0; m1 = mn1;
        float ps0 = 0.f, ps1 = 0.f;
#pragma unroll
        for (int nt = 0; nt < 8; nt++) {
            S[nt].x = __expf(S[nt].x - m0);
            S[nt].y = __expf(S[nt].y - m0);
            S[nt].z = __expf(S[nt].z - m1);
            S[nt].w = __expf(S[nt].w - m1);
            ps0 += S[nt].x + S[nt].y;
            ps1 += S[nt].z + S[nt].w;
        }
        l0 = l0 * c0 + ps0;
        l1 = l1 * c1 + ps1;
#pragma unroll
        for (int nt = 0; nt < 8; nt++) {
            O[nt].x *= c0; O[nt].y *= c0; O[nt].z *= c1; O[nt].w *= c1;
        }

        // ---- PV: shuffle P fragments, split hi/lo at consumer ----
#pragma unroll
        for (int k8 = 0; k8 < 8; k8++) {
            float4 P = S[k8];
            float vx1 = __shfl_sync(FULL, P.x, L1);
            float vy1 = __shfl_sync(FULL, P.y, L1);
            float vz1 = __shfl_sync(FULL, P.z, L1);
            float vw1 = __shfl_sync(FULL, P.w, L1);
            float vx2 = __shfl_sync(FULL, P.x, L2);
            float vy2 = __shfl_sync(FULL, P.y, L2);
            float vz2 = __shfl_sync(FULL, P.z, L2);
            float vw2 = __shfl_sync(FULL, P.w, L2);
            float p00 = par ? vy1 : vx1;   // P[row qr][key 8k8+qc]
            float p10 = par ? vw1 : vz1;   // P[row qr+8][key 8k8+qc]
            float p01 = par ? vy2 : vx2;   // key 8k8+qc+4
            float p11 = par ? vw2 : vz2;
            float h00 = tf32r(p00), h10 = tf32r(p10), h01 = tf32r(p01), h11 = tf32r(p11);
            uint4 Ph = make_uint4(__float_as_uint(h00), __float_as_uint(h10),
                                  __float_as_uint(h01), __float_as_uint(h11));
            uint4 Pl = make_uint4(__float_as_uint(tf32r(p00 - h00)), __float_as_uint(tf32r(p10 - h10)),
                                  __float_as_uint(tf32r(p01 - h01)), __float_as_uint(tf32r(p11 - h11)));
#pragma unroll
            for (int nt = 0; nt < 8; nt++) {
                int vb = VH_ + (8 * nt + qr) * 68 + 8 * k8 + qc;
                uint32_t bh0 = __float_as_uint(sf[vb]);
                uint32_t bh1 = __float_as_uint(sf[vb + 4]);
                int vl = vb + (VL_ - VH_);
                uint32_t bl0 = __float_as_uint(sf[vl]);
                uint32_t bl1 = __float_as_uint(sf[vl + 4]);
                mma8(O[nt], Ph, bh0, bh1);
                mma8(O[nt], Ph, bl0, bl1);
                mma8(O[nt], Pl, bh0, bh1);
            }
        }

        __syncthreads();   // all warps done reading K/V(kt)
        if (kt + 1 < 16) {
            ldtile512(sb + KH_ * 4, Khg + (kt + 1) * 4096, 64, tid);
            ldtile512(sb + KL_ * 4, Klg + (kt + 1) * 4096, 64, tid);
            ldtile512(sb + VH_ * 4, Vhg + (kt + 1) * 64, NN, tid);
            ldtile512(sb + VL_ * 4, Vlg + (kt + 1) * 64, NN, tid);
        }
        cp_commit();
    }

    // final l reduce + epilogue
    l0 += __shfl_xor_sync(FULL, l0, 1);
    l0 += __shfl_xor_sync(FULL, l0, 2);
    l1 += __shfl_xor_sync(FULL, l1, 1);
    l1 += __shfl_xor_sync(FULL, l1, 2);
    float i0 = 1.0f / l0, i1 = 1.0f / l1;

    const float* Xi0 = g_X[pp] + ((size_t)(b * NN + n0) + wrow + qr) * CC;
    const float* Xi8 = Xi0 + 8 * CC;
    float* Xo0 = g_X[pp ^ 1] + ((size_t)(b * NN + n0) + wrow + qr) * CC;
    float* Xo8 = Xo0 + 8 * CC;
#pragma unroll
    for (int nt = 0; nt < 8; nt++) {
        int c = 8 * nt + 2 * qc;
        float2 a = *(const float2*)&Xi0[c];
        float2 bb = *(const float2*)&Xi8[c];
        *(float2*)&Xo0[c] = make_float2(O[nt].x * i0 + a.x, O[nt].y * i0 + a.y);
        *(float2*)&Xo8[c] = make_float2(O[nt].z * i1 + bb.x, O[nt].w * i1 + bb.y);
    }
}
// ---------------------------------------------------------------------------
__global__ void k_head(const float* __restrict__ lw, const float* __restrict__ lb,
                       float* __restrict__ out) {
    __shared__ float meanv[NN];
    __shared__ float red[8];
    int b = blockIdx.x;
    const float* Xb = g_X[0] + (size_t)b * NN * CC;
    for (int n = threadIdx.x; n < NN; n += 256) {
        const float4* p = (const float4*)(Xb + (size_t)n * CC);
        float s = 0.0f;
#pragma unroll
        for (int q = 0; q < 16; q++) { float4 v = p[q]; s += v.x + v.y + v.z + v.w; }
        meanv[n] = s * (1.0f / 64.0f);
    }
    __syncthreads();
    for (int cls = 0; cls < NCLS; cls++) {
        float s = 0.0f;
        for (int n = threadIdx.x; n < NN; n += 256) s += meanv[n] * lw[cls * NN + n];
#pragma unroll
        for (int d = 16; d; d >>= 1) s += __shfl_xor_sync(0xffffffffu, s, d);
        if ((threadIdx.x & 31) == 0) red[threadIdx.x >> 5] = s;
        __syncthreads();
        if (threadIdx.x == 0) {
            float t = 0.0f;
#pragma unroll
            for (int w = 0; w < 8; w++) t += red[w];
            out[b * NCLS + cls] = t + lb[cls];
        }
        __syncthreads();
    }
}
// ---------------------------------------------------------------------------
extern "C" void kernel_launch(void* const* d_in, const int* in_sizes, int n_in,
                              void* d_out, int out_size) {
    (void)in_sizes; (void)n_in; (void)out_size;
    const float* img = (const float*)d_in[0];
    const float* WV  = (const float*)d_in[1];
    const float* WK  = (const float*)d_in[2];
    const float* WQ  = (const float*)d_in[3];
    const float* lw  = (const float*)d_in[4];
    const float* lb  = (const float*)d_in[5];
    float* out = (float*)d_out;

    const int QKV_SMEM  = (64 * XSTRIDE + 64 * 192) * 4;
    const int ATTN_SMEM = ATTN_SMEMF * 4;    // 208896 B
    cudaFuncSetAttribute(k_qkv,  cudaFuncAttributeMaxDynamicSharedMemorySize, QKV_SMEM);
    cudaFuncSetAttribute(k_attn, cudaFuncAttributeMaxDynamicSharedMemorySize, ATTN_SMEM);

    dim3 gq(16, 32), ga(4, 32);
    k_transpose<<<gq, 256>>>(img);
    for (int l = 0; l < DEPTH; l++) {
        k_qkv<<<gq, 256, QKV_SMEM>>>(WQ, WK, WV, l & 1);
        k_attn<<<ga, 512, ATTN_SMEM>>>(l & 1);
    }
    k_head<<<32, 256>>>(lw, lb, out);
}

// round 11
// speedup vs baseline: 1.4822x; 1.0334x over previous
#include <cuda_runtime.h>
#include <cuda_bf16.h>
#include <cstdint>

#define BB 32
#define CC 64
#define NN 1024
#define DEPTH 8
#define NCLS 10

using u64 = unsigned long long;

static __device__ float g_X[2][BB * NN * CC];
static __device__ float g_Qh[BB * NN * CC];
static __device__ float g_Ql[BB * NN * CC];
static __device__ float g_Kh[BB * NN * CC];
static __device__ float g_Kl[BB * NN * CC];
static __device__ float g_Vth[BB * CC * NN];   // V^T hi: [b][c][n]
static __device__ float g_Vtl[BB * CC * NN];   // V^T lo

// ---------------- packed fp32 helpers ----------------
__device__ __forceinline__ u64 ffma2(u64 a, u64 b, u64 c) {
    u64 d; asm("fma.rn.f32x2 %0, %1, %2, %3;" : "=l"(d) : "l"(a), "l"(b), "l"(c)); return d;
}
__device__ __forceinline__ u64 fmul2(u64 a, u64 b) {
    u64 d; asm("mul.rn.f32x2 %0, %1, %2;" : "=l"(d) : "l"(a), "l"(b)); return d;
}
__device__ __forceinline__ u64 dup2(float x) {
    u64 r; asm("mov.b64 %0, {%1, %1};" : "=l"(r) : "f"(x)); return r;
}
__device__ __forceinline__ float2 u2f2(u64 v) {
    float2 r; asm("mov.b64 {%0, %1}, %2;" : "=f"(r.x), "=f"(r.y) : "l"(v)); return r;
}
__device__ __forceinline__ float tf32r(float x) {
    uint32_t u; asm("cvt.rna.tf32.f32 %0, %1;" : "=r"(u) : "f"(x)); return __uint_as_float(u);
}
// ---------------- cp.async ----------------
__device__ __forceinline__ void cp16(uint32_t dst, const float* src) {
    asm volatile("cp.async.cg.shared.global [%0], [%1], 16;" :: "r"(dst), "l"(src));
}
__device__ __forceinline__ void cp_commit() { asm volatile("cp.async.commit_group;" ::: "memory"); }
__device__ __forceinline__ void cp_wait0()  { asm volatile("cp.async.wait_group 0;" ::: "memory"); }

// ---------------- warp mma.sync tf32 m16n8k8 ----------------
__device__ __forceinline__ void mma8(float4& d, const uint4& a, uint32_t b0, uint32_t b1) {
    asm volatile(
        "mma.sync.aligned.m16n8k8.row.col.f32.tf32.tf32.f32 "
        "{%0,%1,%2,%3}, {%4,%5,%6,%7}, {%8,%9}, {%0,%1,%2,%3};"
        : "+f"(d.x), "+f"(d.y), "+f"(d.z), "+f"(d.w)
        : "r"(a.x), "r"(a.y), "r"(a.z), "r"(a.w), "r"(b0), "r"(b1));
}

// ---------------------------------------------------------------------------
__global__ void k_transpose(const float* __restrict__ img) {
    __shared__ float t[64][65];
    int b = blockIdx.y, n0 = blockIdx.x * 64;
    const float* src = img + (size_t)b * CC * NN;
    for (int i = threadIdx.x; i < 4096; i += 256) t[i >> 6][i & 63] = src[(i >> 6) * NN + n0 + (i & 63)];
    __syncthreads();
    float* dst = g_X[0] + ((size_t)b * NN + n0) * CC;
    for (int i = threadIdx.x; i < 4096; i += 256) dst[(i >> 6) * CC + (i & 63)] = t[i & 63][i >> 6];
}
// ---------------------------------------------------------------------------
// QKV (f32x2) -> split tf32 hi/lo; V transposed via smem staging (coalesced).
#define XSTRIDE 68
__global__ void __launch_bounds__(256) k_qkv(const float* __restrict__ WQ,
                                             const float* __restrict__ WK,
                                             const float* __restrict__ WV, int pp) {
    extern __shared__ float sm[];
    float* Xs = sm;                       // 64 x 68
    float* Ws = sm + 64 * XSTRIDE;        // 64 x 192; later reused as V staging
    uint32_t sXs = (uint32_t)__cvta_generic_to_shared(Xs);
    int b = blockIdx.y, n0 = blockIdx.x * 64, tid = threadIdx.x;
    const float* Xin = g_X[pp] + ((size_t)b * NN + n0) * CC;
#pragma unroll
    for (int t = 0; t < 4; t++) {
        int i = tid + t * 256, r = i >> 4, c = (i & 15) << 2;
        cp16(sXs + (r * XSTRIDE + c) * 4, Xin + r * 64 + c);
    }
    cp_commit();
    for (int i = tid; i < 64 * 192; i += 256) {
        int k = i / 192, c = i - k * 192;
        Ws[i] = c < 64 ? WQ[k * 64 + c] : (c < 128 ? WK[k * 64 + c - 64] : WV[k * 64 + c - 128]);
    }
    int tx = tid & 15, ty = tid >> 4;
    u64 acc[4][6];
#pragma unroll
    for (int i = 0; i < 4; i++)
#pragma unroll
        for (int j = 0; j < 6; j++) acc[i][j] = 0ULL;
    cp_wait0();
    __syncthreads();
#pragma unroll 2
    for (int k0 = 0; k0 < 64; k0 += 4) {
        float4 xv[4];
#pragma unroll
        for (int i = 0; i < 4; i++) xv[i] = *(const float4*)&Xs[(ty * 4 + i) * XSTRIDE + k0];
#pragma unroll
        for (int kk = 0; kk < 4; kk++) {
            u64 wv[6];
#pragma unroll
            for (int j = 0; j < 6; j++) wv[j] = *(const u64*)&Ws[(k0 + kk) * 192 + tx * 2 + 32 * j];
            u64 xd[4];
#pragma unroll
            for (int i = 0; i < 4; i++)
                xd[i] = dup2(kk == 0 ? xv[i].x : kk == 1 ? xv[i].y : kk == 2 ? xv[i].z : xv[i].w);
#pragma unroll
            for (int i = 0; i < 4; i++)
#pragma unroll
                for (int j = 0; j < 6; j++) acc[i][j] = ffma2(xd[i], wv[j], acc[i][j]);
        }
    }
    const u64 scale2 = dup2(0.03125f);
    size_t base = ((size_t)b * NN + n0) * CC;
#pragma unroll
    for (int i = 0; i < 4; i++) {
        int r = ty * 4 + i, co = tx * 2;
#pragma unroll
        for (int j = 0; j < 2; j++) {
            int c = co + 32 * j;
            float2 q = u2f2(fmul2(acc[i][j], scale2));
            float qhx = tf32r(q.x), qhy = tf32r(q.y);
            *(float2*)&g_Qh[base + r * 64 + c] = make_float2(qhx, qhy);
            *(float2*)&g_Ql[base + r * 64 + c] = make_float2(tf32r(q.x - qhx), tf32r(q.y - qhy));
            float2 kv = u2f2(acc[i][2 + j]);
            float khx = tf32r(kv.x), khy = tf32r(kv.y);
            *(float2*)&g_Kh[base + r * 64 + c] = make_float2(khx, khy);
            *(float2*)&g_Kl[base + r * 64 + c] = make_float2(tf32r(kv.x - khx), tf32r(kv.y - khy));
        }
    }
    // V: stage split hi/lo into smem (reuse Ws), then coalesced V^T stores.
    __syncthreads();
    float* Vsth = Ws;                    // 64 x 65
    float* Vstl = Ws + 4160;             // 64 x 65
#pragma unroll
    for (int i = 0; i < 4; i++) {
        int r = ty * 4 + i, co = tx * 2;
#pragma unroll
        for (int j = 0; j < 2; j++) {
            int c = co + 32 * j;
            float2 vv = u2f2(acc[i][4 + j]);
            float vhx = tf32r(vv.x), vhy = tf32r(vv.y);
            Vsth[r * 65 + c]     = vhx;
            Vsth[r * 65 + c + 1] = vhy;
            Vstl[r * 65 + c]     = tf32r(vv.x - vhx);
            Vstl[r * 65 + c + 1] = tf32r(vv.y - vhy);
        }
    }
    __syncthreads();
    size_t vb0 = (size_t)b * CC * NN + n0;
    for (int q = tid; q < 4096; q += 256) {
        int c = q >> 6, n = q & 63;
        g_Vth[vb0 + (size_t)c * NN + n] = Vsth[n * 65 + c];
        g_Vtl[vb0 + (size_t)c * NN + n] = Vstl[n * 65 + c];
    }
}
// ---------------------------------------------------------------------------
// mma.sync flash attention. CTA = 256 q-rows, 256 threads, 8 warps x 32 rows
// (two 16-row groups per warp share every K/V B-fragment -> half the LDS).
// smem float offsets:
#define QH_ 0
#define QL_ 17408
#define KH_ 34816
#define KL_ 39168
#define VH_ 43520
#define VL_ 47872
#define ATTN_SMEMF 52224      // 208896 bytes

__device__ __forceinline__ void ldtile256(uint32_t dst, const float* src, int stride, int tid) {
#pragma unroll
    for (int t = 0; t < 4; t++) {
        int q = tid + t * 256;
        int r = q >> 4, c = (q & 15) << 2;
        cp16(dst + (r * 68 + c) * 4, src + (size_t)r * stride + c);
    }
}

__global__ void __launch_bounds__(256, 1) k_attn(int pp) {
    extern __shared__ float sf[];
    uint32_t sb = (uint32_t)__cvta_generic_to_shared(sf);
    int b = blockIdx.y, n0 = blockIdx.x * 256, tid = threadIdx.x;
    int wid = tid >> 5, lane = tid & 31;
    int qr = lane >> 2, qc = lane & 3;
    int wrow = wid * 32;
    int L1 = (lane & 0x1C) | ((lane & 3) >> 1);
    int L2 = L1 + 2;
    bool par = (lane & 1) != 0;
    const uint32_t FULL = 0xffffffffu;

    const float* Qhg = g_Qh + ((size_t)b * NN + n0) * CC;
    const float* Qlg = g_Ql + ((size_t)b * NN + n0) * CC;
    const float* Khg = g_Kh + (size_t)b * NN * CC;
    const float* Klg = g_Kl + (size_t)b * NN * CC;
    const float* Vhg = g_Vth + (size_t)b * CC * NN;
    const float* Vlg = g_Vtl + (size_t)b * CC * NN;

    // prologue: Q hi/lo (256x64) + K0/V0
#pragma unroll
    for (int t = 0; t < 16; t++) {
        int q = tid + t * 256;
        int r = q >> 4, c = (q & 15) << 2;
        cp16(sb + (QH_ + r * 68 + c) * 4, Qhg + r * 64 + c);
        cp16(sb + (QL_ + r * 68 + c) * 4, Qlg + r * 64 + c);
    }
    ldtile256(sb + KH_ * 4, Khg, 64, tid);
    ldtile256(sb + KL_ * 4, Klg, 64, tid);
    ldtile256(sb + VH_ * 4, Vhg, NN, tid);
    ldtile256(sb + VL_ * 4, Vlg, NN, tid);
    cp_commit();

    float4 O[2][8];
#pragma unroll
    for (int g = 0; g < 2; g++)
#pragma unroll
        for (int nt = 0; nt < 8; nt++) O[g][nt] = make_float4(0.f, 0.f, 0.f, 0.f);
    float m[2][2], l[2][2];
#pragma unroll
    for (int g = 0; g < 2; g++) { m[g][0] = m[g][1] = -1e30f; l[g][0] = l[g][1] = 0.f; }

#pragma unroll 1
    for (int kt = 0; kt < 16; ++kt) {
        cp_wait0();
        __syncthreads();   // K/V(kt) (and Q on kt=0) resident & visible

        // ---- S = Qh*Kh + Qh*Kl + Ql*Kh, both 16-row groups share B ----
        float4 S[2][8];
#pragma unroll
        for (int g = 0; g < 2; g++)
#pragma unroll
            for (int nt = 0; nt < 8; nt++) S[g][nt] = make_float4(0.f, 0.f, 0.f, 0.f);
#pragma unroll
        for (int k8 = 0; k8 < 8; k8++) {
            int qa0 = QH_ + (wrow + qr) * 68 + 8 * k8 + qc;
            uint4 Ah0 = make_uint4(__float_as_uint(sf[qa0]),
                                   __float_as_uint(sf[qa0 + 8 * 68]),
                                   __float_as_uint(sf[qa0 + 4]),
                                   __float_as_uint(sf[qa0 + 4 + 8 * 68]));
            int ql0 = qa0 + (QL_ - QH_);
            uint4 Al0 = make_uint4(__float_as_uint(sf[ql0]),
                                   __float_as_uint(sf[ql0 + 8 * 68]),
                                   __float_as_uint(sf[ql0 + 4]),
                                   __float_as_uint(sf[ql0 + 4 + 8 * 68]));
            int qa1 = qa0 + 16 * 68;
            uint4 Ah1 = make_uint4(__float_as_uint(sf[qa1]),
                                   __float_as_uint(sf[qa1 + 8 * 68]),
                                   __float_as_uint(sf[qa1 + 4]),
                                   __float_as_uint(sf[qa1 + 4 + 8 * 68]));
            int ql1 = qa1 + (QL_ - QH_);
            uint4 Al1 = make_uint4(__float_as_uint(sf[ql1]),
                                   __float_as_uint(sf[ql1 + 8 * 68]),
                                   __float_as_uint(sf[ql1 + 4]),
                                   __float_as_uint(sf[ql1 + 4 + 8 * 68]));
#pragma unroll
            for (int nt = 0; nt < 8; nt++) {
                int ab = KH_ + (8 * nt + qr) * 68 + 8 * k8 + qc;
                uint32_t bh0 = __float_as_uint(sf[ab]);
                uint32_t bh1 = __float_as_uint(sf[ab + 4]);
                int al2 = ab + (KL_ - KH_);
                uint32_t bl0 = __float_as_uint(sf[al2]);
                uint32_t bl1 = __float_as_uint(sf[al2 + 4]);
                mma8(S[0][nt], Ah0, bh0, bh1);
                mma8(S[0][nt], Ah0, bl0, bl1);
                mma8(S[0][nt], Al0, bh0, bh1);
                mma8(S[1][nt], Ah1, bh0, bh1);
                mma8(S[1][nt], Ah1, bl0, bl1);
                mma8(S[1][nt], Al1, bh0, bh1);
            }
        }

        // ---- online softmax per group ----
#pragma unroll
        for (int g = 0; g < 2; g++) {
            float mx0 = -1e30f, mx1 = -1e30f;
#pragma unroll
            for (int nt = 0; nt < 8; nt++) {
                mx0 = fmaxf(mx0, fmaxf(S[g][nt].x, S[g][nt].y));
                mx1 = fmaxf(mx1, fmaxf(S[g][nt].z, S[g][nt].w));
            }
            mx0 = fmaxf(mx0, __shfl_xor_sync(FULL, mx0, 1));
            mx0 = fmaxf(mx0, __shfl_xor_sync(FULL, mx0, 2));
            mx1 = fmaxf(mx1, __shfl_xor_sync(FULL, mx1, 1));
            mx1 = fmaxf(mx1, __shfl_xor_sync(FULL, mx1, 2));
            float mn0 = fmaxf(m[g][0], mx0), mn1 = fmaxf(m[g][1], mx1);
            float c0 = __expf(m[g][0] - mn0), c1 = __expf(m[g][1] - mn1);
            m[g][0] = mn0; m[g][1] = mn1;
            float ps0 = 0.f, ps1 = 0.f;
#pragma unroll
            for (int nt = 0; nt < 8; nt++) {
                S[g][nt].x = __expf(S[g][nt].x - mn0);
                S[g][nt].y = __expf(S[g][nt].y - mn0);
                S[g][nt].z = __expf(S[g][nt].z - mn1);
                S[g][nt].w = __expf(S[g][nt].w - mn1);
                ps0 += S[g][nt].x + S[g][nt].y;
                ps1 += S[g][nt].z + S[g][nt].w;
            }
            l[g][0] = l[g][0] * c0 + ps0;
            l[g][1] = l[g][1] * c1 + ps1;
#pragma unroll
            for (int nt = 0; nt < 8; nt++) {
                O[g][nt].x *= c0; O[g][nt].y *= c0; O[g][nt].z *= c1; O[g][nt].w *= c1;
            }
        }

        // ---- PV: shuffle P fragments per group, V B-frags shared ----
#pragma unroll
        for (int k8 = 0; k8 < 8; k8++) {
            uint4 Ph[2], Pl[2];
#pragma unroll
            for (int g = 0; g < 2; g++) {
                float4 P = S[g][k8];
                float vx1 = __shfl_sync(FULL, P.x, L1);
                float vy1 = __shfl_sync(FULL, P.y, L1);
                float vz1 = __shfl_sync(FULL, P.z, L1);
                float vw1 = __shfl_sync(FULL, P.w, L1);
                float vx2 = __shfl_sync(FULL, P.x, L2);
                float vy2 = __shfl_sync(FULL, P.y, L2);
                float vz2 = __shfl_sync(FULL, P.z, L2);
                float vw2 = __shfl_sync(FULL, P.w, L2);
                float p00 = par ? vy1 : vx1;
                float p10 = par ? vw1 : vz1;
                float p01 = par ? vy2 : vx2;
                float p11 = par ? vw2 : vz2;
                float h00 = tf32r(p00), h10 = tf32r(p10), h01 = tf32r(p01), h11 = tf32r(p11);
                Ph[g] = make_uint4(__float_as_uint(h00), __float_as_uint(h10),
                                   __float_as_uint(h01), __float_as_uint(h11));
                Pl[g] = make_uint4(__float_as_uint(tf32r(p00 - h00)), __float_as_uint(tf32r(p10 - h10)),
                                   __float_as_uint(tf32r(p01 - h01)), __float_as_uint(tf32r(p11 - h11)));
            }
#pragma unroll
            for (int nt = 0; nt < 8; nt++) {
                int vb = VH_ + (8 * nt + qr) * 68 + 8 * k8 + qc;
                uint32_t bh0 = __float_as_uint(sf[vb]);
                uint32_t bh1 = __float_as_uint(sf[vb + 4]);
                int vl = vb + (VL_ - VH_);
                uint32_t bl0 = __float_as_uint(sf[vl]);
                uint32_t bl1 = __float_as_uint(sf[vl + 4]);
                mma8(O[0][nt], Ph[0], bh0, bh1);
                mma8(O[0][nt], Ph[0], bl0, bl1);
                mma8(O[0][nt], Pl[0], bh0, bh1);
                mma8(O[1][nt], Ph[1], bh0, bh1);
                mma8(O[1][nt], Ph[1], bl0, bl1);
                mma8(O[1][nt], Pl[1], bh0, bh1);
            }
        }

        __syncthreads();   // all warps done reading K/V(kt)
        if (kt + 1 < 16) {
            ldtile256(sb + KH_ * 4, Khg + (kt + 1) * 4096, 64, tid);
            ldtile256(sb + KL_ * 4, Klg + (kt + 1) * 4096, 64, tid);
            ldtile256(sb + VH_ * 4, Vhg + (kt + 1) * 64, NN, tid);
            ldtile256(sb + VL_ * 4, Vlg + (kt + 1) * 64, NN, tid);
        }
        cp_commit();
    }

    // epilogue per group
#pragma unroll
    for (int g = 0; g < 2; g++) {
        float l0 = l[g][0], l1 = l[g][1];
        l0 += __shfl_xor_sync(FULL, l0, 1);
        l0 += __shfl_xor_sync(FULL, l0, 2);
        l1 += __shfl_xor_sync(FULL, l1, 1);
        l1 += __shfl_xor_sync(FULL, l1, 2);
        float i0 = 1.0f / l0, i1 = 1.0f / l1;
        const float* Xi0 = g_X[pp] + ((size_t)(b * NN + n0) + wrow + g * 16 + qr) * CC;
        const float* Xi8 = Xi0 + 8 * CC;
        float* Xo0 = g_X[pp ^ 1] + ((size_t)(b * NN + n0) + wrow + g * 16 + qr) * CC;
        float* Xo8 = Xo0 + 8 * CC;
#pragma unroll
        for (int nt = 0; nt < 8; nt++) {
            int c = 8 * nt + 2 * qc;
            float2 a = *(const float2*)&Xi0[c];
            float2 bb = *(const float2*)&Xi8[c];
            *(float2*)&Xo0[c] = make_float2(O[g][nt].x * i0 + a.x, O[g][nt].y * i0 + a.y);
            *(float2*)&Xo8[c] = make_float2(O[g][nt].z * i1 + bb.x, O[g][nt].w * i1 + bb.y);
        }
    }
}
// ---------------------------------------------------------------------------
__global__ void k_head(const float* __restrict__ lw, const float* __restrict__ lb,
                       float* __restrict__ out) {
    __shared__ float meanv[NN];
    __shared__ float red[8];
    int b = blockIdx.x;
    const float* Xb = g_X[0] + (size_t)b * NN * CC;
    for (int n = threadIdx.x; n < NN; n += 256) {
        const float4* p = (const float4*)(Xb + (size_t)n * CC);
        float s = 0.0f;
#pragma unroll
        for (int q = 0; q < 16; q++) { float4 v = p[q]; s += v.x + v.y + v.z + v.w; }
        meanv[n] = s * (1.0f / 64.0f);
    }
    __syncthreads();
    for (int cls = 0; cls < NCLS; cls++) {
        float s = 0.0f;
        for (int n = threadIdx.x; n < NN; n += 256) s += meanv[n] * lw[cls * NN + n];
#pragma unroll
        for (int d = 16; d; d >>= 1) s += __shfl_xor_sync(0xffffffffu, s, d);
        if ((threadIdx.x & 31) == 0) red[threadIdx.x >> 5] = s;
        __syncthreads();
        if (threadIdx.x == 0) {
            float t = 0.0f;
#pragma unroll
            for (int w = 0; w < 8; w++) t += red[w];
            out[b * NCLS + cls] = t + lb[cls];
        }
        __syncthreads();
    }
}
// ---------------------------------------------------------------------------
extern "C" void kernel_launch(void* const* d_in, const int* in_sizes, int n_in,
                              void* d_out, int out_size) {
    (void)in_sizes; (void)n_in; (void)out_size;
    const float* img = (const float*)d_in[0];
    const float* WV  = (const float*)d_in[1];
    const float* WK  = (const float*)d_in[2];
    const float* WQ  = (const float*)d_in[3];
    const float* lw  = (const float*)d_in[4];
    const float* lb  = (const float*)d_in[5];
    float* out = (float*)d_out;

    const int QKV_SMEM  = (64 * XSTRIDE + 64 * 192) * 4;
    const int ATTN_SMEM = ATTN_SMEMF * 4;    // 208896 B
    cudaFuncSetAttribute(k_qkv,  cudaFuncAttributeMaxDynamicSharedMemorySize, QKV_SMEM);
    cudaFuncSetAttribute(k_attn, cudaFuncAttributeMaxDynamicSharedMemorySize, ATTN_SMEM);

    dim3 gq(16, 32), ga(4, 32);
    k_transpose<<<gq, 256>>>(img);
    for (int l = 0; l < DEPTH; l++) {
        k_qkv<<<gq, 256, QKV_SMEM>>>(WQ, WK, WV, l & 1);
        k_attn<<<ga, 256, ATTN_SMEM>>>(l & 1);
    }
    k_head<<<32, 256>>>(lw, lb, out);
}

// round 12
// speedup vs baseline: 1.5727x; 1.0611x over previous
#include <cuda_runtime.h>
#include <cuda_bf16.h>
#include <cstdint>

#define BB 32
#define CC 64
#define NN 1024
#define DEPTH 8
#define NCLS 10

using u64 = unsigned long long;

static __device__ float g_X[2][BB * NN * CC];
static __device__ float g_Qh[BB * NN * CC];
static __device__ float g_Ql[BB * NN * CC];
static __device__ float g_Kh[BB * NN * CC];
static __device__ float g_Kl[BB * NN * CC];
static __device__ float g_Vth[BB * CC * NN];   // V^T hi: [b][c][n]
static __device__ float g_Vtl[BB * CC * NN];   // V^T lo

// ---------------- packed fp32 helpers ----------------
__device__ __forceinline__ u64 ffma2(u64 a, u64 b, u64 c) {
    u64 d; asm("fma.rn.f32x2 %0, %1, %2, %3;" : "=l"(d) : "l"(a), "l"(b), "l"(c)); return d;
}
__device__ __forceinline__ u64 fmul2(u64 a, u64 b) {
    u64 d; asm("mul.rn.f32x2 %0, %1, %2;" : "=l"(d) : "l"(a), "l"(b)); return d;
}
__device__ __forceinline__ u64 dup2(float x) {
    u64 r; asm("mov.b64 %0, {%1, %1};" : "=l"(r) : "f"(x)); return r;
}
__device__ __forceinline__ float2 u2f2(u64 v) {
    float2 r; asm("mov.b64 {%0, %1}, %2;" : "=f"(r.x), "=f"(r.y) : "l"(v)); return r;
}
__device__ __forceinline__ float tf32r(float x) {
    uint32_t u; asm("cvt.rna.tf32.f32 %0, %1;" : "=r"(u) : "f"(x)); return __uint_as_float(u);
}
// ---------------- cp.async ----------------
__device__ __forceinline__ void cp16(uint32_t dst, const float* src) {
    asm volatile("cp.async.cg.shared.global [%0], [%1], 16;" :: "r"(dst), "l"(src));
}
__device__ __forceinline__ void cp_commit() { asm volatile("cp.async.commit_group;" ::: "memory"); }
__device__ __forceinline__ void cp_wait0()  { asm volatile("cp.async.wait_group 0;" ::: "memory"); }

// ---------------- warp mma.sync tf32 m16n8k8 ----------------
__device__ __forceinline__ void mma8(float4& d, const uint4& a, uint32_t b0, uint32_t b1) {
    asm volatile(
        "mma.sync.aligned.m16n8k8.row.col.f32.tf32.tf32.f32 "
        "{%0,%1,%2,%3}, {%4,%5,%6,%7}, {%8,%9}, {%0,%1,%2,%3};"
        : "+f"(d.x), "+f"(d.y), "+f"(d.z), "+f"(d.w)
        : "r"(a.x), "r"(a.y), "r"(a.z), "r"(a.w), "r"(b0), "r"(b1));
}

// ---------------------------------------------------------------------------
__global__ void k_transpose(const float* __restrict__ img) {
    __shared__ float t[64][65];
    int b = blockIdx.y, n0 = blockIdx.x * 64;
    const float* src = img + (size_t)b * CC * NN;
    for (int i = threadIdx.x; i < 4096; i += 256) t[i >> 6][i & 63] = src[(i >> 6) * NN + n0 + (i & 63)];
    __syncthreads();
    float* dst = g_X[0] + ((size_t)b * NN + n0) * CC;
    for (int i = threadIdx.x; i < 4096; i += 256) dst[(i >> 6) * CC + (i & 63)] = t[i & 63][i >> 6];
}
// ---------------------------------------------------------------------------
// QKV: 2 row-tiles per CTA (single wave: 256 CTAs @ 2/SM), X double-buffered
// via cp.async, W loaded once. V staged raw in the dead X buffer; split on
// coalesced read side.
__global__ void __launch_bounds__(256) k_qkv(const float* __restrict__ WQ,
                                             const float* __restrict__ WK,
                                             const float* __restrict__ WV, int pp) {
    extern __shared__ float sm[];
    float* Xb[2] = { sm, sm + 4352 };     // 2 x (64 x 68)
    float* Ws = sm + 8704;                // 64 x 192
    uint32_t sX0 = (uint32_t)__cvta_generic_to_shared(Xb[0]);
    uint32_t sX1 = (uint32_t)__cvta_generic_to_shared(Xb[1]);
    uint32_t sWs = (uint32_t)__cvta_generic_to_shared(Ws);
    int b = blockIdx.y, tid = threadIdx.x;
    int r0 = blockIdx.x * 128;            // this CTA's 128-row span

    const float* Xin = g_X[pp] + ((size_t)b * NN + r0) * CC;
    // prologue: X tile0 + all of W
#pragma unroll
    for (int t = 0; t < 4; t++) {
        int i = tid + t * 256, r = i >> 4, c = (i & 15) << 2;
        cp16(sX0 + (r * 68 + c) * 4, Xin + r * 64 + c);
    }
#pragma unroll
    for (int t = 0; t < 12; t++) {
        int fo = (tid + t * 256) * 4;     // 0..12284, 4-aligned
        int k = fo / 192, c = fo - k * 192;
        const float* src = (c < 64) ? (WQ + k * 64 + c)
                         : (c < 128) ? (WK + k * 64 + c - 64)
                                     : (WV + k * 64 + c - 128);
        cp16(sWs + fo * 4, src);
    }
    cp_commit();

    int tx = tid & 15, ty = tid >> 4;
    const u64 scale2 = dup2(0.03125f);

#pragma unroll 1
    for (int tile = 0; tile < 2; tile++) {
        cp_wait0();
        __syncthreads();
        if (tile == 0) {   // prefetch X tile1 while computing tile0
#pragma unroll
            for (int t = 0; t < 4; t++) {
                int i = tid + t * 256, r = i >> 4, c = (i & 15) << 2;
                cp16(sX1 + (r * 68 + c) * 4, Xin + (64 + r) * 64 + c);
            }
            cp_commit();
        }
        float* Xs = Xb[tile];

        u64 acc[4][6];
#pragma unroll
        for (int i = 0; i < 4; i++)
#pragma unroll
            for (int j = 0; j < 6; j++) acc[i][j] = 0ULL;

#pragma unroll 2
        for (int k0 = 0; k0 < 64; k0 += 4) {
            float4 xv[4];
#pragma unroll
            for (int i = 0; i < 4; i++) xv[i] = *(const float4*)&Xs[(ty * 4 + i) * 68 + k0];
#pragma unroll
            for (int kk = 0; kk < 4; kk++) {
                u64 wv[6];
#pragma unroll
                for (int j = 0; j < 6; j++) wv[j] = *(const u64*)&Ws[(k0 + kk) * 192 + tx * 2 + 32 * j];
                u64 xd[4];
#pragma unroll
                for (int i = 0; i < 4; i++)
                    xd[i] = dup2(kk == 0 ? xv[i].x : kk == 1 ? xv[i].y : kk == 2 ? xv[i].z : xv[i].w);
#pragma unroll
                for (int i = 0; i < 4; i++)
#pragma unroll
                    for (int j = 0; j < 6; j++) acc[i][j] = ffma2(xd[i], wv[j], acc[i][j]);
            }
        }

        size_t base = ((size_t)b * NN + r0 + tile * 64) * CC;
#pragma unroll
        for (int i = 0; i < 4; i++) {
            int r = ty * 4 + i, co = tx * 2;
#pragma unroll
            for (int j = 0; j < 2; j++) {
                int c = co + 32 * j;
                float2 q = u2f2(fmul2(acc[i][j], scale2));
                float qhx = tf32r(q.x), qhy = tf32r(q.y);
                *(float2*)&g_Qh[base + r * 64 + c] = make_float2(qhx, qhy);
                *(float2*)&g_Ql[base + r * 64 + c] = make_float2(tf32r(q.x - qhx), tf32r(q.y - qhy));
                float2 kv = u2f2(acc[i][2 + j]);
                float khx = tf32r(kv.x), khy = tf32r(kv.y);
                *(float2*)&g_Kh[base + r * 64 + c] = make_float2(khx, khy);
                *(float2*)&g_Kl[base + r * 64 + c] = make_float2(tf32r(kv.x - khx), tf32r(kv.y - khy));
            }
        }
        // V: stage raw into this tile's (now dead) X buffer, split on read.
        __syncthreads();   // all compute reads of Xs done
#pragma unroll
        for (int i = 0; i < 4; i++) {
            int r = ty * 4 + i, co = tx * 2;
#pragma unroll
            for (int j = 0; j < 2; j++) {
                int c = co + 32 * j;
                *(float2*)&Xs[r * 68 + c] = u2f2(acc[i][4 + j]);
            }
        }
        __syncthreads();
        size_t vb0 = (size_t)b * CC * NN + r0 + tile * 64;
        for (int q = tid; q < 4096; q += 256) {
            int c = q >> 6, n = q & 63;
            float v = Xs[n * 68 + c];
            float vh = tf32r(v);
            g_Vth[vb0 + (size_t)c * NN + n] = vh;
            g_Vtl[vb0 + (size_t)c * NN + n] = tf32r(v - vh);
        }
    }
}
// ---------------------------------------------------------------------------
// mma.sync flash attention. CTA = 256 q-rows, 256 threads, 8 warps x 32 rows.
// (unchanged from R10 best)
#define QH_ 0
#define QL_ 17408
#define KH_ 34816
#define KL_ 39168
#define VH_ 43520
#define VL_ 47872
#define ATTN_SMEMF 52224      // 208896 bytes

__device__ __forceinline__ void ldtile256(uint32_t dst, const float* src, int stride, int tid) {
#pragma unroll
    for (int t = 0; t < 4; t++) {
        int q = tid + t * 256;
        int r = q >> 4, c = (q & 15) << 2;
        cp16(dst + (r * 68 + c) * 4, src + (size_t)r * stride + c);
    }
}

__global__ void __launch_bounds__(256, 1) k_attn(int pp) {
    extern __shared__ float sf[];
    uint32_t sb = (uint32_t)__cvta_generic_to_shared(sf);
    int b = blockIdx.y, n0 = blockIdx.x * 256, tid = threadIdx.x;
    int wid = tid >> 5, lane = tid & 31;
    int qr = lane >> 2, qc = lane & 3;
    int wrow = wid * 32;
    int L1 = (lane & 0x1C) | ((lane & 3) >> 1);
    int L2 = L1 + 2;
    bool par = (lane & 1) != 0;
    const uint32_t FULL = 0xffffffffu;

    const float* Qhg = g_Qh + ((size_t)b * NN + n0) * CC;
    const float* Qlg = g_Ql + ((size_t)b * NN + n0) * CC;
    const float* Khg = g_Kh + (size_t)b * NN * CC;
    const float* Klg = g_Kl + (size_t)b * NN * CC;
    const float* Vhg = g_Vth + (size_t)b * CC * NN;
    const float* Vlg = g_Vtl + (size_t)b * CC * NN;

#pragma unroll
    for (int t = 0; t < 16; t++) {
        int q = tid + t * 256;
        int r = q >> 4, c = (q & 15) << 2;
        cp16(sb + (QH_ + r * 68 + c) * 4, Qhg + r * 64 + c);
        cp16(sb + (QL_ + r * 68 + c) * 4, Qlg + r * 64 + c);
    }
    ldtile256(sb + KH_ * 4, Khg, 64, tid);
    ldtile256(sb + KL_ * 4, Klg, 64, tid);
    ldtile256(sb + VH_ * 4, Vhg, NN, tid);
    ldtile256(sb + VL_ * 4, Vlg, NN, tid);
    cp_commit();

    float4 O[2][8];
#pragma unroll
    for (int g = 0; g < 2; g++)
#pragma unroll
        for (int nt = 0; nt < 8; nt++) O[g][nt] = make_float4(0.f, 0.f, 0.f, 0.f);
    float m[2][2], l[2][2];
#pragma unroll
    for (int g = 0; g < 2; g++) { m[g][0] = m[g][1] = -1e30f; l[g][0] = l[g][1] = 0.f; }

#pragma unroll 1
    for (int kt = 0; kt < 16; ++kt) {
        cp_wait0();
        __syncthreads();

        float4 S[2][8];
#pragma unroll
        for (int g = 0; g < 2; g++)
#pragma unroll
            for (int nt = 0; nt < 8; nt++) S[g][nt] = make_float4(0.f, 0.f, 0.f, 0.f);
#pragma unroll
        for (int k8 = 0; k8 < 8; k8++) {
            int qa0 = QH_ + (wrow + qr) * 68 + 8 * k8 + qc;
            uint4 Ah0 = make_uint4(__float_as_uint(sf[qa0]),
                                   __float_as_uint(sf[qa0 + 8 * 68]),
                                   __float_as_uint(sf[qa0 + 4]),
                                   __float_as_uint(sf[qa0 + 4 + 8 * 68]));
            int ql0 = qa0 + (QL_ - QH_);
            uint4 Al0 = make_uint4(__float_as_uint(sf[ql0]),
                                   __float_as_uint(sf[ql0 + 8 * 68]),
                                   __float_as_uint(sf[ql0 + 4]),
                                   __float_as_uint(sf[ql0 + 4 + 8 * 68]));
            int qa1 = qa0 + 16 * 68;
            uint4 Ah1 = make_uint4(__float_as_uint(sf[qa1]),
                                   __float_as_uint(sf[qa1 + 8 * 68]),
                                   __float_as_uint(sf[qa1 + 4]),
                                   __float_as_uint(sf[qa1 + 4 + 8 * 68]));
            int ql1 = qa1 + (QL_ - QH_);
            uint4 Al1 = make_uint4(__float_as_uint(sf[ql1]),
                                   __float_as_uint(sf[ql1 + 8 * 68]),
                                   __float_as_uint(sf[ql1 + 4]),
                                   __float_as_uint(sf[ql1 + 4 + 8 * 68]));
#pragma unroll
            for (int nt = 0; nt < 8; nt++) {
                int ab = KH_ + (8 * nt + qr) * 68 + 8 * k8 + qc;
                uint32_t bh0 = __float_as_uint(sf[ab]);
                uint32_t bh1 = __float_as_uint(sf[ab + 4]);
                int al2 = ab + (KL_ - KH_);
                uint32_t bl0 = __float_as_uint(sf[al2]);
                uint32_t bl1 = __float_as_uint(sf[al2 + 4]);
                mma8(S[0][nt], Ah0, bh0, bh1);
                mma8(S[0][nt], Ah0, bl0, bl1);
                mma8(S[0][nt], Al0, bh0, bh1);
                mma8(S[1][nt], Ah1, bh0, bh1);
                mma8(S[1][nt], Ah1, bl0, bl1);
                mma8(S[1][nt], Al1, bh0, bh1);
            }
        }

#pragma unroll
        for (int g = 0; g < 2; g++) {
            float mx0 = -1e30f, mx1 = -1e30f;
#pragma unroll
            for (int nt = 0; nt < 8; nt++) {
                mx0 = fmaxf(mx0, fmaxf(S[g][nt].x, S[g][nt].y));
                mx1 = fmaxf(mx1, fmaxf(S[g][nt].z, S[g][nt].w));
            }
            mx0 = fmaxf(mx0, __shfl_xor_sync(FULL, mx0, 1));
            mx0 = fmaxf(mx0, __shfl_xor_sync(FULL, mx0, 2));
            mx1 = fmaxf(mx1, __shfl_xor_sync(FULL, mx1, 1));
            mx1 = fmaxf(mx1, __shfl_xor_sync(FULL, mx1, 2));
            float mn0 = fmaxf(m[g][0], mx0), mn1 = fmaxf(m[g][1], mx1);
            float c0 = __expf(m[g][0] - mn0), c1 = __expf(m[g][1] - mn1);
            m[g][0] = mn0; m[g][1] = mn1;
            float ps0 = 0.f, ps1 = 0.f;
#pragma unroll
            for (int nt = 0; nt < 8; nt++) {
                S[g][nt].x = __expf(S[g][nt].x - mn0);
                S[g][nt].y = __expf(S[g][nt].y - mn0);
                S[g][nt].z = __expf(S[g][nt].z - mn1);
                S[g][nt].w = __expf(S[g][nt].w - mn1);
                ps0 += S[g][nt].x + S[g][nt].y;
                ps1 += S[g][nt].z + S[g][nt].w;
            }
            l[g][0] = l[g][0] * c0 + ps0;
            l[g][1] = l[g][1] * c1 + ps1;
#pragma unroll
            for (int nt = 0; nt < 8; nt++) {
                O[g][nt].x *= c0; O[g][nt].y *= c0; O[g][nt].z *= c1; O[g][nt].w *= c1;
            }
        }

#pragma unroll
        for (int k8 = 0; k8 < 8; k8++) {
            uint4 Ph[2], Pl[2];
#pragma unroll
            for (int g = 0; g < 2; g++) {
                float4 P = S[g][k8];
                float vx1 = __shfl_sync(FULL, P.x, L1);
                float vy1 = __shfl_sync(FULL, P.y, L1);
                float vz1 = __shfl_sync(FULL, P.z, L1);
                float vw1 = __shfl_sync(FULL, P.w, L1);
                float vx2 = __shfl_sync(FULL, P.x, L2);
                float vy2 = __shfl_sync(FULL, P.y, L2);
                float vz2 = __shfl_sync(FULL, P.z, L2);
                float vw2 = __shfl_sync(FULL, P.w, L2);
                float p00 = par ? vy1 : vx1;
                float p10 = par ? vw1 : vz1;
                float p01 = par ? vy2 : vx2;
                float p11 = par ? vw2 : vz2;
                float h00 = tf32r(p00), h10 = tf32r(p10), h01 = tf32r(p01), h11 = tf32r(p11);
                Ph[g] = make_uint4(__float_as_uint(h00), __float_as_uint(h10),
                                   __float_as_uint(h01), __float_as_uint(h11));
                Pl[g] = make_uint4(__float_as_uint(tf32r(p00 - h00)), __float_as_uint(tf32r(p10 - h10)),
                                   __float_as_uint(tf32r(p01 - h01)), __float_as_uint(tf32r(p11 - h11)));
            }
#pragma unroll
            for (int nt = 0; nt < 8; nt++) {
                int vb = VH_ + (8 * nt + qr) * 68 + 8 * k8 + qc;
                uint32_t bh0 = __float_as_uint(sf[vb]);
                uint32_t bh1 = __float_as_uint(sf[vb + 4]);
                int vl = vb + (VL_ - VH_);
                uint32_t bl0 = __float_as_uint(sf[vl]);
                uint32_t bl1 = __float_as_uint(sf[vl + 4]);
                mma8(O[0][nt], Ph[0], bh0, bh1);
                mma8(O[0][nt], Ph[0], bl0, bl1);
                mma8(O[0][nt], Pl[0], bh0, bh1);
                mma8(O[1][nt], Ph[1], bh0, bh1);
                mma8(O[1][nt], Ph[1], bl0, bl1);
                mma8(O[1][nt], Pl[1], bh0, bh1);
            }
        }

        __syncthreads();
        if (kt + 1 < 16) {
            ldtile256(sb + KH_ * 4, Khg + (kt + 1) * 4096, 64, tid);
            ldtile256(sb + KL_ * 4, Klg + (kt + 1) * 4096, 64, tid);
            ldtile256(sb + VH_ * 4, Vhg + (kt + 1) * 64, NN, tid);
            ldtile256(sb + VL_ * 4, Vlg + (kt + 1) * 64, NN, tid);
        }
        cp_commit();
    }

#pragma unroll
    for (int g = 0; g < 2; g++) {
        float l0 = l[g][0], l1 = l[g][1];
        l0 += __shfl_xor_sync(FULL, l0, 1);
        l0 += __shfl_xor_sync(FULL, l0, 2);
        l1 += __shfl_xor_sync(FULL, l1, 1);
        l1 += __shfl_xor_sync(FULL, l1, 2);
        float i0 = 1.0f / l0, i1 = 1.0f / l1;
        const float* Xi0 = g_X[pp] + ((size_t)(b * NN + n0) + wrow + g * 16 + qr) * CC;
        const float* Xi8 = Xi0 + 8 * CC;
        float* Xo0 = g_X[pp ^ 1] + ((size_t)(b * NN + n0) + wrow + g * 16 + qr) * CC;
        float* Xo8 = Xo0 + 8 * CC;
#pragma unroll
        for (int nt = 0; nt < 8; nt++) {
            int c = 8 * nt + 2 * qc;
            float2 a = *(const float2*)&Xi0[c];
            float2 bb = *(const float2*)&Xi8[c];
            *(float2*)&Xo0[c] = make_float2(O[g][nt].x * i0 + a.x, O[g][nt].y * i0 + a.y);
            *(float2*)&Xo8[c] = make_float2(O[g][nt].z * i1 + bb.x, O[g][nt].w * i1 + bb.y);
        }
    }
}
// ---------------------------------------------------------------------------
__global__ void k_head(const float* __restrict__ lw, const float* __restrict__ lb,
                       float* __restrict__ out) {
    __shared__ float meanv[NN];
    __shared__ float red[8];
    int b = blockIdx.x;
    const float* Xb = g_X[0] + (size_t)b * NN * CC;
    for (int n = threadIdx.x; n < NN; n += 256) {
        const float4* p = (const float4*)(Xb + (size_t)n * CC);
        float s = 0.0f;
#pragma unroll
        for (int q = 0; q < 16; q++) { float4 v = p[q]; s += v.x + v.y + v.z + v.w; }
        meanv[n] = s * (1.0f / 64.0f);
    }
    __syncthreads();
    for (int cls = 0; cls < NCLS; cls++) {
        float s = 0.0f;
        for (int n = threadIdx.x; n < NN; n += 256) s += meanv[n] * lw[cls * NN + n];
#pragma unroll
        for (int d = 16; d; d >>= 1) s += __shfl_xor_sync(0xffffffffu, s, d);
        if ((threadIdx.x & 31) == 0) red[threadIdx.x >> 5] = s;
        __syncthreads();
        if (threadIdx.x == 0) {
            float t = 0.0f;
#pragma unroll
            for (int w = 0; w < 8; w++) t += red[w];
            out[b * NCLS + cls] = t + lb[cls];
        }
        __syncthreads();
    }
}
// ---------------------------------------------------------------------------
extern "C" void kernel_launch(void* const* d_in, const int* in_sizes, int n_in,
                              void* d_out, int out_size) {
    (void)in_sizes; (void)n_in; (void)out_size;
    const float* img = (const float*)d_in[0];
    const float* WV  = (const float*)d_in[1];
    const float* WK  = (const float*)d_in[2];
    const float* WQ  = (const float*)d_in[3];
    const float* lw  = (const float*)d_in[4];
    const float* lb  = (const float*)d_in[5];
    float* out = (float*)d_out;

    const int QKV_SMEM  = (2 * 64 * 68 + 64 * 192) * 4;   // 83968 B
    const int ATTN_SMEM = ATTN_SMEMF * 4;                 // 208896 B
    cudaFuncSetAttribute(k_qkv,  cudaFuncAttributeMaxDynamicSharedMemorySize, QKV_SMEM);
    cudaFuncSetAttribute(k_attn, cudaFuncAttributeMaxDynamicSharedMemorySize, ATTN_SMEM);

    dim3 gq(8, 32), ga(4, 32);
    k_transpose<<<dim3(16, 32), 256>>>(img);
    for (int l = 0; l < DEPTH; l++) {
        k_qkv<<<gq, 256, QKV_SMEM>>>(WQ, WK, WV, l & 1);
        k_attn<<<ga, 256, ATTN_SMEM>>>(l & 1);
    }
    k_head<<<32, 256>>>(lw, lb, out);
}

// round 13
// speedup vs baseline: 1.6362x; 1.0404x over previous
#include <cuda_runtime.h>
#include <cuda_bf16.h>
#include <cstdint>

#define BB 32
#define CC 64
#define NN 1024
#define DEPTH 8
#define NCLS 10

using u64 = unsigned long long;

static __device__ float g_X[2][BB * NN * CC];
static __device__ float g_Qh[BB * NN * CC];
static __device__ float g_Ql[BB * NN * CC];
static __device__ float g_K[BB * NN * 128];    // packed: [b][n][f4*4] {kh(c),kh(c+4),kl(c),kl(c+4)}, c=8*(f4>>2)+(f4&3)
static __device__ float g_V[BB * CC * 2048];   // packed V^T: [b][c][key-chunks] same 8-key packing

// ---------------- packed fp32 helpers ----------------
__device__ __forceinline__ u64 ffma2(u64 a, u64 b, u64 c) {
    u64 d; asm("fma.rn.f32x2 %0, %1, %2, %3;" : "=l"(d) : "l"(a), "l"(b), "l"(c)); return d;
}
__device__ __forceinline__ u64 fmul2(u64 a, u64 b) {
    u64 d; asm("mul.rn.f32x2 %0, %1, %2;" : "=l"(d) : "l"(a), "l"(b)); return d;
}
__device__ __forceinline__ u64 dup2(float x) {
    u64 r; asm("mov.b64 %0, {%1, %1};" : "=l"(r) : "f"(x)); return r;
}
__device__ __forceinline__ float2 u2f2(u64 v) {
    float2 r; asm("mov.b64 {%0, %1}, %2;" : "=f"(r.x), "=f"(r.y) : "l"(v)); return r;
}
__device__ __forceinline__ float tf32r(float x) {
    uint32_t u; asm("cvt.rna.tf32.f32 %0, %1;" : "=r"(u) : "f"(x)); return __uint_as_float(u);
}
// ---------------- cp.async ----------------
__device__ __forceinline__ void cp16(uint32_t dst, const float* src) {
    asm volatile("cp.async.cg.shared.global [%0], [%1], 16;" :: "r"(dst), "l"(src));
}
__device__ __forceinline__ void cp_commit() { asm volatile("cp.async.commit_group;" ::: "memory"); }
__device__ __forceinline__ void cp_wait0()  { asm volatile("cp.async.wait_group 0;" ::: "memory"); }

// ---------------- warp mma.sync tf32 m16n8k8 ----------------
__device__ __forceinline__ void mma8(float4& d, const uint4& a, uint32_t b0, uint32_t b1) {
    asm volatile(
        "mma.sync.aligned.m16n8k8.row.col.f32.tf32.tf32.f32 "
        "{%0,%1,%2,%3}, {%4,%5,%6,%7}, {%8,%9}, {%0,%1,%2,%3};"
        : "+f"(d.x), "+f"(d.y), "+f"(d.z), "+f"(d.w)
        : "r"(a.x), "r"(a.y), "r"(a.z), "r"(a.w), "r"(b0), "r"(b1));
}

// ---------------------------------------------------------------------------
__global__ void k_transpose(const float* __restrict__ img) {
    __shared__ float t[64][65];
    int b = blockIdx.y, n0 = blockIdx.x * 64;
    const float* src = img + (size_t)b * CC * NN;
    for (int i = threadIdx.x; i < 4096; i += 256) t[i >> 6][i & 63] = src[(i >> 6) * NN + n0 + (i & 63)];
    __syncthreads();
    float* dst = g_X[0] + ((size_t)b * NN + n0) * CC;
    for (int i = threadIdx.x; i < 4096; i += 256) dst[(i >> 6) * CC + (i & 63)] = t[i & 63][i >> 6];
}
// ---------------------------------------------------------------------------
// QKV: 2 row-tiles/CTA, X double-buffered, W loaded once.
// K staged raw in Kst; V staged raw in dead X buffer; packed-split on write.
__global__ void __launch_bounds__(256) k_qkv(const float* __restrict__ WQ,
                                             const float* __restrict__ WK,
                                             const float* __restrict__ WV, int pp) {
    extern __shared__ float sm[];
    float* Xb[2] = { sm, sm + 4352 };     // 2 x (64 x 68)
    float* Ws = sm + 8704;                // 64 x 192
    float* Kst = sm + 20992;              // 64 x 68 raw K staging
    uint32_t sX0 = (uint32_t)__cvta_generic_to_shared(Xb[0]);
    uint32_t sX1 = (uint32_t)__cvta_generic_to_shared(Xb[1]);
    uint32_t sWs = (uint32_t)__cvta_generic_to_shared(Ws);
    int b = blockIdx.y, tid = threadIdx.x;
    int r0 = blockIdx.x * 128;

    const float* Xin = g_X[pp] + ((size_t)b * NN + r0) * CC;
#pragma unroll
    for (int t = 0; t < 4; t++) {
        int i = tid + t * 256, r = i >> 4, c = (i & 15) << 2;
        cp16(sX0 + (r * 68 + c) * 4, Xin + r * 64 + c);
    }
#pragma unroll
    for (int t = 0; t < 12; t++) {
        int fo = (tid + t * 256) * 4;
        int k = fo / 192, c = fo - k * 192;
        const float* src = (c < 64) ? (WQ + k * 64 + c)
                         : (c < 128) ? (WK + k * 64 + c - 64)
                                     : (WV + k * 64 + c - 128);
        cp16(sWs + fo * 4, src);
    }
    cp_commit();

    int tx = tid & 15, ty = tid >> 4;
    const u64 scale2 = dup2(0.03125f);

#pragma unroll 1
    for (int tile = 0; tile < 2; tile++) {
        cp_wait0();
        __syncthreads();
        if (tile == 0) {
#pragma unroll
            for (int t = 0; t < 4; t++) {
                int i = tid + t * 256, r = i >> 4, c = (i & 15) << 2;
                cp16(sX1 + (r * 68 + c) * 4, Xin + (64 + r) * 64 + c);
            }
            cp_commit();
        }
        float* Xs = Xb[tile];

        u64 acc[4][6];
#pragma unroll
        for (int i = 0; i < 4; i++)
#pragma unroll
            for (int j = 0; j < 6; j++) acc[i][j] = 0ULL;

#pragma unroll 2
        for (int k0 = 0; k0 < 64; k0 += 4) {
            float4 xv[4];
#pragma unroll
            for (int i = 0; i < 4; i++) xv[i] = *(const float4*)&Xs[(ty * 4 + i) * 68 + k0];
#pragma unroll
            for (int kk = 0; kk < 4; kk++) {
                u64 wv[6];
#pragma unroll
                for (int j = 0; j < 6; j++) wv[j] = *(const u64*)&Ws[(k0 + kk) * 192 + tx * 2 + 32 * j];
                u64 xd[4];
#pragma unroll
                for (int i = 0; i < 4; i++)
                    xd[i] = dup2(kk == 0 ? xv[i].x : kk == 1 ? xv[i].y : kk == 2 ? xv[i].z : xv[i].w);
#pragma unroll
                for (int i = 0; i < 4; i++)
#pragma unroll
                    for (int j = 0; j < 6; j++) acc[i][j] = ffma2(xd[i], wv[j], acc[i][j]);
            }
        }

        int rowbase = r0 + tile * 64;
        size_t base = ((size_t)b * NN + rowbase) * CC;
        // Q split writes (layout unchanged)
#pragma unroll
        for (int i = 0; i < 4; i++) {
            int r = ty * 4 + i, co = tx * 2;
#pragma unroll
            for (int j = 0; j < 2; j++) {
                int c = co + 32 * j;
                float2 q = u2f2(fmul2(acc[i][j], scale2));
                float qhx = tf32r(q.x), qhy = tf32r(q.y);
                *(float2*)&g_Qh[base + r * 64 + c] = make_float2(qhx, qhy);
                *(float2*)&g_Ql[base + r * 64 + c] = make_float2(tf32r(q.x - qhx), tf32r(q.y - qhy));
            }
        }
        // stage raw K and raw V
        __syncthreads();   // compute reads of Xs done
#pragma unroll
        for (int i = 0; i < 4; i++) {
            int r = ty * 4 + i, co = tx * 2;
#pragma unroll
            for (int j = 0; j < 2; j++) {
                int c = co + 32 * j;
                *(float2*)&Kst[r * 68 + c] = u2f2(acc[i][2 + j]);
                *(float2*)&Xs[r * 68 + c]  = u2f2(acc[i][4 + j]);   // raw V
            }
        }
        __syncthreads();
        // packed-split global writes (coalesced STG.128)
        float* gK = g_K + ((size_t)b * NN + rowbase) * 128;
        float* gV = g_V + (size_t)b * CC * 2048 + rowbase * 2;   // 64 keys -> 128 floats
        for (int q = tid; q < 2048; q += 256) {
            int r = q >> 5, f = q & 31;
            int c = 8 * (f >> 2) + (f & 3);
            // K: row r (token), channel pair (c, c+4)
            float a = Kst[r * 68 + c], bb = Kst[r * 68 + c + 4];
            float ah = tf32r(a), bh = tf32r(bb);
            *(float4*)&gK[(size_t)r * 128 + f * 4] =
                make_float4(ah, bh, tf32r(a - ah), tf32r(bb - bh));
            // V^T: row r = channel, key pair (c, c+4) within tile
            float va = Xs[c * 68 + r], vb = Xs[(c + 4) * 68 + r];
            float vah = tf32r(va), vbh = tf32r(vb);
            *(float4*)&gV[(size_t)r * 2048 + f * 4] =
                make_float4(vah, vbh, tf32r(va - vah), tf32r(vb - vbh));
        }
    }
}
// ---------------------------------------------------------------------------
// mma.sync flash attention. CTA = 256 q-rows, 256 threads, 8 warps x 32 rows.
// B-operands (K/V) pre-packed: one LDS.128 per (k8,nt) fragment pair.
#define QH_ 0
#define QL_ 17408
#define KP_ 34816             // 64 rows x 144 floats (36 float4, conflict-free)
#define VP_ 44032
#define ATTN_SMEMF 53248      // 212992 bytes

__global__ void __launch_bounds__(256, 1) k_attn(int pp) {
    extern __shared__ float sf[];
    uint32_t sb = (uint32_t)__cvta_generic_to_shared(sf);
    int b = blockIdx.y, n0 = blockIdx.x * 256, tid = threadIdx.x;
    int wid = tid >> 5, lane = tid & 31;
    int qr = lane >> 2, qc = lane & 3;
    int wrow = wid * 32;
    int L1 = (lane & 0x1C) | ((lane & 3) >> 1);
    int L2 = L1 + 2;
    bool par = (lane & 1) != 0;
    const uint32_t FULL = 0xffffffffu;

    const float* Qhg = g_Qh + ((size_t)b * NN + n0) * CC;
    const float* Qlg = g_Ql + ((size_t)b * NN + n0) * CC;
    const float* Kg = g_K + (size_t)b * NN * 128;
    const float* Vg = g_V + (size_t)b * CC * 2048;

    // prologue: Q hi/lo + K0/V0 (packed linear copies)
#pragma unroll
    for (int t = 0; t < 16; t++) {
        int q = tid + t * 256;
        int r = q >> 4, c = (q & 15) << 2;
        cp16(sb + (QH_ + r * 68 + c) * 4, Qhg + r * 64 + c);
        cp16(sb + (QL_ + r * 68 + c) * 4, Qlg + r * 64 + c);
    }
#pragma unroll
    for (int t = 0; t < 8; t++) {
        int q = tid + t * 256;
        int r = q >> 5, q4 = (q & 31) << 2;
        cp16(sb + (KP_ + r * 144 + q4) * 4, Kg + (size_t)r * 128 + q4);
        cp16(sb + (VP_ + r * 144 + q4) * 4, Vg + (size_t)r * 2048 + q4);
    }
    cp_commit();

    float4 O[2][8];
#pragma unroll
    for (int g = 0; g < 2; g++)
#pragma unroll
        for (int nt = 0; nt < 8; nt++) O[g][nt] = make_float4(0.f, 0.f, 0.f, 0.f);
    float m[2][2], l[2][2];
#pragma unroll
    for (int g = 0; g < 2; g++) { m[g][0] = m[g][1] = -1e30f; l[g][0] = l[g][1] = 0.f; }

#pragma unroll 1
    for (int kt = 0; kt < 16; ++kt) {
        cp_wait0();
        __syncthreads();

        // ---- S = Qh*Kh + Qh*Kl + Ql*Kh ----
        float4 S[2][8];
#pragma unroll
        for (int g = 0; g < 2; g++)
#pragma unroll
            for (int nt = 0; nt < 8; nt++) S[g][nt] = make_float4(0.f, 0.f, 0.f, 0.f);
#pragma unroll
        for (int k8 = 0; k8 < 8; k8++) {
            int qa0 = QH_ + (wrow + qr) * 68 + 8 * k8 + qc;
            uint4 Ah0 = make_uint4(__float_as_uint(sf[qa0]),
                                   __float_as_uint(sf[qa0 + 8 * 68]),
                                   __float_as_uint(sf[qa0 + 4]),
                                   __float_as_uint(sf[qa0 + 4 + 8 * 68]));
            int ql0 = qa0 + (QL_ - QH_);
            uint4 Al0 = make_uint4(__float_as_uint(sf[ql0]),
                                   __float_as_uint(sf[ql0 + 8 * 68]),
                                   __float_as_uint(sf[ql0 + 4]),
                                   __float_as_uint(sf[ql0 + 4 + 8 * 68]));
            int qa1 = qa0 + 16 * 68;
            uint4 Ah1 = make_uint4(__float_as_uint(sf[qa1]),
                                   __float_as_uint(sf[qa1 + 8 * 68]),
                                   __float_as_uint(sf[qa1 + 4]),
                                   __float_as_uint(sf[qa1 + 4 + 8 * 68]));
            int ql1 = qa1 + (QL_ - QH_);
            uint4 Al1 = make_uint4(__float_as_uint(sf[ql1]),
                                   __float_as_uint(sf[ql1 + 8 * 68]),
                                   __float_as_uint(sf[ql1 + 4]),
                                   __float_as_uint(sf[ql1 + 4 + 8 * 68]));
#pragma unroll
            for (int nt = 0; nt < 8; nt++) {
                float4 kb = *(const float4*)&sf[KP_ + (8 * nt + qr) * 144 + (4 * k8 + qc) * 4];
                uint32_t bh0 = __float_as_uint(kb.x), bh1 = __float_as_uint(kb.y);
                uint32_t bl0 = __float_as_uint(kb.z), bl1 = __float_as_uint(kb.w);
                mma8(S[0][nt], Ah0, bh0, bh1);
                mma8(S[0][nt], Ah0, bl0, bl1);
                mma8(S[0][nt], Al0, bh0, bh1);
                mma8(S[1][nt], Ah1, bh0, bh1);
                mma8(S[1][nt], Ah1, bl0, bl1);
                mma8(S[1][nt], Al1, bh0, bh1);
            }
        }

        // ---- online softmax per group ----
#pragma unroll
        for (int g = 0; g < 2; g++) {
            float mx0 = -1e30f, mx1 = -1e30f;
#pragma unroll
            for (int nt = 0; nt < 8; nt++) {
                mx0 = fmaxf(mx0, fmaxf(S[g][nt].x, S[g][nt].y));
                mx1 = fmaxf(mx1, fmaxf(S[g][nt].z, S[g][nt].w));
            }
            mx0 = fmaxf(mx0, __shfl_xor_sync(FULL, mx0, 1));
            mx0 = fmaxf(mx0, __shfl_xor_sync(FULL, mx0, 2));
            mx1 = fmaxf(mx1, __shfl_xor_sync(FULL, mx1, 1));
            mx1 = fmaxf(mx1, __shfl_xor_sync(FULL, mx1, 2));
            float mn0 = fmaxf(m[g][0], mx0), mn1 = fmaxf(m[g][1], mx1);
            float c0 = __expf(m[g][0] - mn0), c1 = __expf(m[g][1] - mn1);
            m[g][0] = mn0; m[g][1] = mn1;
            float ps0 = 0.f, ps1 = 0.f;
#pragma unroll
            for (int nt = 0; nt < 8; nt++) {
                S[g][nt].x = __expf(S[g][nt].x - mn0);
                S[g][nt].y = __expf(S[g][nt].y - mn0);
                S[g][nt].z = __expf(S[g][nt].z - mn1);
                S[g][nt].w = __expf(S[g][nt].w - mn1);
                ps0 += S[g][nt].x + S[g][nt].y;
                ps1 += S[g][nt].z + S[g][nt].w;
            }
            l[g][0] = l[g][0] * c0 + ps0;
            l[g][1] = l[g][1] * c1 + ps1;
#pragma unroll
            for (int nt = 0; nt < 8; nt++) {
                O[g][nt].x *= c0; O[g][nt].y *= c0; O[g][nt].z *= c1; O[g][nt].w *= c1;
            }
        }

        // ---- PV: shuffle P fragments per group; V packed LDS.128 ----
#pragma unroll
        for (int k8 = 0; k8 < 8; k8++) {
            uint4 Ph[2], Pl[2];
#pragma unroll
            for (int g = 0; g < 2; g++) {
                float4 P = S[g][k8];
                float vx1 = __shfl_sync(FULL, P.x, L1);
                float vy1 = __shfl_sync(FULL, P.y, L1);
                float vz1 = __shfl_sync(FULL, P.z, L1);
                float vw1 = __shfl_sync(FULL, P.w, L1);
                float vx2 = __shfl_sync(FULL, P.x, L2);
                float vy2 = __shfl_sync(FULL, P.y, L2);
                float vz2 = __shfl_sync(FULL, P.z, L2);
                float vw2 = __shfl_sync(FULL, P.w, L2);
                float p00 = par ? vy1 : vx1;
                float p10 = par ? vw1 : vz1;
                float p01 = par ? vy2 : vx2;
                float p11 = par ? vw2 : vz2;
                float h00 = tf32r(p00), h10 = tf32r(p10), h01 = tf32r(p01), h11 = tf32r(p11);
                Ph[g] = make_uint4(__float_as_uint(h00), __float_as_uint(h10),
                                   __float_as_uint(h01), __float_as_uint(h11));
                Pl[g] = make_uint4(__float_as_uint(tf32r(p00 - h00)), __float_as_uint(tf32r(p10 - h10)),
                                   __float_as_uint(tf32r(p01 - h01)), __float_as_uint(tf32r(p11 - h11)));
            }
#pragma unroll
            for (int nt = 0; nt < 8; nt++) {
                float4 vbq = *(const float4*)&sf[VP_ + (8 * nt + qr) * 144 + (4 * k8 + qc) * 4];
                uint32_t bh0 = __float_as_uint(vbq.x), bh1 = __float_as_uint(vbq.y);
                uint32_t bl0 = __float_as_uint(vbq.z), bl1 = __float_as_uint(vbq.w);
                mma8(O[0][nt], Ph[0], bh0, bh1);
                mma8(O[0][nt], Ph[0], bl0, bl1);
                mma8(O[0][nt], Pl[0], bh0, bh1);
                mma8(O[1][nt], Ph[1], bh0, bh1);
                mma8(O[1][nt], Ph[1], bl0, bl1);
                mma8(O[1][nt], Pl[1], bh0, bh1);
            }
        }

        __syncthreads();
        if (kt + 1 < 16) {
#pragma unroll
            for (int t = 0; t < 8; t++) {
                int q = tid + t * 256;
                int r = q >> 5, q4 = (q & 31) << 2;
                cp16(sb + (KP_ + r * 144 + q4) * 4, Kg + (size_t)(64 * (kt + 1) + r) * 128 + q4);
                cp16(sb + (VP_ + r * 144 + q4) * 4, Vg + (size_t)r * 2048 + (kt + 1) * 128 + q4);
            }
        }
        cp_commit();
    }

    // epilogue per group
#pragma unroll
    for (int g = 0; g < 2; g++) {
        float l0 = l[g][0], l1 = l[g][1];
        l0 += __shfl_xor_sync(FULL, l0, 1);
        l0 += __shfl_xor_sync(FULL, l0, 2);
        l1 += __shfl_xor_sync(FULL, l1, 1);
        l1 += __shfl_xor_sync(FULL, l1, 2);
        float i0 = 1.0f / l0, i1 = 1.0f / l1;
        const float* Xi0 = g_X[pp] + ((size_t)(b * NN + n0) + wrow + g * 16 + qr) * CC;
        const float* Xi8 = Xi0 + 8 * CC;
        float* Xo0 = g_X[pp ^ 1] + ((size_t)(b * NN + n0) + wrow + g * 16 + qr) * CC;
        float* Xo8 = Xo0 + 8 * CC;
#pragma unroll
        for (int nt = 0; nt < 8; nt++) {
            int c = 8 * nt + 2 * qc;
            float2 a = *(const float2*)&Xi0[c];
            float2 bb = *(const float2*)&Xi8[c];
            *(float2*)&Xo0[c] = make_float2(O[g][nt].x * i0 + a.x, O[g][nt].y * i0 + a.y);
            *(float2*)&Xo8[c] = make_float2(O[g][nt].z * i1 + bb.x, O[g][nt].w * i1 + bb.y);
        }
    }
}
// ---------------------------------------------------------------------------
__global__ void k_head(const float* __restrict__ lw, const float* __restrict__ lb,
                       float* __restrict__ out) {
    __shared__ float meanv[NN];
    __shared__ float red[8];
    int b = blockIdx.x;
    const float* Xb = g_X[0] + (size_t)b * NN * CC;
    for (int n = threadIdx.x; n < NN; n += 256) {
        const float4* p = (const float4*)(Xb + (size_t)n * CC);
        float s = 0.0f;
#pragma unroll
        for (int q = 0; q < 16; q++) { float4 v = p[q]; s += v.x + v.y + v.z + v.w; }
        meanv[n] = s * (1.0f / 64.0f);
    }
    __syncthreads();
    for (int cls = 0; cls < NCLS; cls++) {
        float s = 0.0f;
        for (int n = threadIdx.x; n < NN; n += 256) s += meanv[n] * lw[cls * NN + n];
#pragma unroll
        for (int d = 16; d; d >>= 1) s += __shfl_xor_sync(0xffffffffu, s, d);
        if ((threadIdx.x & 31) == 0) red[threadIdx.x >> 5] = s;
        __syncthreads();
        if (threadIdx.x == 0) {
            float t = 0.0f;
#pragma unroll
            for (int w = 0; w < 8; w++) t += red[w];
            out[b * NCLS + cls] = t + lb[cls];
        }
        __syncthreads();
    }
}
// ---------------------------------------------------------------------------
extern "C" void kernel_launch(void* const* d_in, const int* in_sizes, int n_in,
                              void* d_out, int out_size) {
    (void)in_sizes; (void)n_in; (void)out_size;
    const float* img = (const float*)d_in[0];
    const float* WV  = (const float*)d_in[1];
    const float* WK  = (const float*)d_in[2];
    const float* WQ  = (const float*)d_in[3];
    const float* lw  = (const float*)d_in[4];
    const float* lb  = (const float*)d_in[5];
    float* out = (float*)d_out;

    const int QKV_SMEM  = (2 * 64 * 68 + 64 * 192 + 64 * 68) * 4;   // 101376 B
    const int ATTN_SMEM = ATTN_SMEMF * 4;                           // 212992 B
    cudaFuncSetAttribute(k_qkv,  cudaFuncAttributeMaxDynamicSharedMemorySize, QKV_SMEM);
    cudaFuncSetAttribute(k_attn, cudaFuncAttributeMaxDynamicSharedMemorySize, ATTN_SMEM);

    dim3 gq(8, 32), ga(4, 32);
    k_transpose<<<dim3(16, 32), 256>>>(img);
    for (int l = 0; l < DEPTH; l++) {
        k_qkv<<<gq, 256, QKV_SMEM>>>(WQ, WK, WV, l & 1);
        k_attn<<<ga, 256, ATTN_SMEM>>>(l & 1);
    }
    k_head<<<32, 256>>>(lw, lb, out);
}

// round 14
// speedup vs baseline: 2.3624x; 1.4438x over previous
#include <cuda_runtime.h>
#include <cuda_bf16.h>
#include <cuda_fp16.h>
#include <cstdint>

#define BB 32
#define CC 64
#define NN 1024
#define DEPTH 8
#define NCLS 10

using u64 = unsigned long long;

static __device__ float g_X[2][BB * NN * CC];
static __device__ float g_Qp[BB * NN * 64];    // packed fp16 split Q: [b][n][16 f4]
static __device__ float g_Kp[BB * NN * 64];    // packed fp16 split K
static __device__ float g_Vp[BB * CC * NN];    // packed fp16 split V^T: [b][c][tile][16 f4]
static __device__ float g_sQ[BB * 16];
static __device__ float g_sK[BB * 16];
static __device__ float g_sV[BB * 16];

// ---------------- packed fp32 helpers ----------------
__device__ __forceinline__ u64 ffma2(u64 a, u64 b, u64 c) {
    u64 d; asm("fma.rn.f32x2 %0, %1, %2, %3;" : "=l"(d) : "l"(a), "l"(b), "l"(c)); return d;
}
__device__ __forceinline__ u64 fmul2(u64 a, u64 b) {
    u64 d; asm("mul.rn.f32x2 %0, %1, %2;" : "=l"(d) : "l"(a), "l"(b)); return d;
}
__device__ __forceinline__ u64 dup2(float x) {
    u64 r; asm("mov.b64 %0, {%1, %1};" : "=l"(r) : "f"(x)); return r;
}
__device__ __forceinline__ float2 u2f2(u64 v) {
    float2 r; asm("mov.b64 {%0, %1}, %2;" : "=f"(r.x), "=f"(r.y) : "l"(v)); return r;
}
__device__ __forceinline__ uint32_t h2u(float a, float b) {
    __half2 h = __float22half2_rn(make_float2(a, b));
    return *reinterpret_cast<uint32_t*>(&h);
}
__device__ __forceinline__ float2 u2h2f(uint32_t u) {
    __half2 h = *reinterpret_cast<__half2*>(&u);
    return __half22float2(h);
}
// ---------------- cp.async ----------------
__device__ __forceinline__ void cp16(uint32_t dst, const float* src) {
    asm volatile("cp.async.cg.shared.global [%0], [%1], 16;" :: "r"(dst), "l"(src));
}
__device__ __forceinline__ void cp_commit() { asm volatile("cp.async.commit_group;" ::: "memory"); }
__device__ __forceinline__ void cp_wait0()  { asm volatile("cp.async.wait_group 0;" ::: "memory"); }

// ---------------- warp mma.sync fp16 m16n8k16 (fp32 accum) ----------------
__device__ __forceinline__ void mma16(float4& d, uint32_t a0, uint32_t a1, uint32_t a2,
                                      uint32_t a3, uint32_t b0, uint32_t b1) {
    asm volatile(
        "mma.sync.aligned.m16n8k16.row.col.f32.f16.f16.f32 "
        "{%0,%1,%2,%3}, {%4,%5,%6,%7}, {%8,%9}, {%0,%1,%2,%3};"
        : "+f"(d.x), "+f"(d.y), "+f"(d.z), "+f"(d.w)
        : "r"(a0), "r"(a1), "r"(a2), "r"(a3), "r"(b0), "r"(b1));
}

// pow2 scale >= m (exact power of two, handles m==0)
__device__ __forceinline__ float pow2scale(float m) {
    if (m <= 0.0f) return 1.0f;
    uint32_t u = __float_as_uint(m);
    return __uint_as_float((u & 0x7f800000u) + 0x00800000u);
}

// ---------------------------------------------------------------------------
__global__ void k_transpose(const float* __restrict__ img) {
    __shared__ float t[64][65];
    int b = blockIdx.y, n0 = blockIdx.x * 64;
    const float* src = img + (size_t)b * CC * NN;
    for (int i = threadIdx.x; i < 4096; i += 256) t[i >> 6][i & 63] = src[(i >> 6) * NN + n0 + (i & 63)];
    __syncthreads();
    float* dst = g_X[0] + ((size_t)b * NN + n0) * CC;
    for (int i = threadIdx.x; i < 4096; i += 256) dst[(i >> 6) * CC + (i & 63)] = t[i & 63][i >> 6];
}
// ---------------------------------------------------------------------------
// QKV: 2 row-tiles/CTA; X double-buffered; per-tile pow2 scales; fp16-split
// packed outputs shaped as m16n8k16 fragments.
__global__ void __launch_bounds__(256) k_qkv(const float* __restrict__ WQ,
                                             const float* __restrict__ WK,
                                             const float* __restrict__ WV, int pp) {
    extern __shared__ float sm[];
    float* Xb[2] = { sm, sm + 4352 };     // 2 x (64 x 68)
    float* Ws  = sm + 8704;               // 64 x 192
    float* Kst = sm + 20992;              // 64 x 68
    float* Qst = sm + 25344;              // 64 x 68
    float* red = sm + 29696;              // 24 floats
    uint32_t sX0 = (uint32_t)__cvta_generic_to_shared(Xb[0]);
    uint32_t sX1 = (uint32_t)__cvta_generic_to_shared(Xb[1]);
    uint32_t sWs = (uint32_t)__cvta_generic_to_shared(Ws);
    int b = blockIdx.y, tid = threadIdx.x;
    int wid = tid >> 5, lane = tid & 31;
    int r0 = blockIdx.x * 128;

    const float* Xin = g_X[pp] + ((size_t)b * NN + r0) * CC;
#pragma unroll
    for (int t = 0; t < 4; t++) {
        int i = tid + t * 256, r = i >> 4, c = (i & 15) << 2;
        cp16(sX0 + (r * 68 + c) * 4, Xin + r * 64 + c);
    }
#pragma unroll
    for (int t = 0; t < 12; t++) {
        int fo = (tid + t * 256) * 4;
        int k = fo / 192, c = fo - k * 192;
        const float* src = (c < 64) ? (WQ + k * 64 + c)
                         : (c < 128) ? (WK + k * 64 + c - 64)
                                     : (WV + k * 64 + c - 128);
        cp16(sWs + fo * 4, src);
    }
    cp_commit();

    int tx = tid & 15, ty = tid >> 4;
    const u64 scale2 = dup2(0.03125f);

#pragma unroll 1
    for (int tile = 0; tile < 2; tile++) {
        cp_wait0();
        __syncthreads();
        if (tile == 0) {
#pragma unroll
            for (int t = 0; t < 4; t++) {
                int i = tid + t * 256, r = i >> 4, c = (i & 15) << 2;
                cp16(sX1 + (r * 68 + c) * 4, Xin + (64 + r) * 64 + c);
            }
            cp_commit();
        }
        float* Xs = Xb[tile];

        u64 acc[4][6];
#pragma unroll
        for (int i = 0; i < 4; i++)
#pragma unroll
            for (int j = 0; j < 6; j++) acc[i][j] = 0ULL;

#pragma unroll 2
        for (int k0 = 0; k0 < 64; k0 += 4) {
            float4 xv[4];
#pragma unroll
            for (int i = 0; i < 4; i++) xv[i] = *(const float4*)&Xs[(ty * 4 + i) * 68 + k0];
#pragma unroll
            for (int kk = 0; kk < 4; kk++) {
                u64 wv[6];
#pragma unroll
                for (int j = 0; j < 6; j++) wv[j] = *(const u64*)&Ws[(k0 + kk) * 192 + tx * 2 + 32 * j];
                u64 xd[4];
#pragma unroll
                for (int i = 0; i < 4; i++)
                    xd[i] = dup2(kk == 0 ? xv[i].x : kk == 1 ? xv[i].y : kk == 2 ? xv[i].z : xv[i].w);
#pragma unroll
                for (int i = 0; i < 4; i++)
#pragma unroll
                    for (int j = 0; j < 6; j++) acc[i][j] = ffma2(xd[i], wv[j], acc[i][j]);
            }
        }

        // per-tile max reductions (Q scaled)
        float mQ = 0.f, mK = 0.f, mV = 0.f;
#pragma unroll
        for (int i = 0; i < 4; i++)
#pragma unroll
            for (int j = 0; j < 2; j++) {
                float2 q = u2f2(fmul2(acc[i][j], scale2));
                mQ = fmaxf(mQ, fmaxf(fabsf(q.x), fabsf(q.y)));
                float2 k = u2f2(acc[i][2 + j]);
                mK = fmaxf(mK, fmaxf(fabsf(k.x), fabsf(k.y)));
                float2 v = u2f2(acc[i][4 + j]);
                mV = fmaxf(mV, fmaxf(fabsf(v.x), fabsf(v.y)));
            }
#pragma unroll
        for (int d = 16; d; d >>= 1) {
            mQ = fmaxf(mQ, __shfl_xor_sync(0xffffffffu, mQ, d));
            mK = fmaxf(mK, __shfl_xor_sync(0xffffffffu, mK, d));
            mV = fmaxf(mV, __shfl_xor_sync(0xffffffffu, mV, d));
        }
        if (lane == 0) { red[wid] = mQ; red[8 + wid] = mK; red[16 + wid] = mV; }
        __syncthreads();   // also: compute loop reads of Xs done -> staging safe
        mQ = red[0]; mK = red[8]; mV = red[16];
#pragma unroll
        for (int w = 1; w < 8; w++) {
            mQ = fmaxf(mQ, red[w]); mK = fmaxf(mK, red[8 + w]); mV = fmaxf(mV, red[16 + w]);
        }
        float sQv = pow2scale(mQ), sKv = pow2scale(mK), sVv = pow2scale(mV);
        float iQ = 1.0f / sQv, iK = 1.0f / sKv, iV = 1.0f / sVv;
        int tileIdx = blockIdx.x * 2 + tile;
        if (tid == 0) {
            g_sQ[b * 16 + tileIdx] = sQv;
            g_sK[b * 16 + tileIdx] = sKv;
            g_sV[b * 16 + tileIdx] = sVv;
        }

        // stage raw (Q pre-scaled by 1/32) into Qst/Kst; V into Xs
#pragma unroll
        for (int i = 0; i < 4; i++) {
            int r = ty * 4 + i, co = tx * 2;
#pragma unroll
            for (int j = 0; j < 2; j++) {
                int c = co + 32 * j;
                *(float2*)&Qst[r * 68 + c] = u2f2(fmul2(acc[i][j], scale2));
                *(float2*)&Kst[r * 68 + c] = u2f2(acc[i][2 + j]);
                *(float2*)&Xs[r * 68 + c]  = u2f2(acc[i][4 + j]);
            }
        }
        __syncthreads();

        // pack fp16 split: f4 = {h2(c0,c0+1), h2(c0+8,c0+9), l2, l2}
        int rowbase = r0 + tile * 64;
        uint4* gQ = (uint4*)g_Qp + ((size_t)b * NN + rowbase) * 16;
        uint4* gK = (uint4*)g_Kp + ((size_t)b * NN + rowbase) * 16;
        uint4* gV = (uint4*)g_Vp + ((size_t)b * 64 * 16 + tileIdx) * 16;
        for (int q = tid; q < 1024; q += 256) {
            int r = q >> 4, f = q & 15, t = f >> 2, qc = f & 3;
            int c0 = 16 * t + 2 * qc;
            // Q
            {
                float a0 = Qst[r * 68 + c0] * iQ, a1 = Qst[r * 68 + c0 + 1] * iQ;
                float a2 = Qst[r * 68 + c0 + 8] * iQ, a3 = Qst[r * 68 + c0 + 9] * iQ;
                uint32_t h01 = h2u(a0, a1), h23 = h2u(a2, a3);
                float2 b01 = u2h2f(h01), b23 = u2h2f(h23);
                gQ[(size_t)r * 16 + f] = make_uint4(h01, h23,
                    h2u(a0 - b01.x, a1 - b01.y), h2u(a2 - b23.x, a3 - b23.y));
            }
            // K
            {
                float a0 = Kst[r * 68 + c0] * iK, a1 = Kst[r * 68 + c0 + 1] * iK;
                float a2 = Kst[r * 68 + c0 + 8] * iK, a3 = Kst[r * 68 + c0 + 9] * iK;
                uint32_t h01 = h2u(a0, a1), h23 = h2u(a2, a3);
                float2 b01 = u2h2f(h01), b23 = u2h2f(h23);
                gK[(size_t)r * 16 + f] = make_uint4(h01, h23,
                    h2u(a0 - b01.x, a1 - b01.y), h2u(a2 - b23.x, a3 - b23.y));
            }
            // V^T: row r = channel, keys c0.. within tile
            {
                float a0 = Xs[c0 * 68 + r] * iV, a1 = Xs[(c0 + 1) * 68 + r] * iV;
                float a2 = Xs[(c0 + 8) * 68 + r] * iV, a3 = Xs[(c0 + 9) * 68 + r] * iV;
                uint32_t h01 = h2u(a0, a1), h23 = h2u(a2, a3);
                float2 b01 = u2h2f(h01), b23 = u2h2f(h23);
                gV[(size_t)r * 256 + f] = make_uint4(h01, h23,
                    h2u(a0 - b01.x, a1 - b01.y), h2u(a2 - b23.x, a3 - b23.y));
            }
        }
    }
}
// ---------------------------------------------------------------------------
// fp16 mma flash attention. CTA = 256 q-rows, 256 threads, 8 warps x 32 rows.
// smem (bytes): Q 256 rows x 20 f4; K/V 64 rows x 20 f4 each.
#define QPB 0
#define KPB 81920
#define VPB 102400
#define ATTN_SMEMB 122880

__global__ void __launch_bounds__(256, 1) k_attn(int pp) {
    extern __shared__ float sf[];
    char* smc = (char*)sf;
    uint32_t sb = (uint32_t)__cvta_generic_to_shared(sf);
    int b = blockIdx.y, n0 = blockIdx.x * 256, tid = threadIdx.x;
    int wid = tid >> 5, lane = tid & 31;
    int qr = lane >> 2, qc = lane & 3;
    int wrow = wid * 32;
    const uint32_t FULL = 0xffffffffu;

    const uint4* gQ = (const uint4*)g_Qp + ((size_t)b * NN + n0) * 16;
    const uint4* gK = (const uint4*)g_Kp + (size_t)b * NN * 16;
    const uint4* gV = (const uint4*)g_Vp + (size_t)b * 64 * 256;

    // prologue: Q (4096 f4) + K0/V0 (1024 f4 each)
#pragma unroll
    for (int t = 0; t < 16; t++) {
        int q = tid + t * 256, r = q >> 4, j = q & 15;
        cp16(sb + QPB + (r * 20 + j) * 16, (const float*)(gQ + (size_t)r * 16 + j));
    }
#pragma unroll
    for (int t = 0; t < 4; t++) {
        int q = tid + t * 256, r = q >> 4, j = q & 15;
        cp16(sb + KPB + (r * 20 + j) * 16, (const float*)(gK + (size_t)r * 16 + j));
        cp16(sb + VPB + (r * 20 + j) * 16, (const float*)(gV + (size_t)r * 256 + j));
    }
    cp_commit();

    // scales
    float sQg[2];
    sQg[0] = g_sQ[b * 16 + ((n0 + wrow) >> 6)];
    sQg[1] = g_sQ[b * 16 + ((n0 + wrow + 16) >> 6)];
    float sVmax = 0.f;
#pragma unroll
    for (int t = 0; t < 16; t++) sVmax = fmaxf(sVmax, g_sV[b * 16 + t]);
    float invVmax = 1.0f / sVmax;

    float4 O[2][8];
#pragma unroll
    for (int g = 0; g < 2; g++)
#pragma unroll
        for (int nt = 0; nt < 8; nt++) O[g][nt] = make_float4(0.f, 0.f, 0.f, 0.f);
    float m[2][2], l[2][2];
#pragma unroll
    for (int g = 0; g < 2; g++) { m[g][0] = m[g][1] = -1e30f; l[g][0] = l[g][1] = 0.f; }

#pragma unroll 1
    for (int kt = 0; kt < 16; ++kt) {
        float sK_t = g_sK[b * 16 + kt];
        float rV = g_sV[b * 16 + kt] * invVmax;
        cp_wait0();
        __syncthreads();

        // ---- S = Qh*Kh + Qh*Kl + Ql*Kh (fp16 m16n8k16) ----
        float4 S[2][8];
#pragma unroll
        for (int g = 0; g < 2; g++)
#pragma unroll
            for (int nt = 0; nt < 8; nt++) S[g][nt] = make_float4(0.f, 0.f, 0.f, 0.f);
#pragma unroll
        for (int t = 0; t < 4; t++) {
            uint4 q0[2], q8[2];
#pragma unroll
            for (int g = 0; g < 2; g++) {
                int row = wrow + g * 16 + qr;
                q0[g] = *(const uint4*)(smc + QPB + (row * 20 + t * 4 + qc) * 16);
                q8[g] = *(const uint4*)(smc + QPB + ((row + 8) * 20 + t * 4 + qc) * 16);
            }
#pragma unroll
            for (int nt = 0; nt < 8; nt++) {
                uint4 kb = *(const uint4*)(smc + KPB + ((8 * nt + qr) * 20 + t * 4 + qc) * 16);
#pragma unroll
                for (int g = 0; g < 2; g++) {
                    mma16(S[g][nt], q0[g].x, q8[g].x, q0[g].y, q8[g].y, kb.x, kb.y);
                    mma16(S[g][nt], q0[g].x, q8[g].x, q0[g].y, q8[g].y, kb.z, kb.w);
                    mma16(S[g][nt], q0[g].z, q8[g].z, q0[g].w, q8[g].w, kb.x, kb.y);
                }
            }
        }

        // ---- scale to true scores + online softmax + P'' = P*rV ----
#pragma unroll
        for (int g = 0; g < 2; g++) {
            float fs = sQg[g] * sK_t;
            float mx0 = -1e30f, mx1 = -1e30f;
#pragma unroll
            for (int nt = 0; nt < 8; nt++) {
                S[g][nt].x *= fs; S[g][nt].y *= fs; S[g][nt].z *= fs; S[g][nt].w *= fs;
                mx0 = fmaxf(mx0, fmaxf(S[g][nt].x, S[g][nt].y));
                mx1 = fmaxf(mx1, fmaxf(S[g][nt].z, S[g][nt].w));
            }
            mx0 = fmaxf(mx0, __shfl_xor_sync(FULL, mx0, 1));
            mx0 = fmaxf(mx0, __shfl_xor_sync(FULL, mx0, 2));
            mx1 = fmaxf(mx1, __shfl_xor_sync(FULL, mx1, 1));
            mx1 = fmaxf(mx1, __shfl_xor_sync(FULL, mx1, 2));
            float mn0 = fmaxf(m[g][0], mx0), mn1 = fmaxf(m[g][1], mx1);
            float c0 = __expf(m[g][0] - mn0), c1 = __expf(m[g][1] - mn1);
            m[g][0] = mn0; m[g][1] = mn1;
            float ps0 = 0.f, ps1 = 0.f;
#pragma unroll
            for (int nt = 0; nt < 8; nt++) {
                S[g][nt].x = __expf(S[g][nt].x - mn0);
                S[g][nt].y = __expf(S[g][nt].y - mn0);
                S[g][nt].z = __expf(S[g][nt].z - mn1);
                S[g][nt].w = __expf(S[g][nt].w - mn1);
                ps0 += S[g][nt].x + S[g][nt].y;
                ps1 += S[g][nt].z + S[g][nt].w;
                S[g][nt].x *= rV; S[g][nt].y *= rV; S[g][nt].z *= rV; S[g][nt].w *= rV;
            }
            l[g][0] = l[g][0] * c0 + ps0;
            l[g][1] = l[g][1] * c1 + ps1;
#pragma unroll
            for (int nt = 0; nt < 8; nt++) {
                O[g][nt].x *= c0; O[g][nt].y *= c0; O[g][nt].z *= c1; O[g][nt].w *= c1;
            }
        }

        // ---- PV: S-fragments ARE the A-fragments (no shuffles) ----
#pragma unroll
        for (int t = 0; t < 4; t++) {
            uint32_t Ph[2][4], Pl[2][4];
#pragma unroll
            for (int g = 0; g < 2; g++) {
                float4 Sa = S[g][2 * t], Sb = S[g][2 * t + 1];
                uint32_t h0 = h2u(Sa.x, Sa.y), h1 = h2u(Sa.z, Sa.w);
                uint32_t h2 = h2u(Sb.x, Sb.y), h3 = h2u(Sb.z, Sb.w);
                float2 f0 = u2h2f(h0), f1 = u2h2f(h1), f2 = u2h2f(h2), f3 = u2h2f(h3);
                Ph[g][0] = h0; Ph[g][1] = h1; Ph[g][2] = h2; Ph[g][3] = h3;
                Pl[g][0] = h2u(Sa.x - f0.x, Sa.y - f0.y);
                Pl[g][1] = h2u(Sa.z - f1.x, Sa.w - f1.y);
                Pl[g][2] = h2u(Sb.x - f2.x, Sb.y - f2.y);
                Pl[g][3] = h2u(Sb.z - f3.x, Sb.w - f3.y);
            }
#pragma unroll
            for (int nt = 0; nt < 8; nt++) {
                uint4 vb = *(const uint4*)(smc + VPB + ((8 * nt + qr) * 20 + t * 4 + qc) * 16);
#pragma unroll
                for (int g = 0; g < 2; g++) {
                    mma16(O[g][nt], Ph[g][0], Ph[g][1], Ph[g][2], Ph[g][3], vb.x, vb.y);
                    mma16(O[g][nt], Ph[g][0], Ph[g][1], Ph[g][2], Ph[g][3], vb.z, vb.w);
                    mma16(O[g][nt], Pl[g][0], Pl[g][1], Pl[g][2], Pl[g][3], vb.x, vb.y);
                }
            }
        }

        __syncthreads();
        if (kt + 1 < 16) {
#pragma unroll
            for (int t = 0; t < 4; t++) {
                int q = tid + t * 256, r = q >> 4, j = q & 15;
                cp16(sb + KPB + (r * 20 + j) * 16,
                     (const float*)(gK + (size_t)((kt + 1) * 64 + r) * 16 + j));
                cp16(sb + VPB + (r * 20 + j) * 16,
                     (const float*)(gV + (size_t)r * 256 + (kt + 1) * 16 + j));
            }
        }
        cp_commit();
    }

    // epilogue: out = sVmax * O / l + Xin
#pragma unroll
    for (int g = 0; g < 2; g++) {
        float l0 = l[g][0], l1 = l[g][1];
        l0 += __shfl_xor_sync(FULL, l0, 1);
        l0 += __shfl_xor_sync(FULL, l0, 2);
        l1 += __shfl_xor_sync(FULL, l1, 1);
        l1 += __shfl_xor_sync(FULL, l1, 2);
        float i0 = sVmax / l0, i1 = sVmax / l1;
        const float* Xi0 = g_X[pp] + ((size_t)(b * NN + n0) + wrow + g * 16 + qr) * CC;
        const float* Xi8 = Xi0 + 8 * CC;
        float* Xo0 = g_X[pp ^ 1] + ((size_t)(b * NN + n0) + wrow + g * 16 + qr) * CC;
        float* Xo8 = Xo0 + 8 * CC;
#pragma unroll
        for (int nt = 0; nt < 8; nt++) {
            int c = 8 * nt + 2 * qc;
            float2 a = *(const float2*)&Xi0[c];
            float2 bb = *(const float2*)&Xi8[c];
            *(float2*)&Xo0[c] = make_float2(O[g][nt].x * i0 + a.x, O[g][nt].y * i0 + a.y);
            *(float2*)&Xo8[c] = make_float2(O[g][nt].z * i1 + bb.x, O[g][nt].w * i1 + bb.y);
        }
    }
}
// ---------------------------------------------------------------------------
__global__ void k_head(const float* __restrict__ lw, const float* __restrict__ lb,
                       float* __restrict__ out) {
    __shared__ float meanv[NN];
    __shared__ float red[8];
    int b = blockIdx.x;
    const float* Xb = g_X[0] + (size_t)b * NN * CC;
    for (int n = threadIdx.x; n < NN; n += 256) {
        const float4* p = (const float4*)(Xb + (size_t)n * CC);
        float s = 0.0f;
#pragma unroll
        for (int q = 0; q < 16; q++) { float4 v = p[q]; s += v.x + v.y + v.z + v.w; }
        meanv[n] = s * (1.0f / 64.0f);
    }
    __syncthreads();
    for (int cls = 0; cls < NCLS; cls++) {
        float s = 0.0f;
        for (int n = threadIdx.x; n < NN; n += 256) s += meanv[n] * lw[cls * NN + n];
#pragma unroll
        for (int d = 16; d; d >>= 1) s += __shfl_xor_sync(0xffffffffu, s, d);
        if ((threadIdx.x & 31) == 0) red[threadIdx.x >> 5] = s;
        __syncthreads();
        if (threadIdx.x == 0) {
            float t = 0.0f;
#pragma unroll
            for (int w = 0; w < 8; w++) t += red[w];
            out[b * NCLS + cls] = t + lb[cls];
        }
        __syncthreads();
    }
}
// ---------------------------------------------------------------------------
extern "C" void kernel_launch(void* const* d_in, const int* in_sizes, int n_in,
                              void* d_out, int out_size) {
    (void)in_sizes; (void)n_in; (void)out_size;
    const float* img = (const float*)d_in[0];
    const float* WV  = (const float*)d_in[1];
    const float* WK  = (const float*)d_in[2];
    const float* WQ  = (const float*)d_in[3];
    const float* lw  = (const float*)d_in[4];
    const float* lb  = (const float*)d_in[5];
    float* out = (float*)d_out;

    const int QKV_SMEM  = (29696 + 32) * 4;   // ~119 KB
    const int ATTN_SMEM = ATTN_SMEMB;         // 122880 B
    cudaFuncSetAttribute(k_qkv,  cudaFuncAttributeMaxDynamicSharedMemorySize, QKV_SMEM);
    cudaFuncSetAttribute(k_attn, cudaFuncAttributeMaxDynamicSharedMemorySize, ATTN_SMEM);

    dim3 gq(8, 32), ga(4, 32);
    k_transpose<<<dim3(16, 32), 256>>>(img);
    for (int l = 0; l < DEPTH; l++) {
        k_qkv<<<gq, 256, QKV_SMEM>>>(WQ, WK, WV, l & 1);
        k_attn<<<ga, 256, ATTN_SMEM>>>(l & 1);
    }
    k_head<<<32, 256>>>(lw, lb, out);
}

// round 15
// speedup vs baseline: 2.4651x; 1.0435x over previous
#include <cuda_runtime.h>
#include <cuda_bf16.h>
#include <cuda_fp16.h>
#include <cstdint>

#define BB 32
#define CC 64
#define NN 1024
#define DEPTH 8
#define NCLS 10

using u64 = unsigned long long;

static __device__ float g_X[2][BB * NN * CC];
static __device__ float g_Qp[BB * NN * 64];    // packed fp16 split Q: [b][n][16 f4]
static __device__ float g_Kp[BB * NN * 64];    // packed fp16 split K
static __device__ float g_Vp[BB * CC * NN];    // packed fp16 split V^T
static __device__ float g_sQ[BB * 16];
static __device__ float g_sK[BB * 16];
static __device__ float g_sV[BB * 16];

// ---------------- packed fp32 helpers ----------------
__device__ __forceinline__ u64 ffma2(u64 a, u64 b, u64 c) {
    u64 d; asm("fma.rn.f32x2 %0, %1, %2, %3;" : "=l"(d) : "l"(a), "l"(b), "l"(c)); return d;
}
__device__ __forceinline__ u64 fmul2(u64 a, u64 b) {
    u64 d; asm("mul.rn.f32x2 %0, %1, %2;" : "=l"(d) : "l"(a), "l"(b)); return d;
}
__device__ __forceinline__ u64 dup2(float x) {
    u64 r; asm("mov.b64 %0, {%1, %1};" : "=l"(r) : "f"(x)); return r;
}
__device__ __forceinline__ float2 u2f2(u64 v) {
    float2 r; asm("mov.b64 {%0, %1}, %2;" : "=f"(r.x), "=f"(r.y) : "l"(v)); return r;
}
__device__ __forceinline__ uint32_t h2u(float a, float b) {
    __half2 h = __float22half2_rn(make_float2(a, b));
    return *reinterpret_cast<uint32_t*>(&h);
}
__device__ __forceinline__ float2 u2h2f(uint32_t u) {
    __half2 h = *reinterpret_cast<__half2*>(&u);
    return __half22float2(h);
}
// ---------------- cp.async ----------------
__device__ __forceinline__ void cp16(uint32_t dst, const float* src) {
    asm volatile("cp.async.cg.shared.global [%0], [%1], 16;" :: "r"(dst), "l"(src));
}
__device__ __forceinline__ void cp_commit() { asm volatile("cp.async.commit_group;" ::: "memory"); }
__device__ __forceinline__ void cp_wait0()  { asm volatile("cp.async.wait_group 0;" ::: "memory"); }

// ---------------- warp mma.sync fp16 m16n8k16 (fp32 accum) ----------------
__device__ __forceinline__ void mma16(float4& d, uint32_t a0, uint32_t a1, uint32_t a2,
                                      uint32_t a3, uint32_t b0, uint32_t b1) {
    asm volatile(
        "mma.sync.aligned.m16n8k16.row.col.f32.f16.f16.f32 "
        "{%0,%1,%2,%3}, {%4,%5,%6,%7}, {%8,%9}, {%0,%1,%2,%3};"
        : "+f"(d.x), "+f"(d.y), "+f"(d.z), "+f"(d.w)
        : "r"(a0), "r"(a1), "r"(a2), "r"(a3), "r"(b0), "r"(b1));
}

__device__ __forceinline__ float pow2scale(float m) {
    if (m <= 0.0f) return 1.0f;
    uint32_t u = __float_as_uint(m);
    return __uint_as_float((u & 0x7f800000u) + 0x00800000u);
}

// ---------------------------------------------------------------------------
__global__ void k_transpose(const float* __restrict__ img) {
    __shared__ float t[64][65];
    int b = blockIdx.y, n0 = blockIdx.x * 64;
    const float* src = img + (size_t)b * CC * NN;
    for (int i = threadIdx.x; i < 4096; i += 256) t[i >> 6][i & 63] = src[(i >> 6) * NN + n0 + (i & 63)];
    __syncthreads();
    float* dst = g_X[0] + ((size_t)b * NN + n0) * CC;
    for (int i = threadIdx.x; i < 4096; i += 256) dst[(i >> 6) * CC + (i & 63)] = t[i & 63][i >> 6];
}
// ---------------------------------------------------------------------------
// QKV: 2 row-tiles/CTA, single X buffer (101.5 KB smem -> 2 CTAs/SM).
__global__ void __launch_bounds__(256, 2) k_qkv(const float* __restrict__ WQ,
                                                const float* __restrict__ WK,
                                                const float* __restrict__ WV, int pp) {
    extern __shared__ float sm[];
    float* Xs  = sm;                       // 64 x 68
    float* Ws  = sm + 4352;                // 64 x 192
    float* Kst = sm + 16640;               // 64 x 68
    float* Qst = sm + 20992;               // 64 x 68
    float* red = sm + 25344;               // 32 floats
    uint32_t sXs = (uint32_t)__cvta_generic_to_shared(Xs);
    uint32_t sWs = (uint32_t)__cvta_generic_to_shared(Ws);
    int b = blockIdx.y, tid = threadIdx.x;
    int wid = tid >> 5, lane = tid & 31;
    int r0 = blockIdx.x * 128;

    const float* Xin = g_X[pp] + ((size_t)b * NN + r0) * CC;
    // prologue: W + X tile0
#pragma unroll
    for (int t = 0; t < 12; t++) {
        int fo = (tid + t * 256) * 4;
        int k = fo / 192, c = fo - k * 192;
        const float* src = (c < 64) ? (WQ + k * 64 + c)
                         : (c < 128) ? (WK + k * 64 + c - 64)
                                     : (WV + k * 64 + c - 128);
        cp16(sWs + fo * 4, src);
    }
#pragma unroll
    for (int t = 0; t < 4; t++) {
        int i = tid + t * 256, r = i >> 4, c = (i & 15) << 2;
        cp16(sXs + (r * 68 + c) * 4, Xin + r * 64 + c);
    }
    cp_commit();

    int tx = tid & 15, ty = tid >> 4;
    const u64 scale2 = dup2(0.03125f);

#pragma unroll 1
    for (int tile = 0; tile < 2; tile++) {
        cp_wait0();
        __syncthreads();

        u64 acc[4][6];
#pragma unroll
        for (int i = 0; i < 4; i++)
#pragma unroll
            for (int j = 0; j < 6; j++) acc[i][j] = 0ULL;

#pragma unroll 2
        for (int k0 = 0; k0 < 64; k0 += 4) {
            float4 xv[4];
#pragma unroll
            for (int i = 0; i < 4; i++) xv[i] = *(const float4*)&Xs[(ty * 4 + i) * 68 + k0];
#pragma unroll
            for (int kk = 0; kk < 4; kk++) {
                u64 wv[6];
#pragma unroll
                for (int j = 0; j < 6; j++) wv[j] = *(const u64*)&Ws[(k0 + kk) * 192 + tx * 2 + 32 * j];
                u64 xd[4];
#pragma unroll
                for (int i = 0; i < 4; i++)
                    xd[i] = dup2(kk == 0 ? xv[i].x : kk == 1 ? xv[i].y : kk == 2 ? xv[i].z : xv[i].w);
#pragma unroll
                for (int i = 0; i < 4; i++)
#pragma unroll
                    for (int j = 0; j < 6; j++) acc[i][j] = ffma2(xd[i], wv[j], acc[i][j]);
            }
        }

        // per-tile max reductions
        float mQ = 0.f, mK = 0.f, mV = 0.f;
#pragma unroll
        for (int i = 0; i < 4; i++)
#pragma unroll
            for (int j = 0; j < 2; j++) {
                float2 q = u2f2(fmul2(acc[i][j], scale2));
                mQ = fmaxf(mQ, fmaxf(fabsf(q.x), fabsf(q.y)));
                float2 k = u2f2(acc[i][2 + j]);
                mK = fmaxf(mK, fmaxf(fabsf(k.x), fabsf(k.y)));
                float2 v = u2f2(acc[i][4 + j]);
                mV = fmaxf(mV, fmaxf(fabsf(v.x), fabsf(v.y)));
            }
#pragma unroll
        for (int d = 16; d; d >>= 1) {
            mQ = fmaxf(mQ, __shfl_xor_sync(0xffffffffu, mQ, d));
            mK = fmaxf(mK, __shfl_xor_sync(0xffffffffu, mK, d));
            mV = fmaxf(mV, __shfl_xor_sync(0xffffffffu, mV, d));
        }
        if (lane == 0) { red[wid] = mQ; red[8 + wid] = mK; red[16 + wid] = mV; }
        __syncthreads();   // compute reads of Xs done -> staging safe
        mQ = red[0]; mK = red[8]; mV = red[16];
#pragma unroll
        for (int w = 1; w < 8; w++) {
            mQ = fmaxf(mQ, red[w]); mK = fmaxf(mK, red[8 + w]); mV = fmaxf(mV, red[16 + w]);
        }
        float sQv = pow2scale(mQ), sKv = pow2scale(mK), sVv = pow2scale(mV);
        float iQ = 1.0f / sQv, iK = 1.0f / sKv, iV = 1.0f / sVv;
        int tileIdx = blockIdx.x * 2 + tile;
        if (tid == 0) {
            g_sQ[b * 16 + tileIdx] = sQv;
            g_sK[b * 16 + tileIdx] = sKv;
            g_sV[b * 16 + tileIdx] = sVv;
        }

        // stage raw Q/K into Qst/Kst, raw V into Xs
#pragma unroll
        for (int i = 0; i < 4; i++) {
            int r = ty * 4 + i, co = tx * 2;
#pragma unroll
            for (int j = 0; j < 2; j++) {
                int c = co + 32 * j;
                *(float2*)&Qst[r * 68 + c] = u2f2(fmul2(acc[i][j], scale2));
                *(float2*)&Kst[r * 68 + c] = u2f2(acc[i][2 + j]);
                *(float2*)&Xs[r * 68 + c]  = u2f2(acc[i][4 + j]);
            }
        }
        __syncthreads();

        // pack fp16 split outputs
        int rowbase = r0 + tile * 64;
        uint4* gQ = (uint4*)g_Qp + ((size_t)b * NN + rowbase) * 16;
        uint4* gK = (uint4*)g_Kp + ((size_t)b * NN + rowbase) * 16;
        uint4* gV = (uint4*)g_Vp + ((size_t)b * 64 * 16 + tileIdx) * 16;
        for (int q = tid; q < 1024; q += 256) {
            int r = q >> 4, f = q & 15, t = f >> 2, qc = f & 3;
            int c0 = 16 * t + 2 * qc;
            {
                float a0 = Qst[r * 68 + c0] * iQ, a1 = Qst[r * 68 + c0 + 1] * iQ;
                float a2 = Qst[r * 68 + c0 + 8] * iQ, a3 = Qst[r * 68 + c0 + 9] * iQ;
                uint32_t h01 = h2u(a0, a1), h23 = h2u(a2, a3);
                float2 b01 = u2h2f(h01), b23 = u2h2f(h23);
                gQ[(size_t)r * 16 + f] = make_uint4(h01, h23,
                    h2u(a0 - b01.x, a1 - b01.y), h2u(a2 - b23.x, a3 - b23.y));
            }
            {
                float a0 = Kst[r * 68 + c0] * iK, a1 = Kst[r * 68 + c0 + 1] * iK;
                float a2 = Kst[r * 68 + c0 + 8] * iK, a3 = Kst[r * 68 + c0 + 9] * iK;
                uint32_t h01 = h2u(a0, a1), h23 = h2u(a2, a3);
                float2 b01 = u2h2f(h01), b23 = u2h2f(h23);
                gK[(size_t)r * 16 + f] = make_uint4(h01, h23,
                    h2u(a0 - b01.x, a1 - b01.y), h2u(a2 - b23.x, a3 - b23.y));
            }
            {
                float a0 = Xs[c0 * 68 + r] * iV, a1 = Xs[(c0 + 1) * 68 + r] * iV;
                float a2 = Xs[(c0 + 8) * 68 + r] * iV, a3 = Xs[(c0 + 9) * 68 + r] * iV;
                uint32_t h01 = h2u(a0, a1), h23 = h2u(a2, a3);
                float2 b01 = u2h2f(h01), b23 = u2h2f(h23);
                gV[(size_t)r * 256 + f] = make_uint4(h01, h23,
                    h2u(a0 - b01.x, a1 - b01.y), h2u(a2 - b23.x, a3 - b23.y));
            }
        }
        // reload X for next tile (Xs free after pack reads)
        if (tile == 0) {
            __syncthreads();
#pragma unroll
            for (int t = 0; t < 4; t++) {
                int i = tid + t * 256, r = i >> 4, c = (i & 15) << 2;
                cp16(sXs + (r * 68 + c) * 4, Xin + (64 + r) * 64 + c);
            }
            cp_commit();
        }
    }
}
// ---------------------------------------------------------------------------
// fp16 mma flash attention. CTA = 128 q-rows, 256 threads, 8 warps x 16 rows,
// 80 KB smem -> 2 CTAs/SM (4 warps/SMSP), grid 8x32 = single wave.
#define QPB 0
#define KPB 40960
#define VPB 61440
#define ATTN_SMEMB 81920

__global__ void __launch_bounds__(256, 2) k_attn(int pp) {
    extern __shared__ float sf[];
    char* smc = (char*)sf;
    uint32_t sb = (uint32_t)__cvta_generic_to_shared(sf);
    int b = blockIdx.y, n0 = blockIdx.x * 128, tid = threadIdx.x;
    int wid = tid >> 5, lane = tid & 31;
    int qr = lane >> 2, qc = lane & 3;
    int wrow = wid * 16;
    const uint32_t FULL = 0xffffffffu;

    const uint4* gQ = (const uint4*)g_Qp + ((size_t)b * NN + n0) * 16;
    const uint4* gK = (const uint4*)g_Kp + (size_t)b * NN * 16;
    const uint4* gV = (const uint4*)g_Vp + (size_t)b * 64 * 256;

    // prologue: Q (2048 f4) + K0/V0 (1024 f4 each)
#pragma unroll
    for (int t = 0; t < 8; t++) {
        int q = tid + t * 256, r = q >> 4, j = q & 15;
        cp16(sb + QPB + (r * 20 + j) * 16, (const float*)(gQ + (size_t)r * 16 + j));
    }
#pragma unroll
    for (int t = 0; t < 4; t++) {
        int q = tid + t * 256, r = q >> 4, j = q & 15;
        cp16(sb + KPB + (r * 20 + j) * 16, (const float*)(gK + (size_t)r * 16 + j));
        cp16(sb + VPB + (r * 20 + j) * 16, (const float*)(gV + (size_t)r * 256 + j));
    }
    cp_commit();

    float sQg = g_sQ[b * 16 + ((n0 + wrow) >> 6)];
    float sVmax = 0.f;
#pragma unroll
    for (int t = 0; t < 16; t++) sVmax = fmaxf(sVmax, g_sV[b * 16 + t]);
    float invVmax = 1.0f / sVmax;

    float4 O[8];
#pragma unroll
    for (int nt = 0; nt < 8; nt++) O[nt] = make_float4(0.f, 0.f, 0.f, 0.f);
    float m0 = -1e30f, m1 = -1e30f, l0 = 0.f, l1 = 0.f;

#pragma unroll 1
    for (int kt = 0; kt < 16; ++kt) {
        float sK_t = g_sK[b * 16 + kt];
        float rV = g_sV[b * 16 + kt] * invVmax;
        cp_wait0();
        __syncthreads();

        // ---- S = Qh*Kh + Qh*Kl + Ql*Kh ----
        float4 S[8];
#pragma unroll
        for (int nt = 0; nt < 8; nt++) S[nt] = make_float4(0.f, 0.f, 0.f, 0.f);
#pragma unroll
        for (int t = 0; t < 4; t++) {
            int row = wrow + qr;
            uint4 q0 = *(const uint4*)(smc + QPB + (row * 20 + t * 4 + qc) * 16);
            uint4 q8 = *(const uint4*)(smc + QPB + ((row + 8) * 20 + t * 4 + qc) * 16);
#pragma unroll
            for (int nt = 0; nt < 8; nt++) {
                uint4 kb = *(const uint4*)(smc + KPB + ((8 * nt + qr) * 20 + t * 4 + qc) * 16);
                mma16(S[nt], q0.x, q8.x, q0.y, q8.y, kb.x, kb.y);
                mma16(S[nt], q0.x, q8.x, q0.y, q8.y, kb.z, kb.w);
                mma16(S[nt], q0.z, q8.z, q0.w, q8.w, kb.x, kb.y);
            }
        }

        // ---- scale + online softmax + P'' = P*rV ----
        float fs = sQg * sK_t;
        float mx0 = -1e30f, mx1 = -1e30f;
#pragma unroll
        for (int nt = 0; nt < 8; nt++) {
            S[nt].x *= fs; S[nt].y *= fs; S[nt].z *= fs; S[nt].w *= fs;
            mx0 = fmaxf(mx0, fmaxf(S[nt].x, S[nt].y));
            mx1 = fmaxf(mx1, fmaxf(S[nt].z, S[nt].w));
        }
        mx0 = fmaxf(mx0, __shfl_xor_sync(FULL, mx0, 1));
        mx0 = fmaxf(mx0, __shfl_xor_sync(FULL, mx0, 2));
        mx1 = fmaxf(mx1, __shfl_xor_sync(FULL, mx1, 1));
        mx1 = fmaxf(mx1, __shfl_xor_sync(FULL, mx1, 2));
        float mn0 = fmaxf(m0, mx0), mn1 = fmaxf(m1, mx1);
        float c0 = __expf(m0 - mn0), c1 = __expf(m1 - mn1);
        m0 = mn0; m1 = mn1;
        float ps0 = 0.f, ps1 = 0.f;
#pragma unroll
        for (int nt = 0; nt < 8; nt++) {
            S[nt].x = __expf(S[nt].x - mn0);
            S[nt].y = __expf(S[nt].y - mn0);
            S[nt].z = __expf(S[nt].z - mn1);
            S[nt].w = __expf(S[nt].w - mn1);
            ps0 += S[nt].x + S[nt].y;
            ps1 += S[nt].z + S[nt].w;
            S[nt].x *= rV; S[nt].y *= rV; S[nt].z *= rV; S[nt].w *= rV;
        }
        l0 = l0 * c0 + ps0;
        l1 = l1 * c1 + ps1;
#pragma unroll
        for (int nt = 0; nt < 8; nt++) {
            O[nt].x *= c0; O[nt].y *= c0; O[nt].z *= c1; O[nt].w *= c1;
        }

        // ---- PV: S-fragments are the A-fragments ----
#pragma unroll
        for (int t = 0; t < 4; t++) {
            float4 Sa = S[2 * t], Sb = S[2 * t + 1];
            uint32_t h0 = h2u(Sa.x, Sa.y), h1 = h2u(Sa.z, Sa.w);
            uint32_t h2 = h2u(Sb.x, Sb.y), h3 = h2u(Sb.z, Sb.w);
            float2 f0 = u2h2f(h0), f1 = u2h2f(h1), f2 = u2h2f(h2), f3 = u2h2f(h3);
            uint32_t p0 = h2u(Sa.x - f0.x, Sa.y - f0.y);
            uint32_t p1 = h2u(Sa.z - f1.x, Sa.w - f1.y);
            uint32_t p2 = h2u(Sb.x - f2.x, Sb.y - f2.y);
            uint32_t p3 = h2u(Sb.z - f3.x, Sb.w - f3.y);
#pragma unroll
            for (int nt = 0; nt < 8; nt++) {
                uint4 vb = *(const uint4*)(smc + VPB + ((8 * nt + qr) * 20 + t * 4 + qc) * 16);
                mma16(O[nt], h0, h1, h2, h3, vb.x, vb.y);
                mma16(O[nt], h0, h1, h2, h3, vb.z, vb.w);
                mma16(O[nt], p0, p1, p2, p3, vb.x, vb.y);
            }
        }

        __syncthreads();
        if (kt + 1 < 16) {
#pragma unroll
            for (int t = 0; t < 4; t++) {
                int q = tid + t * 256, r = q >> 4, j = q & 15;
                cp16(sb + KPB + (r * 20 + j) * 16,
                     (const float*)(gK + (size_t)((kt + 1) * 64 + r) * 16 + j));
                cp16(sb + VPB + (r * 20 + j) * 16,
                     (const float*)(gV + (size_t)r * 256 + (kt + 1) * 16 + j));
            }
        }
        cp_commit();
    }

    // epilogue: out = sVmax * O / l + Xin
    l0 += __shfl_xor_sync(FULL, l0, 1);
    l0 += __shfl_xor_sync(FULL, l0, 2);
    l1 += __shfl_xor_sync(FULL, l1, 1);
    l1 += __shfl_xor_sync(FULL, l1, 2);
    float i0 = sVmax / l0, i1 = sVmax / l1;
    const float* Xi0 = g_X[pp] + ((size_t)(b * NN + n0) + wrow + qr) * CC;
    const float* Xi8 = Xi0 + 8 * CC;
    float* Xo0 = g_X[pp ^ 1] + ((size_t)(b * NN + n0) + wrow + qr) * CC;
    float* Xo8 = Xo0 + 8 * CC;
#pragma unroll
    for (int nt = 0; nt < 8; nt++) {
        int c = 8 * nt + 2 * qc;
        float2 a = *(const float2*)&Xi0[c];
        float2 bb = *(const float2*)&Xi8[c];
        *(float2*)&Xo0[c] = make_float2(O[nt].x * i0 + a.x, O[nt].y * i0 + a.y);
        *(float2*)&Xo8[c] = make_float2(O[nt].z * i1 + bb.x, O[nt].w * i1 + bb.y);
    }
}
// ---------------------------------------------------------------------------
__global__ void k_head(const float* __restrict__ lw, const float* __restrict__ lb,
                       float* __restrict__ out) {
    __shared__ float meanv[NN];
    __shared__ float red[8];
    int b = blockIdx.x;
    const float* Xb = g_X[0] + (size_t)b * NN * CC;
    for (int n = threadIdx.x; n < NN; n += 256) {
        const float4* p = (const float4*)(Xb + (size_t)n * CC);
        float s = 0.0f;
#pragma unroll
        for (int q = 0; q < 16; q++) { float4 v = p[q]; s += v.x + v.y + v.z + v.w; }
        meanv[n] = s * (1.0f / 64.0f);
    }
    __syncthreads();
    for (int cls = 0; cls < NCLS; cls++) {
        float s = 0.0f;
        for (int n = threadIdx.x; n < NN; n += 256) s += meanv[n] * lw[cls * NN + n];
#pragma unroll
        for (int d = 16; d; d >>= 1) s += __shfl_xor_sync(0xffffffffu, s, d);
        if ((threadIdx.x & 31) == 0) red[threadIdx.x >> 5] = s;
        __syncthreads();
        if (threadIdx.x == 0) {
            float t = 0.0f;
#pragma unroll
            for (int w = 0; w < 8; w++) t += red[w];
            out[b * NCLS + cls] = t + lb[cls];
        }
        __syncthreads();
    }
}
// ---------------------------------------------------------------------------
extern "C" void kernel_launch(void* const* d_in, const int* in_sizes, int n_in,
                              void* d_out, int out_size) {
    (void)in_sizes; (void)n_in; (void)out_size;
    const float* img = (const float*)d_in[0];
    const float* WV  = (const float*)d_in[1];
    const float* WK  = (const float*)d_in[2];
    const float* WQ  = (const float*)d_in[3];
    const float* lw  = (const float*)d_in[4];
    const float* lb  = (const float*)d_in[5];
    float* out = (float*)d_out;

    const int QKV_SMEM  = (25344 + 32) * 4;   // 101504 B -> 2 CTAs/SM
    const int ATTN_SMEM = ATTN_SMEMB;         // 81920 B -> 2 CTAs/SM
    cudaFuncSetAttribute(k_qkv,  cudaFuncAttributeMaxDynamicSharedMemorySize, QKV_SMEM);
    cudaFuncSetAttribute(k_attn, cudaFuncAttributeMaxDynamicSharedMemorySize, ATTN_SMEM);

    dim3 gq(8, 32), ga(8, 32);
    k_transpose<<<dim3(16, 32), 256>>>(img);
    for (int l = 0; l < DEPTH; l++) {
        k_qkv<<<gq, 256, QKV_SMEM>>>(WQ, WK, WV, l & 1);
        k_attn<<<ga, 256, ATTN_SMEM>>>(l & 1);
    }
    k_head<<<32, 256>>>(lw, lb, out);
}

// round 16
// speedup vs baseline: 2.5987x; 1.0542x over previous
#include <cuda_runtime.h>
#include <cuda_bf16.h>
#include <cuda_fp16.h>
#include <cstdint>

#define BB 32
#define CC 64
#define NN 1024
#define DEPTH 8
#define NCLS 10

using u64 = unsigned long long;

static __device__ float g_X[2][BB * NN * CC];
static __device__ float g_Qp[BB * NN * 64];    // packed fp16 split Q: [b][n][16 f4]
static __device__ float g_Kp[BB * NN * 64];    // packed fp16 split K
static __device__ float g_Vp[BB * CC * NN];    // packed fp16 split V^T
static __device__ float g_sQ[BB * 16];
static __device__ float g_sK[BB * 16];
static __device__ float g_sV[BB * 16];

// ---------------- packed fp32 helpers ----------------
__device__ __forceinline__ u64 ffma2(u64 a, u64 b, u64 c) {
    u64 d; asm("fma.rn.f32x2 %0, %1, %2, %3;" : "=l"(d) : "l"(a), "l"(b), "l"(c)); return d;
}
__device__ __forceinline__ u64 fmul2(u64 a, u64 b) {
    u64 d; asm("mul.rn.f32x2 %0, %1, %2;" : "=l"(d) : "l"(a), "l"(b)); return d;
}
__device__ __forceinline__ u64 dup2(float x) {
    u64 r; asm("mov.b64 %0, {%1, %1};" : "=l"(r) : "f"(x)); return r;
}
__device__ __forceinline__ float2 u2f2(u64 v) {
    float2 r; asm("mov.b64 {%0, %1}, %2;" : "=f"(r.x), "=f"(r.y) : "l"(v)); return r;
}
__device__ __forceinline__ uint32_t h2u(float a, float b) {
    __half2 h = __float22half2_rn(make_float2(a, b));
    return *reinterpret_cast<uint32_t*>(&h);
}
__device__ __forceinline__ float2 u2h2f(uint32_t u) {
    __half2 h = *reinterpret_cast<__half2*>(&u);
    return __half22float2(h);
}
// ---------------- cp.async ----------------
__device__ __forceinline__ void cp16(uint32_t dst, const float* src) {
    asm volatile("cp.async.cg.shared.global [%0], [%1], 16;" :: "r"(dst), "l"(src));
}
__device__ __forceinline__ void cp_commit() { asm volatile("cp.async.commit_group;" ::: "memory"); }
__device__ __forceinline__ void cp_wait0()  { asm volatile("cp.async.wait_group 0;" ::: "memory"); }

// ---------------- warp mma.sync fp16 m16n8k16 (fp32 accum) ----------------
__device__ __forceinline__ void mma16(float4& d, uint32_t a0, uint32_t a1, uint32_t a2,
                                      uint32_t a3, uint32_t b0, uint32_t b1) {
    asm volatile(
        "mma.sync.aligned.m16n8k16.row.col.f32.f16.f16.f32 "
        "{%0,%1,%2,%3}, {%4,%5,%6,%7}, {%8,%9}, {%0,%1,%2,%3};"
        : "+f"(d.x), "+f"(d.y), "+f"(d.z), "+f"(d.w)
        : "r"(a0), "r"(a1), "r"(a2), "r"(a3), "r"(b0), "r"(b1));
}

__device__ __forceinline__ float pow2scale(float m) {
    if (m <= 0.0f) return 1.0f;
    uint32_t u = __float_as_uint(m);
    return __uint_as_float((u & 0x7f800000u) + 0x00800000u);
}

// ---------------------------------------------------------------------------
__global__ void k_transpose(const float* __restrict__ img) {
    __shared__ float t[64][65];
    int b = blockIdx.y, n0 = blockIdx.x * 64;
    const float* src = img + (size_t)b * CC * NN;
    for (int i = threadIdx.x; i < 4096; i += 256) t[i >> 6][i & 63] = src[(i >> 6) * NN + n0 + (i & 63)];
    __syncthreads();
    float* dst = g_X[0] + ((size_t)b * NN + n0) * CC;
    for (int i = threadIdx.x; i < 4096; i += 256) dst[(i >> 6) * CC + (i & 63)] = t[i & 63][i >> 6];
}
// ---------------------------------------------------------------------------
// QKV: 2 row-tiles/CTA, single X buffer (101.5 KB smem -> 2 CTAs/SM).
__global__ void __launch_bounds__(256, 2) k_qkv(const float* __restrict__ WQ,
                                                const float* __restrict__ WK,
                                                const float* __restrict__ WV, int pp) {
    extern __shared__ float sm[];
    float* Xs  = sm;                       // 64 x 68
    float* Ws  = sm + 4352;                // 64 x 192
    float* Kst = sm + 16640;               // 64 x 68
    float* Qst = sm + 20992;               // 64 x 68
    float* red = sm + 25344;               // 32 floats
    uint32_t sXs = (uint32_t)__cvta_generic_to_shared(Xs);
    uint32_t sWs = (uint32_t)__cvta_generic_to_shared(Ws);
    int b = blockIdx.y, tid = threadIdx.x;
    int wid = tid >> 5, lane = tid & 31;
    int r0 = blockIdx.x * 128;

    const float* Xin = g_X[pp] + ((size_t)b * NN + r0) * CC;
#pragma unroll
    for (int t = 0; t < 12; t++) {
        int fo = (tid + t * 256) * 4;
        int k = fo / 192, c = fo - k * 192;
        const float* src = (c < 64) ? (WQ + k * 64 + c)
                         : (c < 128) ? (WK + k * 64 + c - 64)
                                     : (WV + k * 64 + c - 128);
        cp16(sWs + fo * 4, src);
    }
#pragma unroll
    for (int t = 0; t < 4; t++) {
        int i = tid + t * 256, r = i >> 4, c = (i & 15) << 2;
        cp16(sXs + (r * 68 + c) * 4, Xin + r * 64 + c);
    }
    cp_commit();

    int tx = tid & 15, ty = tid >> 4;
    const u64 scale2 = dup2(0.03125f);

#pragma unroll 1
    for (int tile = 0; tile < 2; tile++) {
        cp_wait0();
        __syncthreads();

        u64 acc[4][6];
#pragma unroll
        for (int i = 0; i < 4; i++)
#pragma unroll
            for (int j = 0; j < 6; j++) acc[i][j] = 0ULL;

#pragma unroll 2
        for (int k0 = 0; k0 < 64; k0 += 4) {
            float4 xv[4];
#pragma unroll
            for (int i = 0; i < 4; i++) xv[i] = *(const float4*)&Xs[(ty * 4 + i) * 68 + k0];
#pragma unroll
            for (int kk = 0; kk < 4; kk++) {
                u64 wv[6];
#pragma unroll
                for (int j = 0; j < 6; j++) wv[j] = *(const u64*)&Ws[(k0 + kk) * 192 + tx * 2 + 32 * j];
                u64 xd[4];
#pragma unroll
                for (int i = 0; i < 4; i++)
                    xd[i] = dup2(kk == 0 ? xv[i].x : kk == 1 ? xv[i].y : kk == 2 ? xv[i].z : xv[i].w);
#pragma unroll
                for (int i = 0; i < 4; i++)
#pragma unroll
                    for (int j = 0; j < 6; j++) acc[i][j] = ffma2(xd[i], wv[j], acc[i][j]);
            }
        }

        float mQ = 0.f, mK = 0.f, mV = 0.f;
#pragma unroll
        for (int i = 0; i < 4; i++)
#pragma unroll
            for (int j = 0; j < 2; j++) {
                float2 q = u2f2(fmul2(acc[i][j], scale2));
                mQ = fmaxf(mQ, fmaxf(fabsf(q.x), fabsf(q.y)));
                float2 k = u2f2(acc[i][2 + j]);
                mK = fmaxf(mK, fmaxf(fabsf(k.x), fabsf(k.y)));
                float2 v = u2f2(acc[i][4 + j]);
                mV = fmaxf(mV, fmaxf(fabsf(v.x), fabsf(v.y)));
            }
#pragma unroll
        for (int d = 16; d; d >>= 1) {
            mQ = fmaxf(mQ, __shfl_xor_sync(0xffffffffu, mQ, d));
            mK = fmaxf(mK, __shfl_xor_sync(0xffffffffu, mK, d));
            mV = fmaxf(mV, __shfl_xor_sync(0xffffffffu, mV, d));
        }
        if (lane == 0) { red[wid] = mQ; red[8 + wid] = mK; red[16 + wid] = mV; }
        __syncthreads();
        mQ = red[0]; mK = red[8]; mV = red[16];
#pragma unroll
        for (int w = 1; w < 8; w++) {
            mQ = fmaxf(mQ, red[w]); mK = fmaxf(mK, red[8 + w]); mV = fmaxf(mV, red[16 + w]);
        }
        float sQv = pow2scale(mQ), sKv = pow2scale(mK), sVv = pow2scale(mV);
        float iQ = 1.0f / sQv, iK = 1.0f / sKv, iV = 1.0f / sVv;
        int tileIdx = blockIdx.x * 2 + tile;
        if (tid == 0) {
            g_sQ[b * 16 + tileIdx] = sQv;
            g_sK[b * 16 + tileIdx] = sKv;
            g_sV[b * 16 + tileIdx] = sVv;
        }

#pragma unroll
        for (int i = 0; i < 4; i++) {
            int r = ty * 4 + i, co = tx * 2;
#pragma unroll
            for (int j = 0; j < 2; j++) {
                int c = co + 32 * j;
                *(float2*)&Qst[r * 68 + c] = u2f2(fmul2(acc[i][j], scale2));
                *(float2*)&Kst[r * 68 + c] = u2f2(acc[i][2 + j]);
                *(float2*)&Xs[r * 68 + c]  = u2f2(acc[i][4 + j]);
            }
        }
        __syncthreads();

        int rowbase = r0 + tile * 64;
        uint4* gQ = (uint4*)g_Qp + ((size_t)b * NN + rowbase) * 16;
        uint4* gK = (uint4*)g_Kp + ((size_t)b * NN + rowbase) * 16;
        uint4* gV = (uint4*)g_Vp + ((size_t)b * 64 * 16 + tileIdx) * 16;
        for (int q = tid; q < 1024; q += 256) {
            int r = q >> 4, f = q & 15, t = f >> 2, qc = f & 3;
            int c0 = 16 * t + 2 * qc;
            {
                float a0 = Qst[r * 68 + c0] * iQ, a1 = Qst[r * 68 + c0 + 1] * iQ;
                float a2 = Qst[r * 68 + c0 + 8] * iQ, a3 = Qst[r * 68 + c0 + 9] * iQ;
                uint32_t h01 = h2u(a0, a1), h23 = h2u(a2, a3);
                float2 b01 = u2h2f(h01), b23 = u2h2f(h23);
                gQ[(size_t)r * 16 + f] = make_uint4(h01, h23,
                    h2u(a0 - b01.x, a1 - b01.y), h2u(a2 - b23.x, a3 - b23.y));
            }
            {
                float a0 = Kst[r * 68 + c0] * iK, a1 = Kst[r * 68 + c0 + 1] * iK;
                float a2 = Kst[r * 68 + c0 + 8] * iK, a3 = Kst[r * 68 + c0 + 9] * iK;
                uint32_t h01 = h2u(a0, a1), h23 = h2u(a2, a3);
                float2 b01 = u2h2f(h01), b23 = u2h2f(h23);
                gK[(size_t)r * 16 + f] = make_uint4(h01, h23,
                    h2u(a0 - b01.x, a1 - b01.y), h2u(a2 - b23.x, a3 - b23.y));
            }
            {
                float a0 = Xs[c0 * 68 + r] * iV, a1 = Xs[(c0 + 1) * 68 + r] * iV;
                float a2 = Xs[(c0 + 8) * 68 + r] * iV, a3 = Xs[(c0 + 9) * 68 + r] * iV;
                uint32_t h01 = h2u(a0, a1), h23 = h2u(a2, a3);
                float2 b01 = u2h2f(h01), b23 = u2h2f(h23);
                gV[(size_t)r * 256 + f] = make_uint4(h01, h23,
                    h2u(a0 - b01.x, a1 - b01.y), h2u(a2 - b23.x, a3 - b23.y));
            }
        }
        if (tile == 0) {
            __syncthreads();
#pragma unroll
            for (int t = 0; t < 4; t++) {
                int i = tid + t * 256, r = i >> 4, c = (i & 15) << 2;
                cp16(sXs + (r * 68 + c) * 4, Xin + (64 + r) * 64 + c);
            }
            cp_commit();
        }
    }
}
// ---------------------------------------------------------------------------
// fp16 mma flash attention. CTA = 128 q-rows, 256 threads, 8 warps x 16 rows.
// Q fragments in registers; K/V double-buffered smem (80 KB -> 2 CTAs/SM).
#define KPB(s) ((s) * 20480)
#define VPB(s) (40960 + (s) * 20480)
#define ATTN_SMEMB 81920

__global__ void __launch_bounds__(256, 2) k_attn(int pp) {
    extern __shared__ float sf[];
    char* smc = (char*)sf;
    uint32_t sb = (uint32_t)__cvta_generic_to_shared(sf);
    int b = blockIdx.y, n0 = blockIdx.x * 128, tid = threadIdx.x;
    int wid = tid >> 5, lane = tid & 31;
    int qr = lane >> 2, qc = lane & 3;
    int wrow = wid * 16;
    const uint32_t FULL = 0xffffffffu;

    const uint4* gQ = (const uint4*)g_Qp + ((size_t)b * NN + n0) * 16;
    const uint4* gK = (const uint4*)g_Kp + (size_t)b * NN * 16;
    const uint4* gV = (const uint4*)g_Vp + (size_t)b * 64 * 256;

    // K0/V0 into buffer 0
#pragma unroll
    for (int t = 0; t < 4; t++) {
        int q = tid + t * 256, r = q >> 4, j = q & 15;
        cp16(sb + KPB(0) + (r * 20 + j) * 16, (const float*)(gK + (size_t)r * 16 + j));
        cp16(sb + VPB(0) + (r * 20 + j) * 16, (const float*)(gV + (size_t)r * 256 + j));
    }
    cp_commit();

    // Q fragments -> registers (one-time global loads)
    uint4 q0[4], q8[4];
#pragma unroll
    for (int t = 0; t < 4; t++) {
        q0[t] = gQ[(size_t)(wrow + qr) * 16 + t * 4 + qc];
        q8[t] = gQ[(size_t)(wrow + qr + 8) * 16 + t * 4 + qc];
    }

    float sQg = g_sQ[b * 16 + ((n0 + wrow) >> 6)];
    float sVmax = 0.f;
#pragma unroll
    for (int t = 0; t < 16; t++) sVmax = fmaxf(sVmax, g_sV[b * 16 + t]);
    float invVmax = 1.0f / sVmax;

    float4 O[8];
#pragma unroll
    for (int nt = 0; nt < 8; nt++) O[nt] = make_float4(0.f, 0.f, 0.f, 0.f);
    float m0 = -1e30f, m1 = -1e30f, l0 = 0.f, l1 = 0.f;

#pragma unroll 1
    for (int kt = 0; kt < 16; ++kt) {
        float sK_t = g_sK[b * 16 + kt];
        float rV = g_sV[b * 16 + kt] * invVmax;
        cp_wait0();        // K/V(kt) resident
        __syncthreads();   // visible to all; buffer (kt+1)&1 free (kt-1 done)

        // issue prefetch of tile kt+1 into the other buffer
        if (kt + 1 < 16) {
            int s = (kt + 1) & 1;
#pragma unroll
            for (int t = 0; t < 4; t++) {
                int q = tid + t * 256, r = q >> 4, j = q & 15;
                cp16(sb + KPB(s) + (r * 20 + j) * 16,
                     (const float*)(gK + (size_t)((kt + 1) * 64 + r) * 16 + j));
                cp16(sb + VPB(s) + (r * 20 + j) * 16,
                     (const float*)(gV + (size_t)r * 256 + (kt + 1) * 16 + j));
            }
        }
        cp_commit();

        int buf = kt & 1;

        // ---- S = Qh*Kh + Qh*Kl + Ql*Kh ----
        float4 S[8];
#pragma unroll
        for (int nt = 0; nt < 8; nt++) S[nt] = make_float4(0.f, 0.f, 0.f, 0.f);
#pragma unroll
        for (int t = 0; t < 4; t++) {
#pragma unroll
            for (int nt = 0; nt < 8; nt++) {
                uint4 kb = *(const uint4*)(smc + KPB(buf) + ((8 * nt + qr) * 20 + t * 4 + qc) * 16);
                mma16(S[nt], q0[t].x, q8[t].x, q0[t].y, q8[t].y, kb.x, kb.y);
                mma16(S[nt], q0[t].x, q8[t].x, q0[t].y, q8[t].y, kb.z, kb.w);
                mma16(S[nt], q0[t].z, q8[t].z, q0[t].w, q8[t].w, kb.x, kb.y);
            }
        }

        // ---- scale + online softmax + P'' = P*rV ----
        float fs = sQg * sK_t;
        float mx0 = -1e30f, mx1 = -1e30f;
#pragma unroll
        for (int nt = 0; nt < 8; nt++) {
            S[nt].x *= fs; S[nt].y *= fs; S[nt].z *= fs; S[nt].w *= fs;
            mx0 = fmaxf(mx0, fmaxf(S[nt].x, S[nt].y));
            mx1 = fmaxf(mx1, fmaxf(S[nt].z, S[nt].w));
        }
        mx0 = fmaxf(mx0, __shfl_xor_sync(FULL, mx0, 1));
        mx0 = fmaxf(mx0, __shfl_xor_sync(FULL, mx0, 2));
        mx1 = fmaxf(mx1, __shfl_xor_sync(FULL, mx1, 1));
        mx1 = fmaxf(mx1, __shfl_xor_sync(FULL, mx1, 2));
        float mn0 = fmaxf(m0, mx0), mn1 = fmaxf(m1, mx1);
        float c0 = __expf(m0 - mn0), c1 = __expf(m1 - mn1);
        m0 = mn0; m1 = mn1;
        float ps0 = 0.f, ps1 = 0.f;
#pragma unroll
        for (int nt = 0; nt < 8; nt++) {
            S[nt].x = __expf(S[nt].x - mn0);
            S[nt].y = __expf(S[nt].y - mn0);
            S[nt].z = __expf(S[nt].z - mn1);
            S[nt].w = __expf(S[nt].w - mn1);
            ps0 += S[nt].x + S[nt].y;
            ps1 += S[nt].z + S[nt].w;
            S[nt].x *= rV; S[nt].y *= rV; S[nt].z *= rV; S[nt].w *= rV;
        }
        l0 = l0 * c0 + ps0;
        l1 = l1 * c1 + ps1;
#pragma unroll
        for (int nt = 0; nt < 8; nt++) {
            O[nt].x *= c0; O[nt].y *= c0; O[nt].z *= c1; O[nt].w *= c1;
        }

        // ---- PV: S-fragments are the A-fragments ----
#pragma unroll
        for (int t = 0; t < 4; t++) {
            float4 Sa = S[2 * t], Sb = S[2 * t + 1];
            uint32_t h0 = h2u(Sa.x, Sa.y), h1 = h2u(Sa.z, Sa.w);
            uint32_t h2 = h2u(Sb.x, Sb.y), h3 = h2u(Sb.z, Sb.w);
            float2 f0 = u2h2f(h0), f1 = u2h2f(h1), f2 = u2h2f(h2), f3 = u2h2f(h3);
            uint32_t p0 = h2u(Sa.x - f0.x, Sa.y - f0.y);
            uint32_t p1 = h2u(Sa.z - f1.x, Sa.w - f1.y);
            uint32_t p2 = h2u(Sb.x - f2.x, Sb.y - f2.y);
            uint32_t p3 = h2u(Sb.z - f3.x, Sb.w - f3.y);
#pragma unroll
            for (int nt = 0; nt < 8; nt++) {
                uint4 vb = *(const uint4*)(smc + VPB(buf) + ((8 * nt + qr) * 20 + t * 4 + qc) * 16);
                mma16(O[nt], h0, h1, h2, h3, vb.x, vb.y);
                mma16(O[nt], h0, h1, h2, h3, vb.z, vb.w);
                mma16(O[nt], p0, p1, p2, p3, vb.x, vb.y);
            }
        }
    }

    // epilogue: out = sVmax * O / l + Xin
    l0 += __shfl_xor_sync(FULL, l0, 1);
    l0 += __shfl_xor_sync(FULL, l0, 2);
    l1 += __shfl_xor_sync(FULL, l1, 1);
    l1 += __shfl_xor_sync(FULL, l1, 2);
    float i0 = sVmax / l0, i1 = sVmax / l1;
    const float* Xi0 = g_X[pp] + ((size_t)(b * NN + n0) + wrow + qr) * CC;
    const float* Xi8 = Xi0 + 8 * CC;
    float* Xo0 = g_X[pp ^ 1] + ((size_t)(b * NN + n0) + wrow + qr) * CC;
    float* Xo8 = Xo0 + 8 * CC;
#pragma unroll
    for (int nt = 0; nt < 8; nt++) {
        int c = 8 * nt + 2 * qc;
        float2 a = *(const float2*)&Xi0[c];
        float2 bb = *(const float2*)&Xi8[c];
        *(float2*)&Xo0[c] = make_float2(O[nt].x * i0 + a.x, O[nt].y * i0 + a.y);
        *(float2*)&Xo8[c] = make_float2(O[nt].z * i1 + bb.x, O[nt].w * i1 + bb.y);
    }
}
// ---------------------------------------------------------------------------
__global__ void k_head(const float* __restrict__ lw, const float* __restrict__ lb,
                       float* __restrict__ out) {
    __shared__ float meanv[NN];
    __shared__ float red[8];
    int b = blockIdx.x;
    const float* Xb = g_X[0] + (size_t)b * NN * CC;
    for (int n = threadIdx.x; n < NN; n += 256) {
        const float4* p = (const float4*)(Xb + (size_t)n * CC);
        float s = 0.0f;
#pragma unroll
        for (int q = 0; q < 16; q++) { float4 v = p[q]; s += v.x + v.y + v.z + v.w; }
        meanv[n] = s * (1.0f / 64.0f);
    }
    __syncthreads();
    for (int cls = 0; cls < NCLS; cls++) {
        float s = 0.0f;
        for (int n = threadIdx.x; n < NN; n += 256) s += meanv[n] * lw[cls * NN + n];
#pragma unroll
        for (int d = 16; d; d >>= 1) s += __shfl_xor_sync(0xffffffffu, s, d);
        if ((threadIdx.x & 31) == 0) red[threadIdx.x >> 5] = s;
        __syncthreads();
        if (threadIdx.x == 0) {
            float t = 0.0f;
#pragma unroll
            for (int w = 0; w < 8; w++) t += red[w];
            out[b * NCLS + cls] = t + lb[cls];
        }
        __syncthreads();
    }
}
// ---------------------------------------------------------------------------
extern "C" void kernel_launch(void* const* d_in, const int* in_sizes, int n_in,
                              void* d_out, int out_size) {
    (void)in_sizes; (void)n_in; (void)out_size;
    const float* img = (const float*)d_in[0];
    const float* WV  = (const float*)d_in[1];
    const float* WK  = (const float*)d_in[2];
    const float* WQ  = (const float*)d_in[3];
    const float* lw  = (const float*)d_in[4];
    const float* lb  = (const float*)d_in[5];
    float* out = (float*)d_out;

    const int QKV_SMEM  = (25344 + 32) * 4;   // 101504 B -> 2 CTAs/SM
    const int ATTN_SMEM = ATTN_SMEMB;         // 81920 B -> 2 CTAs/SM
    cudaFuncSetAttribute(k_qkv,  cudaFuncAttributeMaxDynamicSharedMemorySize, QKV_SMEM);
    cudaFuncSetAttribute(k_attn, cudaFuncAttributeMaxDynamicSharedMemorySize, ATTN_SMEM);

    dim3 gq(8, 32), ga(8, 32);
    k_transpose<<<dim3(16, 32), 256>>>(img);
    for (int l = 0; l < DEPTH; l++) {
        k_qkv<<<gq, 256, QKV_SMEM>>>(WQ, WK, WV, l & 1);
        k_attn<<<ga, 256, ATTN_SMEM>>>(l & 1);
    }
    k_head<<<32, 256>>>(lw, lb, out);
}

// round 17
// speedup vs baseline: 2.8505x; 1.0969x over previous
#include <cuda_runtime.h>
#include <cuda_bf16.h>
#include <cuda_fp16.h>
#include <cstdint>

#define BB 32
#define CC 64
#define NN 1024
#define DEPTH 8
#define NCLS 10

using u64 = unsigned long long;

static __device__ float g_X[2][BB * NN * CC];
static __device__ float g_Qp[BB * NN * 64];    // packed fp16 split Q: [b][n][16 f4]
static __device__ float g_Kp[BB * NN * 64];    // packed fp16 split K
static __device__ float g_Vp[BB * CC * NN];    // packed fp16 split V^T
static __device__ float g_Wp[192 * 64];        // packed fp16 split W (Q|K|V cols), B-frag layout
static __device__ float g_sQ[BB * 16];
static __device__ float g_sK[BB * 16];
static __device__ float g_sV[BB * 16];
static __device__ float g_sX[BB * 16];

// ---------------- helpers ----------------
__device__ __forceinline__ uint32_t h2u(float a, float b) {
    __half2 h = __float22half2_rn(make_float2(a, b));
    return *reinterpret_cast<uint32_t*>(&h);
}
__device__ __forceinline__ float2 u2h2f(uint32_t u) {
    __half2 h = *reinterpret_cast<__half2*>(&u);
    return __half22float2(h);
}
__device__ __forceinline__ void cp16(uint32_t dst, const float* src) {
    asm volatile("cp.async.cg.shared.global [%0], [%1], 16;" :: "r"(dst), "l"(src));
}
__device__ __forceinline__ void cp_commit() { asm volatile("cp.async.commit_group;" ::: "memory"); }
__device__ __forceinline__ void cp_wait0()  { asm volatile("cp.async.wait_group 0;" ::: "memory"); }

__device__ __forceinline__ void mma16(float4& d, uint32_t a0, uint32_t a1, uint32_t a2,
                                      uint32_t a3, uint32_t b0, uint32_t b1) {
    asm volatile(
        "mma.sync.aligned.m16n8k16.row.col.f32.f16.f16.f32 "
        "{%0,%1,%2,%3}, {%4,%5,%6,%7}, {%8,%9}, {%0,%1,%2,%3};"
        : "+f"(d.x), "+f"(d.y), "+f"(d.z), "+f"(d.w)
        : "r"(a0), "r"(a1), "r"(a2), "r"(a3), "r"(b0), "r"(b1));
}

__device__ __forceinline__ float pow2scale(float m) {
    if (m <= 0.0f) return 1.0f;
    uint32_t u = __float_as_uint(m);
    return __uint_as_float((u & 0x7f800000u) + 0x00800000u);
}

// ---------------------------------------------------------------------------
// One-time: pack W (WQ|WK|WV) into fp16 hi/lo B-fragment layout.
// g_Wp[col n][f = t*4+qc] = {h2(W[k0][n],W[k0+1][n]), h2(W[k0+8],W[k0+9]), lo, lo}
__global__ void k_packw(const float* __restrict__ WQ, const float* __restrict__ WK,
                        const float* __restrict__ WV) {
    uint4* gW = (uint4*)g_Wp;
    for (int idx = threadIdx.x; idx < 3072; idx += 256) {
        int n = idx >> 4, f = idx & 15, t = f >> 2, qc = f & 3;
        int k0 = 16 * t + 2 * qc;
        const float* src;
        int col;
        if (n < 64)       { src = WQ; col = n; }
        else if (n < 128) { src = WK; col = n - 64; }
        else              { src = WV; col = n - 128; }
        float w0 = src[k0 * 64 + col];
        float w1 = src[(k0 + 1) * 64 + col];
        float w2 = src[(k0 + 8) * 64 + col];
        float w3 = src[(k0 + 9) * 64 + col];
        uint32_t h01 = h2u(w0, w1), h23 = h2u(w2, w3);
        float2 b01 = u2h2f(h01), b23 = u2h2f(h23);
        gW[idx] = make_uint4(h01, h23,
                             h2u(w0 - b01.x, w1 - b01.y), h2u(w2 - b23.x, w3 - b23.y));
    }
}
// ---------------------------------------------------------------------------
// Transpose + per-64-row-tile |X| max -> g_sX
__global__ void k_transpose(const float* __restrict__ img) {
    __shared__ float t[64][65];
    __shared__ float red[8];
    int b = blockIdx.y, n0 = blockIdx.x * 64;
    const float* src = img + (size_t)b * CC * NN;
    for (int i = threadIdx.x; i < 4096; i += 256) t[i >> 6][i & 63] = src[(i >> 6) * NN + n0 + (i & 63)];
    __syncthreads();
    float* dst = g_X[0] + ((size_t)b * NN + n0) * CC;
    float mx = 0.f;
    for (int i = threadIdx.x; i < 4096; i += 256) {
        float v = t[i & 63][i >> 6];
        dst[(i >> 6) * CC + (i & 63)] = v;
        mx = fmaxf(mx, fabsf(v));
    }
#pragma unroll
    for (int d = 16; d; d >>= 1) mx = fmaxf(mx, __shfl_xor_sync(0xffffffffu, mx, d));
    if ((threadIdx.x & 31) == 0) red[threadIdx.x >> 5] = mx;
    __syncthreads();
    if (threadIdx.x == 0) {
        float m = red[0];
#pragma unroll
        for (int w = 1; w < 8; w++) m = fmaxf(m, red[w]);
        g_sX[b * 16 + blockIdx.x] = pow2scale(m);
    }
}
// ---------------------------------------------------------------------------
// QKV via fp16-split tensor MMA. 2 tiles/CTA, 8 warps (4 row-groups x 2 col-halves).
// smem floats: Xs [0,4352), Vst [4352,8704), red [8704,8736), Xp at 8736 (64 x 20 f4)
#define XP_F 8736
#define QKV_SMEMF (8736 + 5120)

__global__ void __launch_bounds__(256, 2) k_qkv(int pp) {
    extern __shared__ float sm[];
    float* Xs  = sm;
    float* Vst = sm + 4352;
    float* red = sm + 8704;
    char* smc = (char*)sm;
    uint32_t sb = (uint32_t)__cvta_generic_to_shared(sm);
    int b = blockIdx.y, tid = threadIdx.x;
    int wid = tid >> 5, lane = tid & 31;
    int qr = lane >> 2, qc = lane & 3;
    int rows16 = wid & 3, colhalf = wid >> 2;
    int row = rows16 * 16 + qr;
    int r0 = blockIdx.x * 128;
    const uint32_t FULL = 0xffffffffu;
    const uint4* gW = (const uint4*)g_Wp;

    const float* Xin = g_X[pp] + ((size_t)b * NN + r0) * CC;
#pragma unroll
    for (int t = 0; t < 4; t++) {
        int i = tid + t * 256, r = i >> 4, c = (i & 15) << 2;
        cp16(sb + (r * 68 + c) * 4, Xin + r * 64 + c);
    }
    cp_commit();

#pragma unroll 1
    for (int tile = 0; tile < 2; tile++) {
        int tileIdx = blockIdx.x * 2 + tile;
        float sXt = g_sX[b * 16 + tileIdx];
        float iX = 1.0f / sXt;
        cp_wait0();
        __syncthreads();   // X tile resident; prev V-pack reads of Vst done

        // ---- pack Xs -> Xp (scaled fp16 split A-fragments) ----
        for (int q = tid; q < 1024; q += 256) {
            int r = q >> 4, f = q & 15, t = f >> 2, c = f & 3;
            int c0 = 16 * t + 2 * c;
            float a0 = Xs[r * 68 + c0] * iX, a1 = Xs[r * 68 + c0 + 1] * iX;
            float a2 = Xs[r * 68 + c0 + 8] * iX, a3 = Xs[r * 68 + c0 + 9] * iX;
            uint32_t h01 = h2u(a0, a1), h23 = h2u(a2, a3);
            float2 b01 = u2h2f(h01), b23 = u2h2f(h23);
            *(uint4*)(smc + (XP_F + (r * 20 + f) * 4) * 4) = make_uint4(h01, h23,
                h2u(a0 - b01.x, a1 - b01.y), h2u(a2 - b23.x, a3 - b23.y));
        }
        __syncthreads();   // Xp visible; Xs free

        if (tile == 0) {   // prefetch X tile1 into Xs while mma runs on Xp
#pragma unroll
            for (int t = 0; t < 4; t++) {
                int i = tid + t * 256, r = i >> 4, c = (i & 15) << 2;
                cp16(sb + (r * 68 + c) * 4, Xin + (64 + r) * 64 + c);
            }
        }
        cp_commit();

        // ---- mma: A = Xp (rows row,row+8), B = W cols colhalf*96 + 8nt + qr ----
        float4 A[12];
#pragma unroll
        for (int nt = 0; nt < 12; nt++) A[nt] = make_float4(0.f, 0.f, 0.f, 0.f);
#pragma unroll
        for (int t = 0; t < 4; t++) {
            uint4 x0 = *(const uint4*)(smc + (XP_F + (row * 20 + t * 4 + qc) * 4) * 4);
            uint4 x8 = *(const uint4*)(smc + (XP_F + ((row + 8) * 20 + t * 4 + qc) * 4) * 4);
#pragma unroll
            for (int nt = 0; nt < 12; nt++) {
                uint4 wb = gW[(size_t)(colhalf * 96 + 8 * nt + qr) * 16 + t * 4 + qc];
                mma16(A[nt], x0.x, x8.x, x0.y, x8.y, wb.x, wb.y);
                mma16(A[nt], x0.x, x8.x, x0.y, x8.y, wb.z, wb.w);
                mma16(A[nt], x0.z, x8.z, x0.w, x8.w, wb.x, wb.y);
            }
        }

        // ---- per-tile output maxes ----
        float fsQ = sXt * 0.03125f;
        float mQ = 0.f, mK = 0.f, mV = 0.f;
        if (colhalf == 0) {
#pragma unroll
            for (int nt = 0; nt < 8; nt++) {
                mQ = fmaxf(mQ, fmaxf(fmaxf(fabsf(A[nt].x), fabsf(A[nt].y)),
                                     fmaxf(fabsf(A[nt].z), fabsf(A[nt].w))));
            }
#pragma unroll
            for (int nt = 8; nt < 12; nt++) {
                mK = fmaxf(mK, fmaxf(fmaxf(fabsf(A[nt].x), fabsf(A[nt].y)),
                                     fmaxf(fabsf(A[nt].z), fabsf(A[nt].w))));
            }
        } else {
#pragma unroll
            for (int nt = 0; nt < 4; nt++) {
                mK = fmaxf(mK, fmaxf(fmaxf(fabsf(A[nt].x), fabsf(A[nt].y)),
                                     fmaxf(fabsf(A[nt].z), fabsf(A[nt].w))));
            }
#pragma unroll
            for (int nt = 4; nt < 12; nt++) {
                mV = fmaxf(mV, fmaxf(fmaxf(fabsf(A[nt].x), fabsf(A[nt].y)),
                                     fmaxf(fabsf(A[nt].z), fabsf(A[nt].w))));
            }
        }
        mQ *= fsQ; mK *= sXt; mV *= sXt;
#pragma unroll
        for (int d = 16; d; d >>= 1) {
            mQ = fmaxf(mQ, __shfl_xor_sync(FULL, mQ, d));
            mK = fmaxf(mK, __shfl_xor_sync(FULL, mK, d));
            mV = fmaxf(mV, __shfl_xor_sync(FULL, mV, d));
        }
        if (lane == 0) { red[wid] = mQ; red[8 + wid] = mK; red[16 + wid] = mV; }
        __syncthreads();
        mQ = red[0]; mK = red[8]; mV = red[16];
#pragma unroll
        for (int w = 1; w < 8; w++) {
            mQ = fmaxf(mQ, red[w]); mK = fmaxf(mK, red[8 + w]); mV = fmaxf(mV, red[16 + w]);
        }
        float sQv = pow2scale(mQ), sKv = pow2scale(mK), sVv = pow2scale(mV);
        if (tid == 0) {
            g_sQ[b * 16 + tileIdx] = sQv;
            g_sK[b * 16 + tileIdx] = sKv;
            g_sV[b * 16 + tileIdx] = sVv;
        }

        // ---- pack Q/K directly from register fragments ----
        int rowbase = r0 + tile * 64;
        uint4* gQ = (uint4*)g_Qp + ((size_t)b * NN + rowbase) * 16;
        uint4* gK = (uint4*)g_Kp + ((size_t)b * NN + rowbase) * 16;
        if (colhalf == 0) {
            float fq = fsQ / sQv;
#pragma unroll
            for (int t = 0; t < 4; t++) {
                float4 Aa = A[2 * t], Ab = A[2 * t + 1];
                float a0 = Aa.x * fq, a1 = Aa.y * fq, b0 = Ab.x * fq, b1 = Ab.y * fq;
                uint32_t h01 = h2u(a0, a1), h23 = h2u(b0, b1);
                float2 e01 = u2h2f(h01), e23 = u2h2f(h23);
                gQ[(size_t)row * 16 + t * 4 + qc] = make_uint4(h01, h23,
                    h2u(a0 - e01.x, a1 - e01.y), h2u(b0 - e23.x, b1 - e23.y));
                a0 = Aa.z * fq; a1 = Aa.w * fq; b0 = Ab.z * fq; b1 = Ab.w * fq;
                h01 = h2u(a0, a1); h23 = h2u(b0, b1);
                e01 = u2h2f(h01); e23 = u2h2f(h23);
                gQ[(size_t)(row + 8) * 16 + t * 4 + qc] = make_uint4(h01, h23,
                    h2u(a0 - e01.x, a1 - e01.y), h2u(b0 - e23.x, b1 - e23.y));
            }
            float fk = sXt / sKv;
#pragma unroll
            for (int t = 0; t < 2; t++) {
                float4 Aa = A[8 + 2 * t], Ab = A[9 + 2 * t];
                float a0 = Aa.x * fk, a1 = Aa.y * fk, b0 = Ab.x * fk, b1 = Ab.y * fk;
                uint32_t h01 = h2u(a0, a1), h23 = h2u(b0, b1);
                float2 e01 = u2h2f(h01), e23 = u2h2f(h23);
                gK[(size_t)row * 16 + t * 4 + qc] = make_uint4(h01, h23,
                    h2u(a0 - e01.x, a1 - e01.y), h2u(b0 - e23.x, b1 - e23.y));
                a0 = Aa.z * fk; a1 = Aa.w * fk; b0 = Ab.z * fk; b1 = Ab.w * fk;
                h01 = h2u(a0, a1); h23 = h2u(b0, b1);
                e01 = u2h2f(h01); e23 = u2h2f(h23);
                gK[(size_t)(row + 8) * 16 + t * 4 + qc] = make_uint4(h01, h23,
                    h2u(a0 - e01.x, a1 - e01.y), h2u(b0 - e23.x, b1 - e23.y));
            }
        } else {
            float fk = sXt / sKv;
#pragma unroll
            for (int t = 0; t < 2; t++) {
                float4 Aa = A[2 * t], Ab = A[2 * t + 1];
                float a0 = Aa.x * fk, a1 = Aa.y * fk, b0 = Ab.x * fk, b1 = Ab.y * fk;
                uint32_t h01 = h2u(a0, a1), h23 = h2u(b0, b1);
                float2 e01 = u2h2f(h01), e23 = u2h2f(h23);
                gK[(size_t)row * 16 + (t + 2) * 4 + qc] = make_uint4(h01, h23,
                    h2u(a0 - e01.x, a1 - e01.y), h2u(b0 - e23.x, b1 - e23.y));
                a0 = Aa.z * fk; a1 = Aa.w * fk; b0 = Ab.z * fk; b1 = Ab.w * fk;
                h01 = h2u(a0, a1); h23 = h2u(b0, b1);
                e01 = u2h2f(h01); e23 = u2h2f(h23);
                gK[(size_t)(row + 8) * 16 + (t + 2) * 4 + qc] = make_uint4(h01, h23,
                    h2u(a0 - e01.x, a1 - e01.y), h2u(b0 - e23.x, b1 - e23.y));
            }
            // stage raw V into Vst
#pragma unroll
            for (int nt = 4; nt < 12; nt++) {
                int c = 8 * (nt - 4) + 2 * qc;
                *(float2*)&Vst[row * 68 + c] = make_float2(A[nt].x * sXt, A[nt].y * sXt);
                *(float2*)&Vst[(row + 8) * 68 + c] = make_float2(A[nt].z * sXt, A[nt].w * sXt);
            }
        }
        __syncthreads();   // Vst complete

        // ---- V^T pack (transpose) ----
        float iV = 1.0f / sVv;
        uint4* gV = (uint4*)g_Vp + ((size_t)b * 64 * 16 + tileIdx) * 16;
        for (int q = tid; q < 1024; q += 256) {
            int r = q >> 4, f = q & 15, t = f >> 2, c = f & 3;
            int c0 = 16 * t + 2 * c;
            float a0 = Vst[c0 * 68 + r] * iV, a1 = Vst[(c0 + 1) * 68 + r] * iV;
            float a2 = Vst[(c0 + 8) * 68 + r] * iV, a3 = Vst[(c0 + 9) * 68 + r] * iV;
            uint32_t h01 = h2u(a0, a1), h23 = h2u(a2, a3);
            float2 b01 = u2h2f(h01), b23 = u2h2f(h23);
            gV[(size_t)r * 256 + f] = make_uint4(h01, h23,
                h2u(a0 - b01.x, a1 - b01.y), h2u(a2 - b23.x, a3 - b23.y));
        }
    }
}
// ---------------------------------------------------------------------------
// fp16 mma flash attention (R15 structure) + g_sX epilogue for next layer.
#define KPB(s) ((s) * 20480)
#define VPB(s) (40960 + (s) * 20480)
#define ATTN_SMEMB 81984   // + 64B red

__global__ void __launch_bounds__(256, 2) k_attn(int pp) {
    extern __shared__ float sf[];
    char* smc = (char*)sf;
    float* red = (float*)(smc + 81920);
    uint32_t sb = (uint32_t)__cvta_generic_to_shared(sf);
    int b = blockIdx.y, n0 = blockIdx.x * 128, tid = threadIdx.x;
    int wid = tid >> 5, lane = tid & 31;
    int qr = lane >> 2, qc = lane & 3;
    int wrow = wid * 16;
    const uint32_t FULL = 0xffffffffu;

    const uint4* gQ = (const uint4*)g_Qp + ((size_t)b * NN + n0) * 16;
    const uint4* gK = (const uint4*)g_Kp + (size_t)b * NN * 16;
    const uint4* gV = (const uint4*)g_Vp + (size_t)b * 64 * 256;

#pragma unroll
    for (int t = 0; t < 4; t++) {
        int q = tid + t * 256, r = q >> 4, j = q & 15;
        cp16(sb + KPB(0) + (r * 20 + j) * 16, (const float*)(gK + (size_t)r * 16 + j));
        cp16(sb + VPB(0) + (r * 20 + j) * 16, (const float*)(gV + (size_t)r * 256 + j));
    }
    cp_commit();

    uint4 q0[4], q8[4];
#pragma unroll
    for (int t = 0; t < 4; t++) {
        q0[t] = gQ[(size_t)(wrow + qr) * 16 + t * 4 + qc];
        q8[t] = gQ[(size_t)(wrow + qr + 8) * 16 + t * 4 + qc];
    }

    float sQg = g_sQ[b * 16 + ((n0 + wrow) >> 6)];
    float sVmax = 0.f;
#pragma unroll
    for (int t = 0; t < 16; t++) sVmax = fmaxf(sVmax, g_sV[b * 16 + t]);
    float invVmax = 1.0f / sVmax;

    float4 O[8];
#pragma unroll
    for (int nt = 0; nt < 8; nt++) O[nt] = make_float4(0.f, 0.f, 0.f, 0.f);
    float m0 = -1e30f, m1 = -1e30f, l0 = 0.f, l1 = 0.f;

#pragma unroll 1
    for (int kt = 0; kt < 16; ++kt) {
        float sK_t = g_sK[b * 16 + kt];
        float rV = g_sV[b * 16 + kt] * invVmax;
        cp_wait0();
        __syncthreads();

        if (kt + 1 < 16) {
            int s = (kt + 1) & 1;
#pragma unroll
            for (int t = 0; t < 4; t++) {
                int q = tid + t * 256, r = q >> 4, j = q & 15;
                cp16(sb + KPB(s) + (r * 20 + j) * 16,
                     (const float*)(gK + (size_t)((kt + 1) * 64 + r) * 16 + j));
                cp16(sb + VPB(s) + (r * 20 + j) * 16,
                     (const float*)(gV + (size_t)r * 256 + (kt + 1) * 16 + j));
            }
        }
        cp_commit();

        int buf = kt & 1;
        float4 S[8];
#pragma unroll
        for (int nt = 0; nt < 8; nt++) S[nt] = make_float4(0.f, 0.f, 0.f, 0.f);
#pragma unroll
        for (int t = 0; t < 4; t++) {
#pragma unroll
            for (int nt = 0; nt < 8; nt++) {
                uint4 kb = *(const uint4*)(smc + KPB(buf) + ((8 * nt + qr) * 20 + t * 4 + qc) * 16);
                mma16(S[nt], q0[t].x, q8[t].x, q0[t].y, q8[t].y, kb.x, kb.y);
                mma16(S[nt], q0[t].x, q8[t].x, q0[t].y, q8[t].y, kb.z, kb.w);
                mma16(S[nt], q0[t].z, q8[t].z, q0[t].w, q8[t].w, kb.x, kb.y);
            }
        }

        float fs = sQg * sK_t;
        float mx0 = -1e30f, mx1 = -1e30f;
#pragma unroll
        for (int nt = 0; nt < 8; nt++) {
            S[nt].x *= fs; S[nt].y *= fs; S[nt].z *= fs; S[nt].w *= fs;
            mx0 = fmaxf(mx0, fmaxf(S[nt].x, S[nt].y));
            mx1 = fmaxf(mx1, fmaxf(S[nt].z, S[nt].w));
        }
        mx0 = fmaxf(mx0, __shfl_xor_sync(FULL, mx0, 1));
        mx0 = fmaxf(mx0, __shfl_xor_sync(FULL, mx0, 2));
        mx1 = fmaxf(mx1, __shfl_xor_sync(FULL, mx1, 1));
        mx1 = fmaxf(mx1, __shfl_xor_sync(FULL, mx1, 2));
        float mn0 = fmaxf(m0, mx0), mn1 = fmaxf(m1, mx1);
        float c0 = __expf(m0 - mn0), c1 = __expf(m1 - mn1);
        m0 = mn0; m1 = mn1;
        float ps0 = 0.f, ps1 = 0.f;
#pragma unroll
        for (int nt = 0; nt < 8; nt++) {
            S[nt].x = __expf(S[nt].x - mn0);
            S[nt].y = __expf(S[nt].y - mn0);
            S[nt].z = __expf(S[nt].z - mn1);
            S[nt].w = __expf(S[nt].w - mn1);
            ps0 += S[nt].x + S[nt].y;
            ps1 += S[nt].z + S[nt].w;
            S[nt].x *= rV; S[nt].y *= rV; S[nt].z *= rV; S[nt].w *= rV;
        }
        l0 = l0 * c0 + ps0;
        l1 = l1 * c1 + ps1;
#pragma unroll
        for (int nt = 0; nt < 8; nt++) {
            O[nt].x *= c0; O[nt].y *= c0; O[nt].z *= c1; O[nt].w *= c1;
        }

#pragma unroll
        for (int t = 0; t < 4; t++) {
            float4 Sa = S[2 * t], Sb = S[2 * t + 1];
            uint32_t h0 = h2u(Sa.x, Sa.y), h1 = h2u(Sa.z, Sa.w);
            uint32_t h2 = h2u(Sb.x, Sb.y), h3 = h2u(Sb.z, Sb.w);
            float2 f0 = u2h2f(h0), f1 = u2h2f(h1), f2 = u2h2f(h2), f3 = u2h2f(h3);
            uint32_t p0 = h2u(Sa.x - f0.x, Sa.y - f0.y);
            uint32_t p1 = h2u(Sa.z - f1.x, Sa.w - f1.y);
            uint32_t p2 = h2u(Sb.x - f2.x, Sb.y - f2.y);
            uint32_t p3 = h2u(Sb.z - f3.x, Sb.w - f3.y);
#pragma unroll
            for (int nt = 0; nt < 8; nt++) {
                uint4 vb = *(const uint4*)(smc + VPB(buf) + ((8 * nt + qr) * 20 + t * 4 + qc) * 16);
                mma16(O[nt], h0, h1, h2, h3, vb.x, vb.y);
                mma16(O[nt], h0, h1, h2, h3, vb.z, vb.w);
                mma16(O[nt], p0, p1, p2, p3, vb.x, vb.y);
            }
        }
    }

    // epilogue: out = sVmax*O/l + Xin; track per-tile max for next-layer g_sX
    l0 += __shfl_xor_sync(FULL, l0, 1);
    l0 += __shfl_xor_sync(FULL, l0, 2);
    l1 += __shfl_xor_sync(FULL, l1, 1);
    l1 += __shfl_xor_sync(FULL, l1, 2);
    float i0 = sVmax / l0, i1 = sVmax / l1;
    const float* Xi0 = g_X[pp] + ((size_t)(b * NN + n0) + wrow + qr) * CC;
    const float* Xi8 = Xi0 + 8 * CC;
    float* Xo0 = g_X[pp ^ 1] + ((size_t)(b * NN + n0) + wrow + qr) * CC;
    float* Xo8 = Xo0 + 8 * CC;
    float mxo = 0.f;
#pragma unroll
    for (int nt = 0; nt < 8; nt++) {
        int c = 8 * nt + 2 * qc;
        float2 a = *(const float2*)&Xi0[c];
        float2 bb = *(const float2*)&Xi8[c];
        float r0v = O[nt].x * i0 + a.x, r1v = O[nt].y * i0 + a.y;
        float r2v = O[nt].z * i1 + bb.x, r3v = O[nt].w * i1 + bb.y;
        *(float2*)&Xo0[c] = make_float2(r0v, r1v);
        *(float2*)&Xo8[c] = make_float2(r2v, r3v);
        mxo = fmaxf(mxo, fmaxf(fmaxf(fabsf(r0v), fabsf(r1v)), fmaxf(fabsf(r2v), fabsf(r3v))));
    }
#pragma unroll
    for (int d = 16; d; d >>= 1) mxo = fmaxf(mxo, __shfl_xor_sync(FULL, mxo, d));
    if (lane == 0) red[wid] = mxo;
    __syncthreads();
    if (tid == 0) {
        float m = fmaxf(fmaxf(red[0], red[1]), fmaxf(red[2], red[3]));
        g_sX[b * 16 + 2 * blockIdx.x] = pow2scale(m);
        m = fmaxf(fmaxf(red[4], red[5]), fmaxf(red[6], red[7]));
        g_sX[b * 16 + 2 * blockIdx.x + 1] = pow2scale(m);
    }
}
// ---------------------------------------------------------------------------
__global__ void k_head(const float* __restrict__ lw, const float* __restrict__ lb,
                       float* __restrict__ out) {
    __shared__ float meanv[NN];
    __shared__ float red[8];
    int b = blockIdx.x;
    const float* Xb = g_X[0] + (size_t)b * NN * CC;
    for (int n = threadIdx.x; n < NN; n += 256) {
        const float4* p = (const float4*)(Xb + (size_t)n * CC);
        float s = 0.0f;
#pragma unroll
        for (int q = 0; q < 16; q++) { float4 v = p[q]; s += v.x + v.y + v.z + v.w; }
        meanv[n] = s * (1.0f / 64.0f);
    }
    __syncthreads();
    for (int cls = 0; cls < NCLS; cls++) {
        float s = 0.0f;
        for (int n = threadIdx.x; n < NN; n += 256) s += meanv[n] * lw[cls * NN + n];
#pragma unroll
        for (int d = 16; d; d >>= 1) s += __shfl_xor_sync(0xffffffffu, s, d);
        if ((threadIdx.x & 31) == 0) red[threadIdx.x >> 5] = s;
        __syncthreads();
        if (threadIdx.x == 0) {
            float t = 0.0f;
#pragma unroll
            for (int w = 0; w < 8; w++) t += red[w];
            out[b * NCLS + cls] = t + lb[cls];
        }
        __syncthreads();
    }
}
// ---------------------------------------------------------------------------
extern "C" void kernel_launch(void* const* d_in, const int* in_sizes, int n_in,
                              void* d_out, int out_size) {
    (void)in_sizes; (void)n_in; (void)out_size;
    const float* img = (const float*)d_in[0];
    const float* WV  = (const float*)d_in[1];
    const float* WK  = (const float*)d_in[2];
    const float* WQ  = (const float*)d_in[3];
    const float* lw  = (const float*)d_in[4];
    const float* lb  = (const float*)d_in[5];
    float* out = (float*)d_out;

    const int QKV_SMEM  = QKV_SMEMF * 4;   // 55424 B
    const int ATTN_SMEM = ATTN_SMEMB;      // 81984 B
    cudaFuncSetAttribute(k_qkv,  cudaFuncAttributeMaxDynamicSharedMemorySize, QKV_SMEM);
    cudaFuncSetAttribute(k_attn, cudaFuncAttributeMaxDynamicSharedMemorySize, ATTN_SMEM);

    dim3 gq(8, 32), ga(8, 32);
    k_packw<<<1, 256>>>(WQ, WK, WV);
    k_transpose<<<dim3(16, 32), 256>>>(img);
    for (int l = 0; l < DEPTH; l++) {
        k_qkv<<<gq, 256, QKV_SMEM>>>(l & 1);
        k_attn<<<ga, 256, ATTN_SMEM>>>(l & 1);
    }
    k_head<<<32, 256>>>(lw, lb, out);
}